// round 12
// baseline (speedup 1.0000x reference)
#include <cuda_runtime.h>
#include <cuda_bf16.h>
#include <math.h>

// ---------------------------------------------------------------------------
// FourLayer_64F. Round 12: conv_mma inner loop rebuilt around paired-k smem
// (one LDS.64 feeds both tf32 mma B operands); single smem buffer, low-reg
// loader to restore occupancy. Structure otherwise = Round 10/11: 12
// launches, BN+pool fusions, fused BN stats, bf16 mma sims.
// ---------------------------------------------------------------------------

#define NIMG 57
#define NEG_SLOPE 0.2f

typedef unsigned int u32;

__device__ __forceinline__ u32 f2tf32(float v) {
    u32 r;
    asm("cvt.rna.tf32.f32 %0, %1;" : "=r"(r) : "f"(v));
    return r;
}

// ---------------- scratch pool (floats) ------------------------------------
#define OFF_P1   ((size_t)0)                        // 57*64*1764 pooled pre-BN1
#define OFF_C2   (OFF_P1 + (size_t)57*64*1764)      // 57*64*1764
#define OFF_C3   (OFF_C2 + (size_t)57*64*1764)      // 57*64*441
#define OFF_C4   (OFF_C3 + (size_t)57*64*441)
#define OFF_QH   (OFF_C4 + (size_t)57*64*441)       // bf16 32*441*64 -> 451584 f
#define OFF_SK   (OFF_QH + (size_t)451584)          // bf16 5*64*2240 -> 358400 f
#define OFF_SC   (OFF_SK + (size_t)358400)          // 6*64 scale
#define OFF_SHF  (OFF_SC + 384)                     // 6*64 shift
#define OFF_PART (OFF_SHF + 384)                    // 32*5*4
#define OFF_WB   (OFF_PART + 640)                   // 3*36864 conv64 weights
#define OFF_WB1  (OFF_WB + (size_t)3*36864)         // 2048 conv1 weights
#define OFF_ST1  (OFF_WB1 + 2048)                   // 57*42*64*2 block partials
#define POOL_TOTAL (OFF_ST1 + (size_t)57*42*64*2)

__device__ float d_pool[POOL_TOTAL];

__device__ __forceinline__ float lrelu(float v) {
    return v >= 0.f ? v : NEG_SLOPE * v;
}
__device__ __forceinline__ int img_group(int img) {
    return (img < 32) ? 0 : 1 + (img - 32) / 5;
}

__device__ __forceinline__ u32 smem_u32(const void* p) {
    u32 a;
    asm("{ .reg .u64 t; cvta.to.shared.u64 t, %1; cvt.u32.u64 %0, t; }"
        : "=r"(a) : "l"(p));
    return a;
}
__device__ __forceinline__ void ldsm_x4(u32& r0, u32& r1, u32& r2, u32& r3,
                                        u32 addr) {
    asm volatile("ldmatrix.sync.aligned.m8n8.x4.shared.b16 {%0,%1,%2,%3}, [%4];"
                 : "=r"(r0), "=r"(r1), "=r"(r2), "=r"(r3) : "r"(addr));
}
__device__ __forceinline__ void ldsm_x4t(u32& r0, u32& r1, u32& r2, u32& r3,
                                         u32 addr) {
    asm volatile(
        "ldmatrix.sync.aligned.m8n8.x4.trans.shared.b16 {%0,%1,%2,%3}, [%4];"
        : "=r"(r0), "=r"(r1), "=r"(r2), "=r"(r3) : "r"(addr));
}
__device__ __forceinline__ void mma16816(float* d, const u32* a, u32 b0, u32 b1) {
    asm volatile(
        "mma.sync.aligned.m16n8k16.row.col.f32.bf16.bf16.f32 "
        "{%0,%1,%2,%3}, {%4,%5,%6,%7}, {%8,%9}, {%0,%1,%2,%3};"
        : "+f"(d[0]), "+f"(d[1]), "+f"(d[2]), "+f"(d[3])
        : "r"(a[0]), "r"(a[1]), "r"(a[2]), "r"(a[3]), "r"(b0), "r"(b1));
}
__device__ __forceinline__ void mma_tf32(float* d, u32 a0, u32 a1, u32 a2,
                                         u32 a3, u32 b0, u32 b1) {
    asm volatile(
        "mma.sync.aligned.m16n8k8.row.col.f32.tf32.tf32.f32 "
        "{%0,%1,%2,%3}, {%4,%5,%6,%7}, {%8,%9}, {%0,%1,%2,%3};"
        : "+f"(d[0]), "+f"(d[1]), "+f"(d[2]), "+f"(d[3])
        : "r"(a0), "r"(a1), "r"(a2), "r"(a3), "r"(b0), "r"(b1));
}

// ---------------------------------------------------------------------------
// Weight prep for all four conv layers in ONE launch (unchanged).
// ---------------------------------------------------------------------------
__global__ void wprep_kernel(const float* __restrict__ w1,
                             const float* __restrict__ w2,
                             const float* __restrict__ w3,
                             const float* __restrict__ w4,
                             float* __restrict__ wbuf,
                             float* __restrict__ wbuf1) {
    int idx = blockIdx.x * 256 + threadIdx.x;
    if (idx < 3 * 36864) {
        int which = idx / 36864;
        int r = idx % 36864;
        const float* w = (which == 0) ? w2 : (which == 1) ? w3 : w4;
        int j = r & 3;
        int lane = (r >> 2) & 31;
        int wm = (r >> 7) & 3;
        int rest = r >> 9;
        int t = rest % 9, cc = rest / 9;
        int oc = wm * 16 + (lane >> 2) + (j & 1) * 8;
        int ci = cc * 8 + (lane & 3) + ((j >> 1) & 1) * 4;
        wbuf[idx] = __uint_as_float(f2tf32(w[(oc * 64 + ci) * 9 + t]));
    } else if (idx < 3 * 36864 + 2048) {
        int r = idx - 3 * 36864;
        int j = r & 3;
        int lane = (r >> 2) & 31;
        int wm = (r >> 7) & 3;
        int ks = r >> 9;
        int oc = wm * 16 + (lane >> 2) + (j & 1) * 8;
        int k = ks * 8 + (lane & 3) + ((j >> 1) & 1) * 4;
        float v = 0.f;
        if (k < 27) v = w1[(oc * 3 + k / 9) * 9 + (k % 9)];
        wbuf1[r] = __uint_as_float(f2tf32(v));
    }
}

// ---------------------------------------------------------------------------
// conv1 + maxpool, tf32 shift-GEMM (unchanged). grid (42, 57).
// ---------------------------------------------------------------------------
#define C1P 88
#define C1CIP 360

__global__ void __launch_bounds__(256) conv1_pool_kernel(
    const float* __restrict__ in1, const float* __restrict__ in2,
    const float* __restrict__ wbuf1, float* __restrict__ p1pre,
    float* __restrict__ st1) {
    __shared__ char sraw[45056];
    __shared__ float s_stats[2][64][2];
    u32* s_in = (u32*)sraw;
    float(*sacc)[176] = (float(*)[176])sraw;

    const int bx = blockIdx.x;
    const int img = blockIdx.y;
    const int tid = threadIdx.x;
    const int wid = tid >> 5, lane = tid & 31;
    const int wm = wid & 3, wn = wid >> 2;

    const float* ip = (img < 32) ? (in1 + (size_t)img * 3 * 7056)
                                 : (in2 + (size_t)(img - 32) * 3 * 7056);

    for (int i = tid; i < 3 * 4 * C1P; i += 256) {
        int ci = i / (4 * C1P);
        int rem = i % (4 * C1P);
        int r = rem / C1P, c = rem % C1P;
        int gy = 2 * bx - 1 + r, gx = c - 1;
        float v = 0.f;
        if (gy >= 0 && gy < 84 && gx >= 0 && gx < 84)
            v = ip[ci * 7056 + gy * 84 + gx];
        s_in[ci * C1CIP + r * C1P + c] = f2tf32(v);
    }
    if (tid < 24)
        s_in[(tid / 8) * C1CIP + 4 * C1P + (tid % 8)] = 0u;
    __syncthreads();

    u32 koffA[4], koffB[4];
#pragma unroll
    for (int ks = 0; ks < 4; ks++) {
        int kA = ks * 8 + (lane & 3), kB = kA + 4;
        koffA[ks] = (kA < 27)
            ? (u32)((kA / 9) * C1CIP + ((kA % 9) / 3) * C1P + (kA % 9) % 3)
            : 0u;
        koffB[ks] = (kB < 27)
            ? (u32)((kB / 9) * C1CIP + ((kB % 9) / 3) * C1P + (kB % 9) % 3)
            : 0u;
    }
    const u32 pixrow = (u32)(wn * C1P) + (u32)(lane >> 2);

    float acc[11][4];
#pragma unroll
    for (int n8 = 0; n8 < 11; n8++)
#pragma unroll
        for (int j = 0; j < 4; j++) acc[n8][j] = 0.f;

#pragma unroll
    for (int ks = 0; ks < 4; ks++) {
        float4 af = *(const float4*)&wbuf1[((ks * 4 + wm) * 32 + lane) * 4];
        u32 a0 = __float_as_uint(af.x);
        u32 a1 = __float_as_uint(af.y);
        u32 a2 = __float_as_uint(af.z);
        u32 a3 = __float_as_uint(af.w);
#pragma unroll
        for (int n8 = 0; n8 < 11; n8++) {
            u32 p = pixrow + n8 * 8;
            u32 b0 = s_in[koffA[ks] + p];
            u32 b1 = s_in[koffB[ks] + p];
            mma_tf32(acc[n8], a0, a1, a2, a3, b0, b1);
        }
    }
    __syncthreads();

    const int oc0 = wm * 16 + (lane >> 2);
    float s0 = 0.f, q0 = 0.f, s1 = 0.f, q1 = 0.f;
#pragma unroll
    for (int n8 = 0; n8 < 11; n8++) {
        int col = n8 * 8 + 2 * (lane & 3);
        if (col < 84) {
            float v0 = acc[n8][0], v1 = acc[n8][2];
            sacc[oc0][wn * C1P + col] = v0;
            sacc[oc0 + 8][wn * C1P + col] = v1;
            s0 += v0; q0 = fmaf(v0, v0, q0);
            s1 += v1; q1 = fmaf(v1, v1, q1);
        }
        if (col + 1 < 84) {
            float v0 = acc[n8][1], v1 = acc[n8][3];
            sacc[oc0][wn * C1P + col + 1] = v0;
            sacc[oc0 + 8][wn * C1P + col + 1] = v1;
            s0 += v0; q0 = fmaf(v0, v0, q0);
            s1 += v1; q1 = fmaf(v1, v1, q1);
        }
    }
#pragma unroll
    for (int off = 1; off <= 2; off <<= 1) {
        s0 += __shfl_xor_sync(0xffffffffu, s0, off);
        q0 += __shfl_xor_sync(0xffffffffu, q0, off);
        s1 += __shfl_xor_sync(0xffffffffu, s1, off);
        q1 += __shfl_xor_sync(0xffffffffu, q1, off);
    }
    if ((lane & 3) == 0) {
        s_stats[wn][oc0][0] = s0;
        s_stats[wn][oc0][1] = q0;
        s_stats[wn][oc0 + 8][0] = s1;
        s_stats[wn][oc0 + 8][1] = q1;
    }
    __syncthreads();

    for (int i = tid; i < 64 * 42; i += 256) {
        int oc = i / 42, pc = i % 42;
        float v = fmaxf(fmaxf(sacc[oc][2 * pc], sacc[oc][2 * pc + 1]),
                        fmaxf(sacc[oc][C1P + 2 * pc], sacc[oc][C1P + 2 * pc + 1]));
        p1pre[((size_t)img * 64 + oc) * 1764 + bx * 42 + pc] = v;
    }
    if (tid < 128) {
        int oc = tid >> 1, wh = tid & 1;
        st1[(((size_t)img * 42 + bx) * 64 + oc) * 2 + wh] =
            s_stats[0][oc][wh] + s_stats[1][oc][wh];
    }
}

// ---------------------------------------------------------------------------
// Fused stats (unchanged). grid (64), 256 threads.
// ---------------------------------------------------------------------------
__global__ void stats_fused_kernel(const float* __restrict__ st1, int NB,
                                   int HW,
                                   const float* __restrict__ gamma,
                                   const float* __restrict__ beta,
                                   float* __restrict__ scale,
                                   float* __restrict__ shift) {
    const int c = blockIdx.x;
    const int tid = threadIdx.x;
    float a[6][2];
#pragma unroll
    for (int g = 0; g < 6; g++) { a[g][0] = 0.f; a[g][1] = 0.f; }
    const int total = NIMG * NB;
    for (int i = tid; i < total; i += 256) {
        int img = i / NB, blk = i % NB;
        int g = img_group(img);
        const float* p = &st1[(((size_t)img * NB + blk) * 64 + c) * 2];
        a[g][0] += p[0];
        a[g][1] += p[1];
    }
    __shared__ float sm[256][12];
#pragma unroll
    for (int g = 0; g < 6; g++) {
        sm[tid][2 * g] = a[g][0];
        sm[tid][2 * g + 1] = a[g][1];
    }
    __syncthreads();
    for (int off = 128; off > 0; off >>= 1) {
        if (tid < off)
#pragma unroll
            for (int j = 0; j < 12; j++) sm[tid][j] += sm[tid + off][j];
        __syncthreads();
    }
    if (tid < 6) {
        int g = tid;
        int nimg = (g == 0) ? 32 : 5;
        float cnt = (float)(nimg * HW);
        float m = sm[0][2 * g] / cnt;
        float var = sm[0][2 * g + 1] / cnt - m * m;
        float inv = rsqrtf(var + 1e-5f);
        float sc = gamma[c] * inv;
        scale[g * 64 + c] = sc;
        shift[g * 64 + c] = beta[c] - m * sc;
    }
}

// ---------------------------------------------------------------------------
// conv64 tf32 shift-GEMM with PAIRED-K smem: 64-bit word
//   s64[(ci&3)*CIP + r*PITCH + c] = ( v[ci], v[ci+4] )
// so each mma's two B operands are ONE LDS.64. CIP chosen with
// 2*CIP % 32 == 8 so the four k-groups + n-lanes are conflict-free.
// MODE: 0 raw; 1 BN+LReLU; 2 BN+LReLU+2x2 maxpool on 2H-sized input.
// ---------------------------------------------------------------------------
template <int H, int NROWS, int PITCH, int CIP, int MODE>
__global__ void __launch_bounds__(256) conv_mma_kernel(
    const float* __restrict__ in, const float* __restrict__ wbuf,
    float* __restrict__ out,
    const float* __restrict__ scale, const float* __restrict__ shift,
    float* __restrict__ st1) {
    constexpr int R = NROWS + 2;
    constexpr int W = H;
    constexpr int HW = H * H;
    constexpr int TOT = 8 * R * (W + 2);
    constexpr int IN_HW = (MODE == 2) ? 4 * HW : HW;
    constexpr int IN_W = (MODE == 2) ? 2 * W : W;

    __shared__ unsigned long long s64[4 * CIP];
    __shared__ float s_stats[2][64][2];
    u32* s32 = (u32*)s64;

    const int rb = blockIdx.x * NROWS;
    const int img = blockIdx.y;
    const int tid = threadIdx.x;
    const int wid = tid >> 5, lane = tid & 31;
    const int wm = wid & 3, wn = wid >> 2;
    const int g = img_group(img);
    const int vrows = min(rb + NROWS, H) - rb;
    const int valid = vrows * W;

    // per-lane B addresses in 64-bit units
    u32 baddr[8];
    {
        u32 kq = (u32)(lane & 3) * CIP;
#pragma unroll
        for (int n8 = 0; n8 < 8; n8++) {
            int n = wn * 64 + n8 * 8 + (lane >> 2);
            u32 poff = 0;
            if (n < valid) poff = (u32)((n / W) * PITCH + (n % W));
            baddr[n8] = kq + poff;
        }
    }

    float acc[8][4];
#pragma unroll
    for (int n8 = 0; n8 < 8; n8++)
#pragma unroll
        for (int j = 0; j < 4; j++) acc[n8][j] = 0.f;

    const float* ip = in + (size_t)img * 64 * IN_HW;

    for (int cc = 0; cc < 8; cc++) {
        __syncthreads();
        for (int i = tid; i < TOT; i += 256) {
            int ci = i / (R * (W + 2));
            int rem = i % (R * (W + 2));
            int r = rem / (W + 2), c = rem % (W + 2);
            int gy = rb - 1 + r, gx = c - 1;
            float v = 0.f;
            if (gy >= 0 && gy < H && gx >= 0 && gx < W) {
                int ch = cc * 8 + ci;
                if (MODE == 2) {
                    float sc = scale[g * 64 + ch], sf = shift[g * 64 + ch];
                    const float* q = ip + (size_t)ch * IN_HW +
                                     (2 * gy) * IN_W + 2 * gx;
                    float v0 = lrelu(fmaf(q[0], sc, sf));
                    float v1 = lrelu(fmaf(q[1], sc, sf));
                    float v2 = lrelu(fmaf(q[IN_W], sc, sf));
                    float v3 = lrelu(fmaf(q[IN_W + 1], sc, sf));
                    v = fmaxf(fmaxf(v0, v1), fmaxf(v2, v3));
                } else {
                    v = ip[(size_t)ch * IN_HW + gy * W + gx];
                    if (MODE == 1)
                        v = lrelu(fmaf(v, scale[g * 64 + ch],
                                       shift[g * 64 + ch]));
                }
            }
            // paired-k store: word (ci&3)*CIP + r*PITCH + c, half ci>>2
            s32[2 * ((ci & 3) * CIP + r * PITCH + c) + (ci >> 2)] = f2tf32(v);
        }
        __syncthreads();

#pragma unroll
        for (int t = 0; t < 9; t++) {
            const int dy = t / 3, dx = t % 3;
            const int soff = dy * PITCH + dx;
            float4 af = *(const float4*)&wbuf[(((cc * 9 + t) * 4 + wm) * 32 +
                                              lane) * 4];
            u32 a0 = __float_as_uint(af.x);
            u32 a1 = __float_as_uint(af.y);
            u32 a2 = __float_as_uint(af.z);
            u32 a3 = __float_as_uint(af.w);
#pragma unroll
            for (int n8 = 0; n8 < 8; n8++) {
                uint2 b01 = ((const uint2*)s64)[baddr[n8] + soff];
                mma_tf32(acc[n8], a0, a1, a2, a3, b01.x, b01.y);
            }
        }
    }

    const int r0 = wm * 16 + (lane >> 2);
    float* op0 = out + ((size_t)img * 64 + r0) * HW;
    float* op1 = out + ((size_t)img * 64 + r0 + 8) * HW;
    float s0 = 0.f, q0 = 0.f, s1 = 0.f, q1 = 0.f;
#pragma unroll
    for (int n8 = 0; n8 < 8; n8++) {
        int nb = wn * 64 + n8 * 8 + 2 * (lane & 3);
        if (nb < valid) {
            int p = (rb + nb / W) * W + nb % W;
            float v0 = acc[n8][0], v1 = acc[n8][2];
            op0[p] = v0;
            op1[p] = v1;
            s0 += v0; q0 = fmaf(v0, v0, q0);
            s1 += v1; q1 = fmaf(v1, v1, q1);
        }
        if (nb + 1 < valid) {
            int p = (rb + (nb + 1) / W) * W + (nb + 1) % W;
            float v0 = acc[n8][1], v1 = acc[n8][3];
            op0[p] = v0;
            op1[p] = v1;
            s0 += v0; q0 = fmaf(v0, v0, q0);
            s1 += v1; q1 = fmaf(v1, v1, q1);
        }
    }
#pragma unroll
    for (int off = 1; off <= 2; off <<= 1) {
        s0 += __shfl_xor_sync(0xffffffffu, s0, off);
        q0 += __shfl_xor_sync(0xffffffffu, q0, off);
        s1 += __shfl_xor_sync(0xffffffffu, s1, off);
        q1 += __shfl_xor_sync(0xffffffffu, q1, off);
    }
    if ((lane & 3) == 0) {
        s_stats[wn][r0][0] = s0;
        s_stats[wn][r0][1] = q0;
        s_stats[wn][r0 + 8][0] = s1;
        s_stats[wn][r0 + 8][1] = q1;
    }
    __syncthreads();
    if (tid < 128) {
        int oc = tid >> 1, wh = tid & 1;
        st1[(((size_t)img * gridDim.x + blockIdx.x) * 64 + oc) * 2 + wh] =
            s_stats[0][oc][wh] + s_stats[1][oc][wh];
    }
}

// ---------------------------------------------------------------------------
// qsnorm (unchanged).
// ---------------------------------------------------------------------------
__global__ void qsnorm_kernel(const float* __restrict__ f,
                              const float* __restrict__ scale,
                              const float* __restrict__ shift,
                              __nv_bfloat16* __restrict__ Qh,
                              __nv_bfloat16* __restrict__ ShK) {
    int idx = blockIdx.x * blockDim.x + threadIdx.x;
    if (idx < 32 * 441) {
        int b = idx / 441, pix = idx % 441;
        const float* p = f + (size_t)b * 64 * 441 + pix;
        float vals[64];
        float s = 0.f;
#pragma unroll 8
        for (int c = 0; c < 64; c++) {
            float v = lrelu(fmaf(p[c * 441], scale[c], shift[c]));
            vals[c] = v;
            s = fmaf(v, v, s);
        }
        float inv = rsqrtf(s);
        __nv_bfloat162* op = (__nv_bfloat162*)&Qh[(size_t)idx * 64];
#pragma unroll 8
        for (int c = 0; c < 32; c++)
            op[c] = __floats2bfloat162_rn(vals[2 * c] * inv,
                                          vals[2 * c + 1] * inv);
    } else if (idx < 32 * 441 + 5 * 2240) {
        int r = idx - 32 * 441;
        int n = r / 2240, m = r % 2240;
        if (m >= 2205) {
#pragma unroll 8
            for (int c = 0; c < 64; c++)
                ShK[((size_t)n * 64 + c) * 2240 + m] = __float2bfloat16(0.f);
            return;
        }
        int sh = m / 441, pix = m % 441;
        int img = 32 + n * 5 + sh;
        int g = 1 + n;
        const float* p = f + (size_t)img * 64 * 441 + pix;
        float vals[64];
        float s = 0.f;
#pragma unroll 8
        for (int c = 0; c < 64; c++) {
            float v = lrelu(fmaf(p[c * 441], scale[g * 64 + c],
                                 shift[g * 64 + c]));
            vals[c] = v;
            s = fmaf(v, v, s);
        }
        float inv = rsqrtf(s);
#pragma unroll 8
        for (int c = 0; c < 64; c++)
            ShK[((size_t)n * 64 + c) * 2240 + m] =
                __float2bfloat16(vals[c] * inv);
    }
}

// ---------------------------------------------------------------------------
// sims via mma.sync m16n8k16 bf16, 128 rows/block (unchanged).
// ---------------------------------------------------------------------------
#define SPAD 72

__device__ __forceinline__ void ins3(float v, float& t0, float& t1, float& t2) {
    float lo = fminf(v, t0);
    t0 = fmaxf(v, t0);
    float mid = fminf(lo, t1);
    t1 = fmaxf(lo, t1);
    t2 = fmaxf(t2, mid);
}

__global__ void __launch_bounds__(256) sims_mma_kernel(
    const __nv_bfloat16* __restrict__ Qh,
    const __nv_bfloat16* __restrict__ ShK,
    float* __restrict__ part) {
    __shared__ __nv_bfloat16 sQ[128][SPAD];
    __shared__ __nv_bfloat16 sS[64][SPAD];
    __shared__ float red[8];

    const int rchunk = blockIdx.x;
    const int n = blockIdx.y;
    const int b = blockIdx.z;
    const int rbase = rchunk * 128;
    const int tid = threadIdx.x;
    const int wid = tid >> 5, lane = tid & 31;

    for (int i = tid; i < 128 * 8; i += 256) {
        int r = i >> 3, c8 = i & 7;
        uint4 v = make_uint4(0u, 0u, 0u, 0u);
        if (rbase + r < 441)
            v = *(const uint4*)&Qh[((size_t)(b * 441 + rbase + r)) * 64 + c8 * 8];
        *(uint4*)&sQ[r][c8 * 8] = v;
    }
    __syncthreads();

    const u32 sQb = smem_u32(&sQ[0][0]);
    const u32 sSb = smem_u32(&sS[0][0]);
    const int m0 = wid * 16;

    u32 afr[4][4];
    {
        int rr = m0 + (lane & 15);
        int cc = (lane >> 4) * 8;
#pragma unroll
        for (int ks = 0; ks < 4; ks++)
            ldsm_x4(afr[ks][0], afr[ks][1], afr[ks][2], afr[ks][3],
                    sQb + (u32)((rr * SPAD + ks * 16 + cc) * 2));
    }

    float ta0 = -1e30f, ta1 = -1e30f, ta2 = -1e30f;
    float tb0 = -1e30f, tb1 = -1e30f, tb2 = -1e30f;

    const __nv_bfloat16* Sbase = ShK + (size_t)n * 64 * 2240;

    for (int tile = 0; tile < 35; tile++) {
        const int c0 = tile * 64;
        __syncthreads();
        for (int i = tid; i < 64 * 8; i += 256) {
            int k = i >> 3, p8 = i & 7;
            uint4 v = *(const uint4*)&Sbase[(size_t)k * 2240 + c0 + p8 * 8];
            *(uint4*)&sS[k][p8 * 8] = v;
        }
        __syncthreads();

        float d[8][4];
#pragma unroll
        for (int j = 0; j < 8; j++)
#pragma unroll
            for (int c = 0; c < 4; c++) d[j][c] = 0.f;

        const int kr_l = (lane & 7) + ((lane >> 3) & 1) * 8;
        const int nc_l = (lane >> 4) * 8;
#pragma unroll
        for (int ks = 0; ks < 4; ks++) {
            int kr = ks * 16 + kr_l;
#pragma unroll
            for (int n16 = 0; n16 < 4; n16++) {
                u32 b0, b1, b2, b3;
                ldsm_x4t(b0, b1, b2, b3,
                         sSb + (u32)((kr * SPAD + n16 * 16 + nc_l) * 2));
                mma16816(d[2 * n16], afr[ks], b0, b1);
                mma16816(d[2 * n16 + 1], afr[ks], b2, b3);
            }
        }

        if (tile != 34) {
#pragma unroll
            for (int n8 = 0; n8 < 8; n8++) {
                ins3(d[n8][0], ta0, ta1, ta2);
                ins3(d[n8][1], ta0, ta1, ta2);
                ins3(d[n8][2], tb0, tb1, tb2);
                ins3(d[n8][3], tb0, tb1, tb2);
            }
        } else {
            int cb = c0 + 2 * (lane & 3);
#pragma unroll
            for (int n8 = 0; n8 < 8; n8++) {
                int c = cb + n8 * 8;
                if (c < 2205) { ins3(d[n8][0], ta0, ta1, ta2);
                                ins3(d[n8][2], tb0, tb1, tb2); }
                if (c + 1 < 2205) { ins3(d[n8][1], ta0, ta1, ta2);
                                    ins3(d[n8][3], tb0, tb1, tb2); }
            }
        }
    }

#pragma unroll
    for (int off = 1; off <= 2; off <<= 1) {
        float x0 = __shfl_xor_sync(0xffffffffu, ta0, off);
        float x1 = __shfl_xor_sync(0xffffffffu, ta1, off);
        float x2 = __shfl_xor_sync(0xffffffffu, ta2, off);
        ins3(x0, ta0, ta1, ta2);
        ins3(x1, ta0, ta1, ta2);
        ins3(x2, ta0, ta1, ta2);
        float y0 = __shfl_xor_sync(0xffffffffu, tb0, off);
        float y1 = __shfl_xor_sync(0xffffffffu, tb1, off);
        float y2 = __shfl_xor_sync(0xffffffffu, tb2, off);
        ins3(y0, tb0, tb1, tb2);
        ins3(y1, tb0, tb1, tb2);
        ins3(y2, tb0, tb1, tb2);
    }

    float s = 0.f;
    if ((lane & 3) == 0) {
        int r1 = rbase + m0 + (lane >> 2);
        if (r1 < 441) s += ta0 + ta1 + ta2;
        if (r1 + 8 < 441) s += tb0 + tb1 + tb2;
    }
#pragma unroll
    for (int off = 16; off > 0; off >>= 1)
        s += __shfl_down_sync(0xffffffffu, s, off);
    if (lane == 0) red[wid] = s;
    __syncthreads();
    if (tid == 0) {
        float r = 0.f;
#pragma unroll
        for (int i = 0; i < 8; i++) r += red[i];
        part[(b * 5 + n) * 4 + rchunk] = r;
    }
}

__global__ void finalize_kernel(const float* __restrict__ part,
                                float* __restrict__ out) {
    int i = threadIdx.x;
    if (i < 160) {
        float s = 0.f;
#pragma unroll
        for (int k = 0; k < 4; k++) s += part[4 * i + k];
        out[i] = s;
    }
}

// ---------------------------------------------------------------------------
extern "C" void kernel_launch(void* const* d_in, const int* in_sizes, int n_in,
                              void* d_out, int out_size) {
    const float* input1 = (const float*)d_in[0];
    const float* input2 = (const float*)d_in[1];
    const float* w1 = (const float*)d_in[2];
    const float* g1 = (const float*)d_in[3];
    const float* b1 = (const float*)d_in[4];
    const float* w2 = (const float*)d_in[5];
    const float* g2 = (const float*)d_in[6];
    const float* b2 = (const float*)d_in[7];
    const float* w3 = (const float*)d_in[8];
    const float* g3 = (const float*)d_in[9];
    const float* b3 = (const float*)d_in[10];
    const float* w4 = (const float*)d_in[11];
    const float* g4 = (const float*)d_in[12];
    const float* b4 = (const float*)d_in[13];
    float* out = (float*)d_out;

    void* poolPtr = nullptr;
    cudaGetSymbolAddress(&poolPtr, d_pool);
    float* P = (float*)poolPtr;
    float* p1pre = P + OFF_P1;
    float* c2 = P + OFF_C2;
    float* c3 = P + OFF_C3;
    float* c4 = P + OFF_C4;
    __nv_bfloat16* Qh = (__nv_bfloat16*)(P + OFF_QH);
    __nv_bfloat16* ShK = (__nv_bfloat16*)(P + OFF_SK);
    float* sc = P + OFF_SC;
    float* sh = P + OFF_SHF;
    float* part = P + OFF_PART;
    float* wb2 = P + OFF_WB;
    float* wb3 = P + OFF_WB + 36864;
    float* wb4 = P + OFF_WB + 2 * 36864;
    float* wb1 = P + OFF_WB1;
    float* st1 = P + OFF_ST1;

    wprep_kernel<<<(3 * 36864 + 2048 + 255) / 256, 256>>>(w1, w2, w3, w4,
                                                          wb2, wb1);
    conv1_pool_kernel<<<dim3(42, NIMG), 256>>>(input1, input2, wb1, p1pre, st1);
    stats_fused_kernel<<<64, 256>>>(st1, 42, 7056, g1, b1, sc, sh);
    // H=42: PITCH=44, CIP=228 (2*CIP%32==8 -> conflict-free LDS.64)
    conv_mma_kernel<42, 3, 44, 228, 1><<<dim3(14, NIMG), 256>>>(
        p1pre, wb2, c2, sc, sh, st1);
    stats_fused_kernel<<<64, 256>>>(st1, 14, 1764, g2, b2, sc, sh);
    // H=21: PITCH=24, CIP=196
    conv_mma_kernel<21, 6, 24, 196, 2><<<dim3(4, NIMG), 256>>>(
        c2, wb3, c3, sc, sh, st1);
    stats_fused_kernel<<<64, 256>>>(st1, 4, 441, g3, b3, sc, sh);
    conv_mma_kernel<21, 6, 24, 196, 1><<<dim3(4, NIMG), 256>>>(
        c3, wb4, c4, sc, sh, st1);
    stats_fused_kernel<<<64, 256>>>(st1, 4, 441, g4, b4, sc, sh);
    qsnorm_kernel<<<(32 * 441 + 5 * 2240 + 127) / 128, 128>>>(c4, sc, sh,
                                                              Qh, ShK);
    sims_mma_kernel<<<dim3(4, 5, 32), 256>>>(Qh, ShK, part);
    finalize_kernel<<<1, 160>>>(part, out);
}

// round 13
// speedup vs baseline: 1.0294x; 1.0294x over previous
#include <cuda_runtime.h>
#include <cuda_bf16.h>
#include <math.h>

// ---------------------------------------------------------------------------
// FourLayer_64F. Round 13: per-layer best-of — conv2 uses a 2M x 4N warp
// layout over paired-k smem (one LDS.64 feeds two mma, halving B crossbar
// traffic); conv3/conv4 restore the Round-11 pipelined double-buffer kernel.
// Rest = Round 10/11 structure (12 launches, fused BN stats/pool, bf16 sims).
// ---------------------------------------------------------------------------

#define NIMG 57
#define NEG_SLOPE 0.2f

typedef unsigned int u32;

__device__ __forceinline__ u32 f2tf32(float v) {
    u32 r;
    asm("cvt.rna.tf32.f32 %0, %1;" : "=r"(r) : "f"(v));
    return r;
}

// ---------------- scratch pool (floats) ------------------------------------
#define OFF_P1   ((size_t)0)                        // 57*64*1764 pooled pre-BN1
#define OFF_C2   (OFF_P1 + (size_t)57*64*1764)      // 57*64*1764
#define OFF_C3   (OFF_C2 + (size_t)57*64*1764)      // 57*64*441
#define OFF_C4   (OFF_C3 + (size_t)57*64*441)
#define OFF_QH   (OFF_C4 + (size_t)57*64*441)       // bf16 32*441*64 -> 451584 f
#define OFF_SK   (OFF_QH + (size_t)451584)          // bf16 5*64*2240 -> 358400 f
#define OFF_SC   (OFF_SK + (size_t)358400)          // 6*64 scale
#define OFF_SHF  (OFF_SC + 384)                     // 6*64 shift
#define OFF_PART (OFF_SHF + 384)                    // 32*5*4
#define OFF_WB   (OFF_PART + 640)                   // 3*36864 conv64 weights
#define OFF_WB1  (OFF_WB + (size_t)3*36864)         // 2048 conv1 weights
#define OFF_ST1  (OFF_WB1 + 2048)                   // 57*42*64*2 block partials
#define POOL_TOTAL (OFF_ST1 + (size_t)57*42*64*2)

__device__ float d_pool[POOL_TOTAL];

__device__ __forceinline__ float lrelu(float v) {
    return v >= 0.f ? v : NEG_SLOPE * v;
}
__device__ __forceinline__ int img_group(int img) {
    return (img < 32) ? 0 : 1 + (img - 32) / 5;
}

__device__ __forceinline__ u32 smem_u32(const void* p) {
    u32 a;
    asm("{ .reg .u64 t; cvta.to.shared.u64 t, %1; cvt.u32.u64 %0, t; }"
        : "=r"(a) : "l"(p));
    return a;
}
__device__ __forceinline__ void ldsm_x4(u32& r0, u32& r1, u32& r2, u32& r3,
                                        u32 addr) {
    asm volatile("ldmatrix.sync.aligned.m8n8.x4.shared.b16 {%0,%1,%2,%3}, [%4];"
                 : "=r"(r0), "=r"(r1), "=r"(r2), "=r"(r3) : "r"(addr));
}
__device__ __forceinline__ void ldsm_x4t(u32& r0, u32& r1, u32& r2, u32& r3,
                                         u32 addr) {
    asm volatile(
        "ldmatrix.sync.aligned.m8n8.x4.trans.shared.b16 {%0,%1,%2,%3}, [%4];"
        : "=r"(r0), "=r"(r1), "=r"(r2), "=r"(r3) : "r"(addr));
}
__device__ __forceinline__ void mma16816(float* d, const u32* a, u32 b0, u32 b1) {
    asm volatile(
        "mma.sync.aligned.m16n8k16.row.col.f32.bf16.bf16.f32 "
        "{%0,%1,%2,%3}, {%4,%5,%6,%7}, {%8,%9}, {%0,%1,%2,%3};"
        : "+f"(d[0]), "+f"(d[1]), "+f"(d[2]), "+f"(d[3])
        : "r"(a[0]), "r"(a[1]), "r"(a[2]), "r"(a[3]), "r"(b0), "r"(b1));
}
__device__ __forceinline__ void mma_tf32(float* d, u32 a0, u32 a1, u32 a2,
                                         u32 a3, u32 b0, u32 b1) {
    asm volatile(
        "mma.sync.aligned.m16n8k8.row.col.f32.tf32.tf32.f32 "
        "{%0,%1,%2,%3}, {%4,%5,%6,%7}, {%8,%9}, {%0,%1,%2,%3};"
        : "+f"(d[0]), "+f"(d[1]), "+f"(d[2]), "+f"(d[3])
        : "r"(a0), "r"(a1), "r"(a2), "r"(a3), "r"(b0), "r"(b1));
}

// ---------------------------------------------------------------------------
// Weight prep for all four conv layers in ONE launch (unchanged).
// ---------------------------------------------------------------------------
__global__ void wprep_kernel(const float* __restrict__ w1,
                             const float* __restrict__ w2,
                             const float* __restrict__ w3,
                             const float* __restrict__ w4,
                             float* __restrict__ wbuf,
                             float* __restrict__ wbuf1) {
    int idx = blockIdx.x * 256 + threadIdx.x;
    if (idx < 3 * 36864) {
        int which = idx / 36864;
        int r = idx % 36864;
        const float* w = (which == 0) ? w2 : (which == 1) ? w3 : w4;
        int j = r & 3;
        int lane = (r >> 2) & 31;
        int wm = (r >> 7) & 3;
        int rest = r >> 9;
        int t = rest % 9, cc = rest / 9;
        int oc = wm * 16 + (lane >> 2) + (j & 1) * 8;
        int ci = cc * 8 + (lane & 3) + ((j >> 1) & 1) * 4;
        wbuf[idx] = __uint_as_float(f2tf32(w[(oc * 64 + ci) * 9 + t]));
    } else if (idx < 3 * 36864 + 2048) {
        int r = idx - 3 * 36864;
        int j = r & 3;
        int lane = (r >> 2) & 31;
        int wm = (r >> 7) & 3;
        int ks = r >> 9;
        int oc = wm * 16 + (lane >> 2) + (j & 1) * 8;
        int k = ks * 8 + (lane & 3) + ((j >> 1) & 1) * 4;
        float v = 0.f;
        if (k < 27) v = w1[(oc * 3 + k / 9) * 9 + (k % 9)];
        wbuf1[r] = __uint_as_float(f2tf32(v));
    }
}

// ---------------------------------------------------------------------------
// conv1 + maxpool, tf32 shift-GEMM (unchanged). grid (42, 57).
// ---------------------------------------------------------------------------
#define C1P 88
#define C1CIP 360

__global__ void __launch_bounds__(256) conv1_pool_kernel(
    const float* __restrict__ in1, const float* __restrict__ in2,
    const float* __restrict__ wbuf1, float* __restrict__ p1pre,
    float* __restrict__ st1) {
    __shared__ char sraw[45056];
    __shared__ float s_stats[2][64][2];
    u32* s_in = (u32*)sraw;
    float(*sacc)[176] = (float(*)[176])sraw;

    const int bx = blockIdx.x;
    const int img = blockIdx.y;
    const int tid = threadIdx.x;
    const int wid = tid >> 5, lane = tid & 31;
    const int wm = wid & 3, wn = wid >> 2;

    const float* ip = (img < 32) ? (in1 + (size_t)img * 3 * 7056)
                                 : (in2 + (size_t)(img - 32) * 3 * 7056);

    for (int i = tid; i < 3 * 4 * C1P; i += 256) {
        int ci = i / (4 * C1P);
        int rem = i % (4 * C1P);
        int r = rem / C1P, c = rem % C1P;
        int gy = 2 * bx - 1 + r, gx = c - 1;
        float v = 0.f;
        if (gy >= 0 && gy < 84 && gx >= 0 && gx < 84)
            v = ip[ci * 7056 + gy * 84 + gx];
        s_in[ci * C1CIP + r * C1P + c] = f2tf32(v);
    }
    if (tid < 24)
        s_in[(tid / 8) * C1CIP + 4 * C1P + (tid % 8)] = 0u;
    __syncthreads();

    u32 koffA[4], koffB[4];
#pragma unroll
    for (int ks = 0; ks < 4; ks++) {
        int kA = ks * 8 + (lane & 3), kB = kA + 4;
        koffA[ks] = (kA < 27)
            ? (u32)((kA / 9) * C1CIP + ((kA % 9) / 3) * C1P + (kA % 9) % 3)
            : 0u;
        koffB[ks] = (kB < 27)
            ? (u32)((kB / 9) * C1CIP + ((kB % 9) / 3) * C1P + (kB % 9) % 3)
            : 0u;
    }
    const u32 pixrow = (u32)(wn * C1P) + (u32)(lane >> 2);

    float acc[11][4];
#pragma unroll
    for (int n8 = 0; n8 < 11; n8++)
#pragma unroll
        for (int j = 0; j < 4; j++) acc[n8][j] = 0.f;

#pragma unroll
    for (int ks = 0; ks < 4; ks++) {
        float4 af = *(const float4*)&wbuf1[((ks * 4 + wm) * 32 + lane) * 4];
        u32 a0 = __float_as_uint(af.x);
        u32 a1 = __float_as_uint(af.y);
        u32 a2 = __float_as_uint(af.z);
        u32 a3 = __float_as_uint(af.w);
#pragma unroll
        for (int n8 = 0; n8 < 11; n8++) {
            u32 p = pixrow + n8 * 8;
            u32 b0 = s_in[koffA[ks] + p];
            u32 b1 = s_in[koffB[ks] + p];
            mma_tf32(acc[n8], a0, a1, a2, a3, b0, b1);
        }
    }
    __syncthreads();

    const int oc0 = wm * 16 + (lane >> 2);
    float s0 = 0.f, q0 = 0.f, s1 = 0.f, q1 = 0.f;
#pragma unroll
    for (int n8 = 0; n8 < 11; n8++) {
        int col = n8 * 8 + 2 * (lane & 3);
        if (col < 84) {
            float v0 = acc[n8][0], v1 = acc[n8][2];
            sacc[oc0][wn * C1P + col] = v0;
            sacc[oc0 + 8][wn * C1P + col] = v1;
            s0 += v0; q0 = fmaf(v0, v0, q0);
            s1 += v1; q1 = fmaf(v1, v1, q1);
        }
        if (col + 1 < 84) {
            float v0 = acc[n8][1], v1 = acc[n8][3];
            sacc[oc0][wn * C1P + col + 1] = v0;
            sacc[oc0 + 8][wn * C1P + col + 1] = v1;
            s0 += v0; q0 = fmaf(v0, v0, q0);
            s1 += v1; q1 = fmaf(v1, v1, q1);
        }
    }
#pragma unroll
    for (int off = 1; off <= 2; off <<= 1) {
        s0 += __shfl_xor_sync(0xffffffffu, s0, off);
        q0 += __shfl_xor_sync(0xffffffffu, q0, off);
        s1 += __shfl_xor_sync(0xffffffffu, s1, off);
        q1 += __shfl_xor_sync(0xffffffffu, q1, off);
    }
    if ((lane & 3) == 0) {
        s_stats[wn][oc0][0] = s0;
        s_stats[wn][oc0][1] = q0;
        s_stats[wn][oc0 + 8][0] = s1;
        s_stats[wn][oc0 + 8][1] = q1;
    }
    __syncthreads();

    for (int i = tid; i < 64 * 42; i += 256) {
        int oc = i / 42, pc = i % 42;
        float v = fmaxf(fmaxf(sacc[oc][2 * pc], sacc[oc][2 * pc + 1]),
                        fmaxf(sacc[oc][C1P + 2 * pc], sacc[oc][C1P + 2 * pc + 1]));
        p1pre[((size_t)img * 64 + oc) * 1764 + bx * 42 + pc] = v;
    }
    if (tid < 128) {
        int oc = tid >> 1, wh = tid & 1;
        st1[(((size_t)img * 42 + bx) * 64 + oc) * 2 + wh] =
            s_stats[0][oc][wh] + s_stats[1][oc][wh];
    }
}

// ---------------------------------------------------------------------------
// Fused stats (unchanged). grid (64), 256 threads.
// ---------------------------------------------------------------------------
__global__ void stats_fused_kernel(const float* __restrict__ st1, int NB,
                                   int HW,
                                   const float* __restrict__ gamma,
                                   const float* __restrict__ beta,
                                   float* __restrict__ scale,
                                   float* __restrict__ shift) {
    const int c = blockIdx.x;
    const int tid = threadIdx.x;
    float a[6][2];
#pragma unroll
    for (int g = 0; g < 6; g++) { a[g][0] = 0.f; a[g][1] = 0.f; }
    const int total = NIMG * NB;
    for (int i = tid; i < total; i += 256) {
        int img = i / NB, blk = i % NB;
        int g = img_group(img);
        const float* p = &st1[(((size_t)img * NB + blk) * 64 + c) * 2];
        a[g][0] += p[0];
        a[g][1] += p[1];
    }
    __shared__ float sm[256][12];
#pragma unroll
    for (int g = 0; g < 6; g++) {
        sm[tid][2 * g] = a[g][0];
        sm[tid][2 * g + 1] = a[g][1];
    }
    __syncthreads();
    for (int off = 128; off > 0; off >>= 1) {
        if (tid < off)
#pragma unroll
            for (int j = 0; j < 12; j++) sm[tid][j] += sm[tid + off][j];
        __syncthreads();
    }
    if (tid < 6) {
        int g = tid;
        int nimg = (g == 0) ? 32 : 5;
        float cnt = (float)(nimg * HW);
        float m = sm[0][2 * g] / cnt;
        float var = sm[0][2 * g + 1] / cnt - m * m;
        float inv = rsqrtf(var + 1e-5f);
        float sc = gamma[c] * inv;
        scale[g * 64 + c] = sc;
        shift[g * 64 + c] = beta[c] - m * sc;
    }
}

// ---------------------------------------------------------------------------
// conv2 (H=42): 2M x 4N warp layout over PAIRED-K smem. Each warp: 32 oc
// rows (2 m16 tiles) x 32 pixels; one LDS.64 B-fragment feeds 2 mma.
// MODE=1 (BN+LReLU on input). PITCH=44, CIP=228 (conflict-free LDS.64).
// ---------------------------------------------------------------------------
template <int H, int NROWS, int PITCH, int CIP>
__global__ void __launch_bounds__(256) conv_mma2_kernel(
    const float* __restrict__ in, const float* __restrict__ wbuf,
    float* __restrict__ out,
    const float* __restrict__ scale, const float* __restrict__ shift,
    float* __restrict__ st1) {
    constexpr int R = NROWS + 2;
    constexpr int W = H;
    constexpr int HW = H * H;
    constexpr int TOT = 8 * R * (W + 2);

    __shared__ unsigned long long s64[4 * CIP];
    __shared__ float s_stats[4][64][2];
    u32* s32 = (u32*)s64;

    const int rb = blockIdx.x * NROWS;
    const int img = blockIdx.y;
    const int tid = threadIdx.x;
    const int wid = tid >> 5, lane = tid & 31;
    const int wm2 = wid & 1, wn4 = wid >> 1;  // M half, N quarter
    const int g = img_group(img);
    const int vrows = min(rb + NROWS, H) - rb;
    const int valid = vrows * W;

    u32 baddr[4];
    {
        u32 kq = (u32)(lane & 3) * CIP;
#pragma unroll
        for (int n8 = 0; n8 < 4; n8++) {
            int n = wn4 * 32 + n8 * 8 + (lane >> 2);
            u32 poff = 0;
            if (n < valid) poff = (u32)((n / W) * PITCH + (n % W));
            baddr[n8] = kq + poff;
        }
    }

    float acc[2][4][4];
#pragma unroll
    for (int mt = 0; mt < 2; mt++)
#pragma unroll
        for (int n8 = 0; n8 < 4; n8++)
#pragma unroll
            for (int j = 0; j < 4; j++) acc[mt][n8][j] = 0.f;

    const float* ip = in + (size_t)img * 64 * HW;

    for (int cc = 0; cc < 8; cc++) {
        __syncthreads();
        for (int i = tid; i < TOT; i += 256) {
            int ci = i / (R * (W + 2));
            int rem = i % (R * (W + 2));
            int r = rem / (W + 2), c = rem % (W + 2);
            int gy = rb - 1 + r, gx = c - 1;
            float v = 0.f;
            if (gy >= 0 && gy < H && gx >= 0 && gx < W) {
                int ch = cc * 8 + ci;
                v = ip[(size_t)ch * HW + gy * W + gx];
                v = lrelu(fmaf(v, scale[g * 64 + ch], shift[g * 64 + ch]));
            }
            s32[2 * ((ci & 3) * CIP + r * PITCH + c) + (ci >> 2)] = f2tf32(v);
        }
        __syncthreads();

#pragma unroll
        for (int t = 0; t < 9; t++) {
            const int dy = t / 3, dx = t % 3;
            const int soff = dy * PITCH + dx;
            float4 afA = *(const float4*)&wbuf[(((cc * 9 + t) * 4 +
                                                 wm2 * 2) * 32 + lane) * 4];
            float4 afB = *(const float4*)&wbuf[(((cc * 9 + t) * 4 +
                                                 wm2 * 2 + 1) * 32 + lane) * 4];
            u32 aA0 = __float_as_uint(afA.x), aA1 = __float_as_uint(afA.y);
            u32 aA2 = __float_as_uint(afA.z), aA3 = __float_as_uint(afA.w);
            u32 aB0 = __float_as_uint(afB.x), aB1 = __float_as_uint(afB.y);
            u32 aB2 = __float_as_uint(afB.z), aB3 = __float_as_uint(afB.w);
#pragma unroll
            for (int n8 = 0; n8 < 4; n8++) {
                uint2 b01 = ((const uint2*)s64)[baddr[n8] + soff];
                mma_tf32(acc[0][n8], aA0, aA1, aA2, aA3, b01.x, b01.y);
                mma_tf32(acc[1][n8], aB0, aB1, aB2, aB3, b01.x, b01.y);
            }
        }
    }

#pragma unroll
    for (int mt = 0; mt < 2; mt++) {
        const int r0 = (wm2 * 2 + mt) * 16 + (lane >> 2);
        float* op0 = out + ((size_t)img * 64 + r0) * HW;
        float* op1 = out + ((size_t)img * 64 + r0 + 8) * HW;
        float s0 = 0.f, q0 = 0.f, s1 = 0.f, q1 = 0.f;
#pragma unroll
        for (int n8 = 0; n8 < 4; n8++) {
            int nb = wn4 * 32 + n8 * 8 + 2 * (lane & 3);
            if (nb < valid) {
                int p = (rb + nb / W) * W + nb % W;
                float v0 = acc[mt][n8][0], v1 = acc[mt][n8][2];
                op0[p] = v0;
                op1[p] = v1;
                s0 += v0; q0 = fmaf(v0, v0, q0);
                s1 += v1; q1 = fmaf(v1, v1, q1);
            }
            if (nb + 1 < valid) {
                int p = (rb + (nb + 1) / W) * W + (nb + 1) % W;
                float v0 = acc[mt][n8][1], v1 = acc[mt][n8][3];
                op0[p] = v0;
                op1[p] = v1;
                s0 += v0; q0 = fmaf(v0, v0, q0);
                s1 += v1; q1 = fmaf(v1, v1, q1);
            }
        }
#pragma unroll
        for (int off = 1; off <= 2; off <<= 1) {
            s0 += __shfl_xor_sync(0xffffffffu, s0, off);
            q0 += __shfl_xor_sync(0xffffffffu, q0, off);
            s1 += __shfl_xor_sync(0xffffffffu, s1, off);
            q1 += __shfl_xor_sync(0xffffffffu, q1, off);
        }
        if ((lane & 3) == 0) {
            s_stats[wn4][r0][0] = s0;
            s_stats[wn4][r0][1] = q0;
            s_stats[wn4][r0 + 8][0] = s1;
            s_stats[wn4][r0 + 8][1] = q1;
        }
    }
    __syncthreads();
    if (tid < 128) {
        int oc = tid >> 1, wh = tid & 1;
        st1[(((size_t)img * gridDim.x + blockIdx.x) * 64 + oc) * 2 + wh] =
            s_stats[0][oc][wh] + s_stats[1][oc][wh] +
            s_stats[2][oc][wh] + s_stats[3][oc][wh];
    }
}

// ---------------------------------------------------------------------------
// conv3/conv4 (H=21): Round-11 pipelined double-buffer kernel (verbatim).
// MODE: 1 BN+LReLU; 2 BN+LReLU+2x2 maxpool on 2H-sized input.
// ---------------------------------------------------------------------------
template <int H, int NROWS, int PITCH, int MODE>
__global__ void __launch_bounds__(256) conv_mma_pipe_kernel(
    const float* __restrict__ in, const float* __restrict__ wbuf,
    float* __restrict__ out,
    const float* __restrict__ scale, const float* __restrict__ shift,
    float* __restrict__ st1) {
    constexpr int R = NROWS + 2;
    constexpr int W = H;
    constexpr int HW = H * H;
    constexpr int CIP = R * PITCH;
    constexpr int TOT = 8 * R * (W + 2);
    constexpr int NLD = (TOT + 255) / 256;
    constexpr int IN_HW = (MODE == 2) ? 4 * HW : HW;
    constexpr int IN_W = (MODE == 2) ? 2 * W : W;
    constexpr int VPE = (MODE == 2) ? 4 : 1;

    __shared__ u32 s_in[2][8 * CIP];
    __shared__ float s_stats[2][64][2];

    const int rb = blockIdx.x * NROWS;
    const int img = blockIdx.y;
    const int tid = threadIdx.x;
    const int wid = tid >> 5, lane = tid & 31;
    const int wm = wid & 3, wn = wid >> 2;
    const int g = img_group(img);
    const int vrows = min(rb + NROWS, H) - rb;
    const int valid = vrows * W;

    int l_ci[NLD];
    u32 l_soff[NLD];
    int l_goff[NLD];
#pragma unroll
    for (int j = 0; j < NLD; j++) {
        int i = tid + j * 256;
        if (i < TOT) {
            int ci = i / (R * (W + 2));
            int rem = i % (R * (W + 2));
            int r = rem / (W + 2), c = rem % (W + 2);
            int gy = rb - 1 + r, gx = c - 1;
            l_ci[j] = ci;
            l_soff[j] = (u32)(ci * CIP + r * PITCH + c);
            bool ok = gy >= 0 && gy < H && gx >= 0 && gx < W;
            l_goff[j] = ok ? ((MODE == 2) ? ((2 * gy) * IN_W + 2 * gx)
                                          : (gy * W + gx))
                           : -1;
        } else {
            l_ci[j] = -1;
            l_soff[j] = 0;
            l_goff[j] = -1;
        }
    }

    const float* ip = in + (size_t)img * 64 * IN_HW;
    float vreg[NLD * VPE];

    auto load_stage = [&](int cc) {
#pragma unroll
        for (int j = 0; j < NLD; j++) {
            if (l_ci[j] < 0) continue;
            if (l_goff[j] >= 0) {
                const float* q = ip + (size_t)(cc * 8 + l_ci[j]) * IN_HW +
                                 l_goff[j];
                if (MODE == 2) {
                    vreg[4 * j + 0] = __ldg(q);
                    vreg[4 * j + 1] = __ldg(q + 1);
                    vreg[4 * j + 2] = __ldg(q + IN_W);
                    vreg[4 * j + 3] = __ldg(q + IN_W + 1);
                } else {
                    vreg[j] = __ldg(q);
                }
            } else {
                if (MODE == 2) {
                    vreg[4 * j] = vreg[4 * j + 1] = 0.f;
                    vreg[4 * j + 2] = vreg[4 * j + 3] = 0.f;
                } else {
                    vreg[j] = 0.f;
                }
            }
        }
    };
    auto store_stage = [&](int buf, int cc) {
#pragma unroll
        for (int j = 0; j < NLD; j++) {
            if (l_ci[j] < 0) continue;
            float v = 0.f;
            if (l_goff[j] >= 0) {
                int ch = cc * 8 + l_ci[j];
                if (MODE == 1) {
                    v = lrelu(fmaf(vreg[j], scale[g * 64 + ch],
                                   shift[g * 64 + ch]));
                } else {
                    float sc = scale[g * 64 + ch], sf = shift[g * 64 + ch];
                    float v0 = lrelu(fmaf(vreg[4 * j], sc, sf));
                    float v1 = lrelu(fmaf(vreg[4 * j + 1], sc, sf));
                    float v2 = lrelu(fmaf(vreg[4 * j + 2], sc, sf));
                    float v3 = lrelu(fmaf(vreg[4 * j + 3], sc, sf));
                    v = fmaxf(fmaxf(v0, v1), fmaxf(v2, v3));
                }
            }
            s_in[buf][l_soff[j]] = f2tf32(v);
        }
    };

    u32 baddr[8];
    {
        u32 cipart = (u32)(lane & 3) * CIP;
#pragma unroll
        for (int n8 = 0; n8 < 8; n8++) {
            int n = wn * 64 + n8 * 8 + (lane >> 2);
            u32 poff = 0;
            if (n < valid) poff = (u32)((n / W) * PITCH + (n % W));
            baddr[n8] = cipart + poff;
        }
    }

    float acc[8][4];
#pragma unroll
    for (int n8 = 0; n8 < 8; n8++)
#pragma unroll
        for (int j = 0; j < 4; j++) acc[n8][j] = 0.f;

    load_stage(0);
    store_stage(0, 0);
    __syncthreads();

    for (int cc = 0; cc < 8; cc++) {
        if (cc < 7) load_stage(cc + 1);

        const u32* sb = s_in[cc & 1];
#pragma unroll
        for (int t = 0; t < 9; t++) {
            const int dy = t / 3, dx = t % 3;
            const int soff = dy * PITCH + dx;
            float4 af = *(const float4*)&wbuf[(((cc * 9 + t) * 4 + wm) * 32 +
                                              lane) * 4];
            u32 a0 = __float_as_uint(af.x);
            u32 a1 = __float_as_uint(af.y);
            u32 a2 = __float_as_uint(af.z);
            u32 a3 = __float_as_uint(af.w);
#pragma unroll
            for (int n8 = 0; n8 < 8; n8++) {
                u32 b0 = sb[baddr[n8] + soff];
                u32 b1 = sb[baddr[n8] + soff + 4 * CIP];
                mma_tf32(acc[n8], a0, a1, a2, a3, b0, b1);
            }
        }

        if (cc < 7) store_stage((cc + 1) & 1, cc + 1);
        __syncthreads();
    }

    const int r0 = wm * 16 + (lane >> 2);
    float* op0 = out + ((size_t)img * 64 + r0) * HW;
    float* op1 = out + ((size_t)img * 64 + r0 + 8) * HW;
    float s0 = 0.f, q0 = 0.f, s1 = 0.f, q1 = 0.f;
#pragma unroll
    for (int n8 = 0; n8 < 8; n8++) {
        int nb = wn * 64 + n8 * 8 + 2 * (lane & 3);
        if (nb < valid) {
            int p = (rb + nb / W) * W + nb % W;
            float v0 = acc[n8][0], v1 = acc[n8][2];
            op0[p] = v0;
            op1[p] = v1;
            s0 += v0; q0 = fmaf(v0, v0, q0);
            s1 += v1; q1 = fmaf(v1, v1, q1);
        }
        if (nb + 1 < valid) {
            int p = (rb + (nb + 1) / W) * W + (nb + 1) % W;
            float v0 = acc[n8][1], v1 = acc[n8][3];
            op0[p] = v0;
            op1[p] = v1;
            s0 += v0; q0 = fmaf(v0, v0, q0);
            s1 += v1; q1 = fmaf(v1, v1, q1);
        }
    }
#pragma unroll
    for (int off = 1; off <= 2; off <<= 1) {
        s0 += __shfl_xor_sync(0xffffffffu, s0, off);
        q0 += __shfl_xor_sync(0xffffffffu, q0, off);
        s1 += __shfl_xor_sync(0xffffffffu, s1, off);
        q1 += __shfl_xor_sync(0xffffffffu, q1, off);
    }
    if ((lane & 3) == 0) {
        s_stats[wn][r0][0] = s0;
        s_stats[wn][r0][1] = q0;
        s_stats[wn][r0 + 8][0] = s1;
        s_stats[wn][r0 + 8][1] = q1;
    }
    __syncthreads();
    if (tid < 128) {
        int oc = tid >> 1, wh = tid & 1;
        st1[(((size_t)img * gridDim.x + blockIdx.x) * 64 + oc) * 2 + wh] =
            s_stats[0][oc][wh] + s_stats[1][oc][wh];
    }
}

// ---------------------------------------------------------------------------
// qsnorm (unchanged).
// ---------------------------------------------------------------------------
__global__ void qsnorm_kernel(const float* __restrict__ f,
                              const float* __restrict__ scale,
                              const float* __restrict__ shift,
                              __nv_bfloat16* __restrict__ Qh,
                              __nv_bfloat16* __restrict__ ShK) {
    int idx = blockIdx.x * blockDim.x + threadIdx.x;
    if (idx < 32 * 441) {
        int b = idx / 441, pix = idx % 441;
        const float* p = f + (size_t)b * 64 * 441 + pix;
        float vals[64];
        float s = 0.f;
#pragma unroll 8
        for (int c = 0; c < 64; c++) {
            float v = lrelu(fmaf(p[c * 441], scale[c], shift[c]));
            vals[c] = v;
            s = fmaf(v, v, s);
        }
        float inv = rsqrtf(s);
        __nv_bfloat162* op = (__nv_bfloat162*)&Qh[(size_t)idx * 64];
#pragma unroll 8
        for (int c = 0; c < 32; c++)
            op[c] = __floats2bfloat162_rn(vals[2 * c] * inv,
                                          vals[2 * c + 1] * inv);
    } else if (idx < 32 * 441 + 5 * 2240) {
        int r = idx - 32 * 441;
        int n = r / 2240, m = r % 2240;
        if (m >= 2205) {
#pragma unroll 8
            for (int c = 0; c < 64; c++)
                ShK[((size_t)n * 64 + c) * 2240 + m] = __float2bfloat16(0.f);
            return;
        }
        int sh = m / 441, pix = m % 441;
        int img = 32 + n * 5 + sh;
        int g = 1 + n;
        const float* p = f + (size_t)img * 64 * 441 + pix;
        float vals[64];
        float s = 0.f;
#pragma unroll 8
        for (int c = 0; c < 64; c++) {
            float v = lrelu(fmaf(p[c * 441], scale[g * 64 + c],
                                 shift[g * 64 + c]));
            vals[c] = v;
            s = fmaf(v, v, s);
        }
        float inv = rsqrtf(s);
#pragma unroll 8
        for (int c = 0; c < 64; c++)
            ShK[((size_t)n * 64 + c) * 2240 + m] =
                __float2bfloat16(vals[c] * inv);
    }
}

// ---------------------------------------------------------------------------
// sims via mma.sync m16n8k16 bf16, 128 rows/block (unchanged).
// ---------------------------------------------------------------------------
#define SPAD 72

__device__ __forceinline__ void ins3(float v, float& t0, float& t1, float& t2) {
    float lo = fminf(v, t0);
    t0 = fmaxf(v, t0);
    float mid = fminf(lo, t1);
    t1 = fmaxf(lo, t1);
    t2 = fmaxf(t2, mid);
}

__global__ void __launch_bounds__(256) sims_mma_kernel(
    const __nv_bfloat16* __restrict__ Qh,
    const __nv_bfloat16* __restrict__ ShK,
    float* __restrict__ part) {
    __shared__ __nv_bfloat16 sQ[128][SPAD];
    __shared__ __nv_bfloat16 sS[64][SPAD];
    __shared__ float red[8];

    const int rchunk = blockIdx.x;
    const int n = blockIdx.y;
    const int b = blockIdx.z;
    const int rbase = rchunk * 128;
    const int tid = threadIdx.x;
    const int wid = tid >> 5, lane = tid & 31;

    for (int i = tid; i < 128 * 8; i += 256) {
        int r = i >> 3, c8 = i & 7;
        uint4 v = make_uint4(0u, 0u, 0u, 0u);
        if (rbase + r < 441)
            v = *(const uint4*)&Qh[((size_t)(b * 441 + rbase + r)) * 64 + c8 * 8];
        *(uint4*)&sQ[r][c8 * 8] = v;
    }
    __syncthreads();

    const u32 sQb = smem_u32(&sQ[0][0]);
    const u32 sSb = smem_u32(&sS[0][0]);
    const int m0 = wid * 16;

    u32 afr[4][4];
    {
        int rr = m0 + (lane & 15);
        int cc = (lane >> 4) * 8;
#pragma unroll
        for (int ks = 0; ks < 4; ks++)
            ldsm_x4(afr[ks][0], afr[ks][1], afr[ks][2], afr[ks][3],
                    sQb + (u32)((rr * SPAD + ks * 16 + cc) * 2));
    }

    float ta0 = -1e30f, ta1 = -1e30f, ta2 = -1e30f;
    float tb0 = -1e30f, tb1 = -1e30f, tb2 = -1e30f;

    const __nv_bfloat16* Sbase = ShK + (size_t)n * 64 * 2240;

    for (int tile = 0; tile < 35; tile++) {
        const int c0 = tile * 64;
        __syncthreads();
        for (int i = tid; i < 64 * 8; i += 256) {
            int k = i >> 3, p8 = i & 7;
            uint4 v = *(const uint4*)&Sbase[(size_t)k * 2240 + c0 + p8 * 8];
            *(uint4*)&sS[k][p8 * 8] = v;
        }
        __syncthreads();

        float d[8][4];
#pragma unroll
        for (int j = 0; j < 8; j++)
#pragma unroll
            for (int c = 0; c < 4; c++) d[j][c] = 0.f;

        const int kr_l = (lane & 7) + ((lane >> 3) & 1) * 8;
        const int nc_l = (lane >> 4) * 8;
#pragma unroll
        for (int ks = 0; ks < 4; ks++) {
            int kr = ks * 16 + kr_l;
#pragma unroll
            for (int n16 = 0; n16 < 4; n16++) {
                u32 b0, b1, b2, b3;
                ldsm_x4t(b0, b1, b2, b3,
                         sSb + (u32)((kr * SPAD + n16 * 16 + nc_l) * 2));
                mma16816(d[2 * n16], afr[ks], b0, b1);
                mma16816(d[2 * n16 + 1], afr[ks], b2, b3);
            }
        }

        if (tile != 34) {
#pragma unroll
            for (int n8 = 0; n8 < 8; n8++) {
                ins3(d[n8][0], ta0, ta1, ta2);
                ins3(d[n8][1], ta0, ta1, ta2);
                ins3(d[n8][2], tb0, tb1, tb2);
                ins3(d[n8][3], tb0, tb1, tb2);
            }
        } else {
            int cb = c0 + 2 * (lane & 3);
#pragma unroll
            for (int n8 = 0; n8 < 8; n8++) {
                int c = cb + n8 * 8;
                if (c < 2205) { ins3(d[n8][0], ta0, ta1, ta2);
                                ins3(d[n8][2], tb0, tb1, tb2); }
                if (c + 1 < 2205) { ins3(d[n8][1], ta0, ta1, ta2);
                                    ins3(d[n8][3], tb0, tb1, tb2); }
            }
        }
    }

#pragma unroll
    for (int off = 1; off <= 2; off <<= 1) {
        float x0 = __shfl_xor_sync(0xffffffffu, ta0, off);
        float x1 = __shfl_xor_sync(0xffffffffu, ta1, off);
        float x2 = __shfl_xor_sync(0xffffffffu, ta2, off);
        ins3(x0, ta0, ta1, ta2);
        ins3(x1, ta0, ta1, ta2);
        ins3(x2, ta0, ta1, ta2);
        float y0 = __shfl_xor_sync(0xffffffffu, tb0, off);
        float y1 = __shfl_xor_sync(0xffffffffu, tb1, off);
        float y2 = __shfl_xor_sync(0xffffffffu, tb2, off);
        ins3(y0, tb0, tb1, tb2);
        ins3(y1, tb0, tb1, tb2);
        ins3(y2, tb0, tb1, tb2);
    }

    float s = 0.f;
    if ((lane & 3) == 0) {
        int r1 = rbase + m0 + (lane >> 2);
        if (r1 < 441) s += ta0 + ta1 + ta2;
        if (r1 + 8 < 441) s += tb0 + tb1 + tb2;
    }
#pragma unroll
    for (int off = 16; off > 0; off >>= 1)
        s += __shfl_down_sync(0xffffffffu, s, off);
    if (lane == 0) red[wid] = s;
    __syncthreads();
    if (tid == 0) {
        float r = 0.f;
#pragma unroll
        for (int i = 0; i < 8; i++) r += red[i];
        part[(b * 5 + n) * 4 + rchunk] = r;
    }
}

__global__ void finalize_kernel(const float* __restrict__ part,
                                float* __restrict__ out) {
    int i = threadIdx.x;
    if (i < 160) {
        float s = 0.f;
#pragma unroll
        for (int k = 0; k < 4; k++) s += part[4 * i + k];
        out[i] = s;
    }
}

// ---------------------------------------------------------------------------
extern "C" void kernel_launch(void* const* d_in, const int* in_sizes, int n_in,
                              void* d_out, int out_size) {
    const float* input1 = (const float*)d_in[0];
    const float* input2 = (const float*)d_in[1];
    const float* w1 = (const float*)d_in[2];
    const float* g1 = (const float*)d_in[3];
    const float* b1 = (const float*)d_in[4];
    const float* w2 = (const float*)d_in[5];
    const float* g2 = (const float*)d_in[6];
    const float* b2 = (const float*)d_in[7];
    const float* w3 = (const float*)d_in[8];
    const float* g3 = (const float*)d_in[9];
    const float* b3 = (const float*)d_in[10];
    const float* w4 = (const float*)d_in[11];
    const float* g4 = (const float*)d_in[12];
    const float* b4 = (const float*)d_in[13];
    float* out = (float*)d_out;

    void* poolPtr = nullptr;
    cudaGetSymbolAddress(&poolPtr, d_pool);
    float* P = (float*)poolPtr;
    float* p1pre = P + OFF_P1;
    float* c2 = P + OFF_C2;
    float* c3 = P + OFF_C3;
    float* c4 = P + OFF_C4;
    __nv_bfloat16* Qh = (__nv_bfloat16*)(P + OFF_QH);
    __nv_bfloat16* ShK = (__nv_bfloat16*)(P + OFF_SK);
    float* sc = P + OFF_SC;
    float* sh = P + OFF_SHF;
    float* part = P + OFF_PART;
    float* wb2 = P + OFF_WB;
    float* wb3 = P + OFF_WB + 36864;
    float* wb4 = P + OFF_WB + 2 * 36864;
    float* wb1 = P + OFF_WB1;
    float* st1 = P + OFF_ST1;

    wprep_kernel<<<(3 * 36864 + 2048 + 255) / 256, 256>>>(w1, w2, w3, w4,
                                                          wb2, wb1);
    conv1_pool_kernel<<<dim3(42, NIMG), 256>>>(input1, input2, wb1, p1pre, st1);
    stats_fused_kernel<<<64, 256>>>(st1, 42, 7056, g1, b1, sc, sh);
    // conv2: 2M x 4N paired-k (B traffic halved)
    conv_mma2_kernel<42, 3, 44, 228><<<dim3(14, NIMG), 256>>>(
        p1pre, wb2, c2, sc, sh, st1);
    stats_fused_kernel<<<64, 256>>>(st1, 14, 1764, g2, b2, sc, sh);
    // conv3: R11 pipelined kernel, BN2+LReLU+pool fused on input
    conv_mma_pipe_kernel<21, 6, 25, 2><<<dim3(4, NIMG), 256>>>(
        c2, wb3, c3, sc, sh, st1);
    stats_fused_kernel<<<64, 256>>>(st1, 4, 441, g3, b3, sc, sh);
    // conv4: R11 pipelined kernel, BN3+LReLU fused on input
    conv_mma_pipe_kernel<21, 6, 25, 1><<<dim3(4, NIMG), 256>>>(
        c3, wb4, c4, sc, sh, st1);
    stats_fused_kernel<<<64, 256>>>(st1, 4, 441, g4, b4, sc, sh);
    qsnorm_kernel<<<(32 * 441 + 5 * 2240 + 127) / 128, 128>>>(c4, sc, sh,
                                                              Qh, ShK);
    sims_mma_kernel<<<dim3(4, 5, 32), 256>>>(Qh, ShK, part);
    finalize_kernel<<<1, 160>>>(part, out);
}

// round 14
// speedup vs baseline: 1.1602x; 1.1270x over previous
#include <cuda_runtime.h>
#include <cuda_bf16.h>
#include <math.h>

// ---------------------------------------------------------------------------
// FourLayer_64F. Round 14: conv2 switched to bf16 mma.sync m16n8k16 (halves
// mma count and smem traffic per MAC; ci-paired bf16 smem words). conv1/3/4
// stay tf32 (conv3/4 = R11 pipelined kernel). Rest = R13 structure.
// ---------------------------------------------------------------------------

#define NIMG 57
#define NEG_SLOPE 0.2f

typedef unsigned int u32;

__device__ __forceinline__ u32 f2tf32(float v) {
    u32 r;
    asm("cvt.rna.tf32.f32 %0, %1;" : "=r"(r) : "f"(v));
    return r;
}
__device__ __forceinline__ u32 pack_bf16(float lo, float hi) {
    __nv_bfloat162 p = __floats2bfloat162_rn(lo, hi);
    return *(u32*)&p;
}

// ---------------- scratch pool (floats) ------------------------------------
#define OFF_P1   ((size_t)0)                        // 57*64*1764 pooled pre-BN1
#define OFF_C2   (OFF_P1 + (size_t)57*64*1764)      // 57*64*1764
#define OFF_C3   (OFF_C2 + (size_t)57*64*1764)      // 57*64*441
#define OFF_C4   (OFF_C3 + (size_t)57*64*441)
#define OFF_QH   (OFF_C4 + (size_t)57*64*441)       // bf16 32*441*64 -> 451584 f
#define OFF_SK   (OFF_QH + (size_t)451584)          // bf16 5*64*2240 -> 358400 f
#define OFF_SC   (OFF_SK + (size_t)358400)          // 6*64 scale
#define OFF_SHF  (OFF_SC + 384)                     // 6*64 shift
#define OFF_PART (OFF_SHF + 384)                    // 32*5*4
#define OFF_WB   (OFF_PART + 640)                   // weights: 18432+2*36864
#define OFF_WB1  (OFF_WB + (size_t)(18432 + 2*36864))  // 2048 conv1 weights
#define OFF_ST1  (OFF_WB1 + 2048)                   // 57*42*64*2 block partials
#define POOL_TOTAL (OFF_ST1 + (size_t)57*42*64*2)

__device__ float d_pool[POOL_TOTAL];

__device__ __forceinline__ float lrelu(float v) {
    return v >= 0.f ? v : NEG_SLOPE * v;
}
__device__ __forceinline__ int img_group(int img) {
    return (img < 32) ? 0 : 1 + (img - 32) / 5;
}

__device__ __forceinline__ u32 smem_u32(const void* p) {
    u32 a;
    asm("{ .reg .u64 t; cvta.to.shared.u64 t, %1; cvt.u32.u64 %0, t; }"
        : "=r"(a) : "l"(p));
    return a;
}
__device__ __forceinline__ void ldsm_x4(u32& r0, u32& r1, u32& r2, u32& r3,
                                        u32 addr) {
    asm volatile("ldmatrix.sync.aligned.m8n8.x4.shared.b16 {%0,%1,%2,%3}, [%4];"
                 : "=r"(r0), "=r"(r1), "=r"(r2), "=r"(r3) : "r"(addr));
}
__device__ __forceinline__ void ldsm_x4t(u32& r0, u32& r1, u32& r2, u32& r3,
                                         u32 addr) {
    asm volatile(
        "ldmatrix.sync.aligned.m8n8.x4.trans.shared.b16 {%0,%1,%2,%3}, [%4];"
        : "=r"(r0), "=r"(r1), "=r"(r2), "=r"(r3) : "r"(addr));
}
__device__ __forceinline__ void mma16816(float* d, const u32* a, u32 b0, u32 b1) {
    asm volatile(
        "mma.sync.aligned.m16n8k16.row.col.f32.bf16.bf16.f32 "
        "{%0,%1,%2,%3}, {%4,%5,%6,%7}, {%8,%9}, {%0,%1,%2,%3};"
        : "+f"(d[0]), "+f"(d[1]), "+f"(d[2]), "+f"(d[3])
        : "r"(a[0]), "r"(a[1]), "r"(a[2]), "r"(a[3]), "r"(b0), "r"(b1));
}
__device__ __forceinline__ void mma_tf32(float* d, u32 a0, u32 a1, u32 a2,
                                         u32 a3, u32 b0, u32 b1) {
    asm volatile(
        "mma.sync.aligned.m16n8k8.row.col.f32.tf32.tf32.f32 "
        "{%0,%1,%2,%3}, {%4,%5,%6,%7}, {%8,%9}, {%0,%1,%2,%3};"
        : "+f"(d[0]), "+f"(d[1]), "+f"(d[2]), "+f"(d[3])
        : "r"(a0), "r"(a1), "r"(a2), "r"(a3), "r"(b0), "r"(b1));
}

// ---------------------------------------------------------------------------
// Weight prep, one launch:
//   [0, 18432):           conv2 bf16 A-fragments (m16n8k16 layout)
//   [18432, 18432+73728): conv3/conv4 tf32 A-fragments (old layout)
//   then 2048:            conv1 tf32 (K=27 padded to 32)
// ---------------------------------------------------------------------------
__global__ void wprep_kernel(const float* __restrict__ w1,
                             const float* __restrict__ w2,
                             const float* __restrict__ w3,
                             const float* __restrict__ w4,
                             float* __restrict__ wbuf,
                             float* __restrict__ wbuf1) {
    int idx = blockIdx.x * 256 + threadIdx.x;
    if (idx < 18432) {
        // conv2 bf16: j = reg 0..3; lane; wm m-tile; rest = cc4*9 + t
        int j = idx & 3;
        int lane = (idx >> 2) & 31;
        int wm = (idx >> 7) & 3;
        int rest = idx >> 9;            // 0..35
        int t = rest % 9, cc4 = rest / 9;
        int oc = wm * 16 + (lane >> 2) + 8 * (j & 1);
        int k2 = 2 * (lane & 3) + 8 * (j >> 1);
        int ci = cc4 * 16 + k2;
        float lo = w2[(oc * 64 + ci) * 9 + t];
        float hi = w2[(oc * 64 + ci + 1) * 9 + t];
        wbuf[idx] = __uint_as_float(pack_bf16(lo, hi));
    } else if (idx < 18432 + 2 * 36864) {
        int r = idx - 18432;
        int which = r / 36864;
        r = r % 36864;
        const float* w = (which == 0) ? w3 : w4;
        int j = r & 3;
        int lane = (r >> 2) & 31;
        int wm = (r >> 7) & 3;
        int rest = r >> 9;
        int t = rest % 9, cc = rest / 9;
        int oc = wm * 16 + (lane >> 2) + (j & 1) * 8;
        int ci = cc * 8 + (lane & 3) + ((j >> 1) & 1) * 4;
        wbuf[idx] = __uint_as_float(f2tf32(w[(oc * 64 + ci) * 9 + t]));
    } else if (idx < 18432 + 2 * 36864 + 2048) {
        int r = idx - (18432 + 2 * 36864);
        int j = r & 3;
        int lane = (r >> 2) & 31;
        int wm = (r >> 7) & 3;
        int ks = r >> 9;
        int oc = wm * 16 + (lane >> 2) + (j & 1) * 8;
        int k = ks * 8 + (lane & 3) + ((j >> 1) & 1) * 4;
        float v = 0.f;
        if (k < 27) v = w1[(oc * 3 + k / 9) * 9 + (k % 9)];
        wbuf1[r] = __uint_as_float(f2tf32(v));
    }
}

// ---------------------------------------------------------------------------
// conv1 + maxpool, tf32 shift-GEMM (unchanged). grid (42, 57).
// ---------------------------------------------------------------------------
#define C1P 88
#define C1CIP 360

__global__ void __launch_bounds__(256) conv1_pool_kernel(
    const float* __restrict__ in1, const float* __restrict__ in2,
    const float* __restrict__ wbuf1, float* __restrict__ p1pre,
    float* __restrict__ st1) {
    __shared__ char sraw[45056];
    __shared__ float s_stats[2][64][2];
    u32* s_in = (u32*)sraw;
    float(*sacc)[176] = (float(*)[176])sraw;

    const int bx = blockIdx.x;
    const int img = blockIdx.y;
    const int tid = threadIdx.x;
    const int wid = tid >> 5, lane = tid & 31;
    const int wm = wid & 3, wn = wid >> 2;

    const float* ip = (img < 32) ? (in1 + (size_t)img * 3 * 7056)
                                 : (in2 + (size_t)(img - 32) * 3 * 7056);

    for (int i = tid; i < 3 * 4 * C1P; i += 256) {
        int ci = i / (4 * C1P);
        int rem = i % (4 * C1P);
        int r = rem / C1P, c = rem % C1P;
        int gy = 2 * bx - 1 + r, gx = c - 1;
        float v = 0.f;
        if (gy >= 0 && gy < 84 && gx >= 0 && gx < 84)
            v = ip[ci * 7056 + gy * 84 + gx];
        s_in[ci * C1CIP + r * C1P + c] = f2tf32(v);
    }
    if (tid < 24)
        s_in[(tid / 8) * C1CIP + 4 * C1P + (tid % 8)] = 0u;
    __syncthreads();

    u32 koffA[4], koffB[4];
#pragma unroll
    for (int ks = 0; ks < 4; ks++) {
        int kA = ks * 8 + (lane & 3), kB = kA + 4;
        koffA[ks] = (kA < 27)
            ? (u32)((kA / 9) * C1CIP + ((kA % 9) / 3) * C1P + (kA % 9) % 3)
            : 0u;
        koffB[ks] = (kB < 27)
            ? (u32)((kB / 9) * C1CIP + ((kB % 9) / 3) * C1P + (kB % 9) % 3)
            : 0u;
    }
    const u32 pixrow = (u32)(wn * C1P) + (u32)(lane >> 2);

    float acc[11][4];
#pragma unroll
    for (int n8 = 0; n8 < 11; n8++)
#pragma unroll
        for (int j = 0; j < 4; j++) acc[n8][j] = 0.f;

#pragma unroll
    for (int ks = 0; ks < 4; ks++) {
        float4 af = *(const float4*)&wbuf1[((ks * 4 + wm) * 32 + lane) * 4];
        u32 a0 = __float_as_uint(af.x);
        u32 a1 = __float_as_uint(af.y);
        u32 a2 = __float_as_uint(af.z);
        u32 a3 = __float_as_uint(af.w);
#pragma unroll
        for (int n8 = 0; n8 < 11; n8++) {
            u32 p = pixrow + n8 * 8;
            u32 b0 = s_in[koffA[ks] + p];
            u32 b1 = s_in[koffB[ks] + p];
            mma_tf32(acc[n8], a0, a1, a2, a3, b0, b1);
        }
    }
    __syncthreads();

    const int oc0 = wm * 16 + (lane >> 2);
    float s0 = 0.f, q0 = 0.f, s1 = 0.f, q1 = 0.f;
#pragma unroll
    for (int n8 = 0; n8 < 11; n8++) {
        int col = n8 * 8 + 2 * (lane & 3);
        if (col < 84) {
            float v0 = acc[n8][0], v1 = acc[n8][2];
            sacc[oc0][wn * C1P + col] = v0;
            sacc[oc0 + 8][wn * C1P + col] = v1;
            s0 += v0; q0 = fmaf(v0, v0, q0);
            s1 += v1; q1 = fmaf(v1, v1, q1);
        }
        if (col + 1 < 84) {
            float v0 = acc[n8][1], v1 = acc[n8][3];
            sacc[oc0][wn * C1P + col + 1] = v0;
            sacc[oc0 + 8][wn * C1P + col + 1] = v1;
            s0 += v0; q0 = fmaf(v0, v0, q0);
            s1 += v1; q1 = fmaf(v1, v1, q1);
        }
    }
#pragma unroll
    for (int off = 1; off <= 2; off <<= 1) {
        s0 += __shfl_xor_sync(0xffffffffu, s0, off);
        q0 += __shfl_xor_sync(0xffffffffu, q0, off);
        s1 += __shfl_xor_sync(0xffffffffu, s1, off);
        q1 += __shfl_xor_sync(0xffffffffu, q1, off);
    }
    if ((lane & 3) == 0) {
        s_stats[wn][oc0][0] = s0;
        s_stats[wn][oc0][1] = q0;
        s_stats[wn][oc0 + 8][0] = s1;
        s_stats[wn][oc0 + 8][1] = q1;
    }
    __syncthreads();

    for (int i = tid; i < 64 * 42; i += 256) {
        int oc = i / 42, pc = i % 42;
        float v = fmaxf(fmaxf(sacc[oc][2 * pc], sacc[oc][2 * pc + 1]),
                        fmaxf(sacc[oc][C1P + 2 * pc], sacc[oc][C1P + 2 * pc + 1]));
        p1pre[((size_t)img * 64 + oc) * 1764 + bx * 42 + pc] = v;
    }
    if (tid < 128) {
        int oc = tid >> 1, wh = tid & 1;
        st1[(((size_t)img * 42 + bx) * 64 + oc) * 2 + wh] =
            s_stats[0][oc][wh] + s_stats[1][oc][wh];
    }
}

// ---------------------------------------------------------------------------
// Fused stats (unchanged). grid (64), 256 threads.
// ---------------------------------------------------------------------------
__global__ void stats_fused_kernel(const float* __restrict__ st1, int NB,
                                   int HW,
                                   const float* __restrict__ gamma,
                                   const float* __restrict__ beta,
                                   float* __restrict__ scale,
                                   float* __restrict__ shift) {
    const int c = blockIdx.x;
    const int tid = threadIdx.x;
    float a[6][2];
#pragma unroll
    for (int g = 0; g < 6; g++) { a[g][0] = 0.f; a[g][1] = 0.f; }
    const int total = NIMG * NB;
    for (int i = tid; i < total; i += 256) {
        int img = i / NB, blk = i % NB;
        int g = img_group(img);
        const float* p = &st1[(((size_t)img * NB + blk) * 64 + c) * 2];
        a[g][0] += p[0];
        a[g][1] += p[1];
    }
    __shared__ float sm[256][12];
#pragma unroll
    for (int g = 0; g < 6; g++) {
        sm[tid][2 * g] = a[g][0];
        sm[tid][2 * g + 1] = a[g][1];
    }
    __syncthreads();
    for (int off = 128; off > 0; off >>= 1) {
        if (tid < off)
#pragma unroll
            for (int j = 0; j < 12; j++) sm[tid][j] += sm[tid + off][j];
        __syncthreads();
    }
    if (tid < 6) {
        int g = tid;
        int nimg = (g == 0) ? 32 : 5;
        float cnt = (float)(nimg * HW);
        float m = sm[0][2 * g] / cnt;
        float var = sm[0][2 * g + 1] / cnt - m * m;
        float inv = rsqrtf(var + 1e-5f);
        float sc = gamma[c] * inv;
        scale[g * 64 + c] = sc;
        shift[g * 64 + c] = beta[c] - m * sc;
    }
}

// ---------------------------------------------------------------------------
// conv2 (H=42) in bf16 m16n8k16. Warps: 4M x 2N (measured best). Smem holds
// bf16 ci-PAIRS as u32 words: sB[cp][r*PITCH+c] = (x[2cp], x[2cp+1]).
// B frag = 2 LDS.32 ((lane&3)*CIP, +4*CIP). 4 chunks of 16 ci; per chunk:
// 9 taps x 8 n8 x 1 mma. CIP=232 (== 8 mod 32 -> conflict-free).
// BN1+LReLU applied in the loader. grid (14, 57).
// ---------------------------------------------------------------------------
#define B2_H 42
#define B2_NR 3
#define B2_R 5
#define B2_PITCH 44
#define B2_CIP 232

__global__ void __launch_bounds__(256) conv2_bf16_kernel(
    const float* __restrict__ in, const float* __restrict__ wbuf,
    float* __restrict__ out,
    const float* __restrict__ scale, const float* __restrict__ shift,
    float* __restrict__ st1) {
    constexpr int W = B2_H, HW = B2_H * B2_H;
    constexpr int TOT = 8 * B2_R * (W + 2);  // words per chunk (8 ci-pairs)

    __shared__ u32 sB[8 * B2_CIP];
    __shared__ float s_stats[2][64][2];

    const int rb = blockIdx.x * B2_NR;
    const int img = blockIdx.y;
    const int tid = threadIdx.x;
    const int wid = tid >> 5, lane = tid & 31;
    const int wm = wid & 3, wn = wid >> 2;
    const int g = img_group(img);
    const int vrows = min(rb + B2_NR, B2_H) - rb;
    const int valid = vrows * W;

    u32 baddr[8];
    {
        u32 kq = (u32)(lane & 3) * B2_CIP;
#pragma unroll
        for (int n8 = 0; n8 < 8; n8++) {
            int n = wn * 64 + n8 * 8 + (lane >> 2);
            u32 poff = 0;
            if (n < valid) poff = (u32)((n / W) * B2_PITCH + (n % W));
            baddr[n8] = kq + poff;
        }
    }

    float acc[8][4];
#pragma unroll
    for (int n8 = 0; n8 < 8; n8++)
#pragma unroll
        for (int j = 0; j < 4; j++) acc[n8][j] = 0.f;

    const float* ip = in + (size_t)img * 64 * HW;

    for (int cc4 = 0; cc4 < 4; cc4++) {
        __syncthreads();
        for (int i = tid; i < TOT; i += 256) {
            int cp = i / (B2_R * (W + 2));
            int rem = i % (B2_R * (W + 2));
            int r = rem / (W + 2), c = rem % (W + 2);
            int gy = rb - 1 + r, gx = c - 1;
            u32 word = 0u;
            if (gy >= 0 && gy < B2_H && gx >= 0 && gx < W) {
                int ci0 = cc4 * 16 + 2 * cp;
                float v0 = ip[(size_t)ci0 * HW + gy * W + gx];
                float v1 = ip[(size_t)(ci0 + 1) * HW + gy * W + gx];
                v0 = lrelu(fmaf(v0, scale[g * 64 + ci0], shift[g * 64 + ci0]));
                v1 = lrelu(fmaf(v1, scale[g * 64 + ci0 + 1],
                                shift[g * 64 + ci0 + 1]));
                word = pack_bf16(v0, v1);
            }
            sB[cp * B2_CIP + r * B2_PITCH + c] = word;
        }
        __syncthreads();

#pragma unroll
        for (int t = 0; t < 9; t++) {
            const int dy = t / 3, dx = t % 3;
            const int soff = dy * B2_PITCH + dx;
            float4 af = *(const float4*)&wbuf[(((cc4 * 9 + t) * 4 + wm) * 32 +
                                              lane) * 4];
            u32 a[4] = {__float_as_uint(af.x), __float_as_uint(af.y),
                        __float_as_uint(af.z), __float_as_uint(af.w)};
#pragma unroll
            for (int n8 = 0; n8 < 8; n8++) {
                u32 b0 = sB[baddr[n8] + soff];
                u32 b1 = sB[baddr[n8] + soff + 4 * B2_CIP];
                mma16816(acc[n8], a, b0, b1);
            }
        }
    }

    const int r0 = wm * 16 + (lane >> 2);
    float* op0 = out + ((size_t)img * 64 + r0) * HW;
    float* op1 = out + ((size_t)img * 64 + r0 + 8) * HW;
    float s0 = 0.f, q0 = 0.f, s1 = 0.f, q1 = 0.f;
#pragma unroll
    for (int n8 = 0; n8 < 8; n8++) {
        int nb = wn * 64 + n8 * 8 + 2 * (lane & 3);
        if (nb < valid) {
            int p = (rb + nb / W) * W + nb % W;
            float v0 = acc[n8][0], v1 = acc[n8][2];
            op0[p] = v0;
            op1[p] = v1;
            s0 += v0; q0 = fmaf(v0, v0, q0);
            s1 += v1; q1 = fmaf(v1, v1, q1);
        }
        if (nb + 1 < valid) {
            int p = (rb + (nb + 1) / W) * W + (nb + 1) % W;
            float v0 = acc[n8][1], v1 = acc[n8][3];
            op0[p] = v0;
            op1[p] = v1;
            s0 += v0; q0 = fmaf(v0, v0, q0);
            s1 += v1; q1 = fmaf(v1, v1, q1);
        }
    }
#pragma unroll
    for (int off = 1; off <= 2; off <<= 1) {
        s0 += __shfl_xor_sync(0xffffffffu, s0, off);
        q0 += __shfl_xor_sync(0xffffffffu, q0, off);
        s1 += __shfl_xor_sync(0xffffffffu, s1, off);
        q1 += __shfl_xor_sync(0xffffffffu, q1, off);
    }
    if ((lane & 3) == 0) {
        s_stats[wn][r0][0] = s0;
        s_stats[wn][r0][1] = q0;
        s_stats[wn][r0 + 8][0] = s1;
        s_stats[wn][r0 + 8][1] = q1;
    }
    __syncthreads();
    if (tid < 128) {
        int oc = tid >> 1, wh = tid & 1;
        st1[(((size_t)img * gridDim.x + blockIdx.x) * 64 + oc) * 2 + wh] =
            s_stats[0][oc][wh] + s_stats[1][oc][wh];
    }
}

// ---------------------------------------------------------------------------
// conv3/conv4 (H=21): R11 pipelined double-buffer tf32 kernel (verbatim).
// MODE: 1 BN+LReLU; 2 BN+LReLU+2x2 maxpool on 2H-sized input.
// ---------------------------------------------------------------------------
template <int H, int NROWS, int PITCH, int MODE>
__global__ void __launch_bounds__(256) conv_mma_pipe_kernel(
    const float* __restrict__ in, const float* __restrict__ wbuf,
    float* __restrict__ out,
    const float* __restrict__ scale, const float* __restrict__ shift,
    float* __restrict__ st1) {
    constexpr int R = NROWS + 2;
    constexpr int W = H;
    constexpr int HW = H * H;
    constexpr int CIP = R * PITCH;
    constexpr int TOT = 8 * R * (W + 2);
    constexpr int NLD = (TOT + 255) / 256;
    constexpr int IN_HW = (MODE == 2) ? 4 * HW : HW;
    constexpr int IN_W = (MODE == 2) ? 2 * W : W;
    constexpr int VPE = (MODE == 2) ? 4 : 1;

    __shared__ u32 s_in[2][8 * CIP];
    __shared__ float s_stats[2][64][2];

    const int rb = blockIdx.x * NROWS;
    const int img = blockIdx.y;
    const int tid = threadIdx.x;
    const int wid = tid >> 5, lane = tid & 31;
    const int wm = wid & 3, wn = wid >> 2;
    const int g = img_group(img);
    const int vrows = min(rb + NROWS, H) - rb;
    const int valid = vrows * W;

    int l_ci[NLD];
    u32 l_soff[NLD];
    int l_goff[NLD];
#pragma unroll
    for (int j = 0; j < NLD; j++) {
        int i = tid + j * 256;
        if (i < TOT) {
            int ci = i / (R * (W + 2));
            int rem = i % (R * (W + 2));
            int r = rem / (W + 2), c = rem % (W + 2);
            int gy = rb - 1 + r, gx = c - 1;
            l_ci[j] = ci;
            l_soff[j] = (u32)(ci * CIP + r * PITCH + c);
            bool ok = gy >= 0 && gy < H && gx >= 0 && gx < W;
            l_goff[j] = ok ? ((MODE == 2) ? ((2 * gy) * IN_W + 2 * gx)
                                          : (gy * W + gx))
                           : -1;
        } else {
            l_ci[j] = -1;
            l_soff[j] = 0;
            l_goff[j] = -1;
        }
    }

    const float* ip = in + (size_t)img * 64 * IN_HW;
    float vreg[NLD * VPE];

    auto load_stage = [&](int cc) {
#pragma unroll
        for (int j = 0; j < NLD; j++) {
            if (l_ci[j] < 0) continue;
            if (l_goff[j] >= 0) {
                const float* q = ip + (size_t)(cc * 8 + l_ci[j]) * IN_HW +
                                 l_goff[j];
                if (MODE == 2) {
                    vreg[4 * j + 0] = __ldg(q);
                    vreg[4 * j + 1] = __ldg(q + 1);
                    vreg[4 * j + 2] = __ldg(q + IN_W);
                    vreg[4 * j + 3] = __ldg(q + IN_W + 1);
                } else {
                    vreg[j] = __ldg(q);
                }
            } else {
                if (MODE == 2) {
                    vreg[4 * j] = vreg[4 * j + 1] = 0.f;
                    vreg[4 * j + 2] = vreg[4 * j + 3] = 0.f;
                } else {
                    vreg[j] = 0.f;
                }
            }
        }
    };
    auto store_stage = [&](int buf, int cc) {
#pragma unroll
        for (int j = 0; j < NLD; j++) {
            if (l_ci[j] < 0) continue;
            float v = 0.f;
            if (l_goff[j] >= 0) {
                int ch = cc * 8 + l_ci[j];
                if (MODE == 1) {
                    v = lrelu(fmaf(vreg[j], scale[g * 64 + ch],
                                   shift[g * 64 + ch]));
                } else {
                    float sc = scale[g * 64 + ch], sf = shift[g * 64 + ch];
                    float v0 = lrelu(fmaf(vreg[4 * j], sc, sf));
                    float v1 = lrelu(fmaf(vreg[4 * j + 1], sc, sf));
                    float v2 = lrelu(fmaf(vreg[4 * j + 2], sc, sf));
                    float v3 = lrelu(fmaf(vreg[4 * j + 3], sc, sf));
                    v = fmaxf(fmaxf(v0, v1), fmaxf(v2, v3));
                }
            }
            s_in[buf][l_soff[j]] = f2tf32(v);
        }
    };

    u32 baddr[8];
    {
        u32 cipart = (u32)(lane & 3) * CIP;
#pragma unroll
        for (int n8 = 0; n8 < 8; n8++) {
            int n = wn * 64 + n8 * 8 + (lane >> 2);
            u32 poff = 0;
            if (n < valid) poff = (u32)((n / W) * PITCH + (n % W));
            baddr[n8] = cipart + poff;
        }
    }

    float acc[8][4];
#pragma unroll
    for (int n8 = 0; n8 < 8; n8++)
#pragma unroll
        for (int j = 0; j < 4; j++) acc[n8][j] = 0.f;

    load_stage(0);
    store_stage(0, 0);
    __syncthreads();

    for (int cc = 0; cc < 8; cc++) {
        if (cc < 7) load_stage(cc + 1);

        const u32* sb = s_in[cc & 1];
#pragma unroll
        for (int t = 0; t < 9; t++) {
            const int dy = t / 3, dx = t % 3;
            const int soff = dy * PITCH + dx;
            float4 af = *(const float4*)&wbuf[(((cc * 9 + t) * 4 + wm) * 32 +
                                              lane) * 4];
            u32 a0 = __float_as_uint(af.x);
            u32 a1 = __float_as_uint(af.y);
            u32 a2 = __float_as_uint(af.z);
            u32 a3 = __float_as_uint(af.w);
#pragma unroll
            for (int n8 = 0; n8 < 8; n8++) {
                u32 b0 = sb[baddr[n8] + soff];
                u32 b1 = sb[baddr[n8] + soff + 4 * CIP];
                mma_tf32(acc[n8], a0, a1, a2, a3, b0, b1);
            }
        }

        if (cc < 7) store_stage((cc + 1) & 1, cc + 1);
        __syncthreads();
    }

    const int r0 = wm * 16 + (lane >> 2);
    float* op0 = out + ((size_t)img * 64 + r0) * HW;
    float* op1 = out + ((size_t)img * 64 + r0 + 8) * HW;
    float s0 = 0.f, q0 = 0.f, s1 = 0.f, q1 = 0.f;
#pragma unroll
    for (int n8 = 0; n8 < 8; n8++) {
        int nb = wn * 64 + n8 * 8 + 2 * (lane & 3);
        if (nb < valid) {
            int p = (rb + nb / W) * W + nb % W;
            float v0 = acc[n8][0], v1 = acc[n8][2];
            op0[p] = v0;
            op1[p] = v1;
            s0 += v0; q0 = fmaf(v0, v0, q0);
            s1 += v1; q1 = fmaf(v1, v1, q1);
        }
        if (nb + 1 < valid) {
            int p = (rb + (nb + 1) / W) * W + (nb + 1) % W;
            float v0 = acc[n8][1], v1 = acc[n8][3];
            op0[p] = v0;
            op1[p] = v1;
            s0 += v0; q0 = fmaf(v0, v0, q0);
            s1 += v1; q1 = fmaf(v1, v1, q1);
        }
    }
#pragma unroll
    for (int off = 1; off <= 2; off <<= 1) {
        s0 += __shfl_xor_sync(0xffffffffu, s0, off);
        q0 += __shfl_xor_sync(0xffffffffu, q0, off);
        s1 += __shfl_xor_sync(0xffffffffu, s1, off);
        q1 += __shfl_xor_sync(0xffffffffu, q1, off);
    }
    if ((lane & 3) == 0) {
        s_stats[wn][r0][0] = s0;
        s_stats[wn][r0][1] = q0;
        s_stats[wn][r0 + 8][0] = s1;
        s_stats[wn][r0 + 8][1] = q1;
    }
    __syncthreads();
    if (tid < 128) {
        int oc = tid >> 1, wh = tid & 1;
        st1[(((size_t)img * gridDim.x + blockIdx.x) * 64 + oc) * 2 + wh] =
            s_stats[0][oc][wh] + s_stats[1][oc][wh];
    }
}

// ---------------------------------------------------------------------------
// qsnorm (unchanged).
// ---------------------------------------------------------------------------
__global__ void qsnorm_kernel(const float* __restrict__ f,
                              const float* __restrict__ scale,
                              const float* __restrict__ shift,
                              __nv_bfloat16* __restrict__ Qh,
                              __nv_bfloat16* __restrict__ ShK) {
    int idx = blockIdx.x * blockDim.x + threadIdx.x;
    if (idx < 32 * 441) {
        int b = idx / 441, pix = idx % 441;
        const float* p = f + (size_t)b * 64 * 441 + pix;
        float vals[64];
        float s = 0.f;
#pragma unroll 8
        for (int c = 0; c < 64; c++) {
            float v = lrelu(fmaf(p[c * 441], scale[c], shift[c]));
            vals[c] = v;
            s = fmaf(v, v, s);
        }
        float inv = rsqrtf(s);
        __nv_bfloat162* op = (__nv_bfloat162*)&Qh[(size_t)idx * 64];
#pragma unroll 8
        for (int c = 0; c < 32; c++)
            op[c] = __floats2bfloat162_rn(vals[2 * c] * inv,
                                          vals[2 * c + 1] * inv);
    } else if (idx < 32 * 441 + 5 * 2240) {
        int r = idx - 32 * 441;
        int n = r / 2240, m = r % 2240;
        if (m >= 2205) {
#pragma unroll 8
            for (int c = 0; c < 64; c++)
                ShK[((size_t)n * 64 + c) * 2240 + m] = __float2bfloat16(0.f);
            return;
        }
        int sh = m / 441, pix = m % 441;
        int img = 32 + n * 5 + sh;
        int g = 1 + n;
        const float* p = f + (size_t)img * 64 * 441 + pix;
        float vals[64];
        float s = 0.f;
#pragma unroll 8
        for (int c = 0; c < 64; c++) {
            float v = lrelu(fmaf(p[c * 441], scale[g * 64 + c],
                                 shift[g * 64 + c]));
            vals[c] = v;
            s = fmaf(v, v, s);
        }
        float inv = rsqrtf(s);
#pragma unroll 8
        for (int c = 0; c < 64; c++)
            ShK[((size_t)n * 64 + c) * 2240 + m] =
                __float2bfloat16(vals[c] * inv);
    }
}

// ---------------------------------------------------------------------------
// sims via mma.sync m16n8k16 bf16, 128 rows/block (unchanged).
// ---------------------------------------------------------------------------
#define SPAD 72

__device__ __forceinline__ void ins3(float v, float& t0, float& t1, float& t2) {
    float lo = fminf(v, t0);
    t0 = fmaxf(v, t0);
    float mid = fminf(lo, t1);
    t1 = fmaxf(lo, t1);
    t2 = fmaxf(t2, mid);
}

__global__ void __launch_bounds__(256) sims_mma_kernel(
    const __nv_bfloat16* __restrict__ Qh,
    const __nv_bfloat16* __restrict__ ShK,
    float* __restrict__ part) {
    __shared__ __nv_bfloat16 sQ[128][SPAD];
    __shared__ __nv_bfloat16 sS[64][SPAD];
    __shared__ float red[8];

    const int rchunk = blockIdx.x;
    const int n = blockIdx.y;
    const int b = blockIdx.z;
    const int rbase = rchunk * 128;
    const int tid = threadIdx.x;
    const int wid = tid >> 5, lane = tid & 31;

    for (int i = tid; i < 128 * 8; i += 256) {
        int r = i >> 3, c8 = i & 7;
        uint4 v = make_uint4(0u, 0u, 0u, 0u);
        if (rbase + r < 441)
            v = *(const uint4*)&Qh[((size_t)(b * 441 + rbase + r)) * 64 + c8 * 8];
        *(uint4*)&sQ[r][c8 * 8] = v;
    }
    __syncthreads();

    const u32 sQb = smem_u32(&sQ[0][0]);
    const u32 sSb = smem_u32(&sS[0][0]);
    const int m0 = wid * 16;

    u32 afr[4][4];
    {
        int rr = m0 + (lane & 15);
        int cc = (lane >> 4) * 8;
#pragma unroll
        for (int ks = 0; ks < 4; ks++)
            ldsm_x4(afr[ks][0], afr[ks][1], afr[ks][2], afr[ks][3],
                    sQb + (u32)((rr * SPAD + ks * 16 + cc) * 2));
    }

    float ta0 = -1e30f, ta1 = -1e30f, ta2 = -1e30f;
    float tb0 = -1e30f, tb1 = -1e30f, tb2 = -1e30f;

    const __nv_bfloat16* Sbase = ShK + (size_t)n * 64 * 2240;

    for (int tile = 0; tile < 35; tile++) {
        const int c0 = tile * 64;
        __syncthreads();
        for (int i = tid; i < 64 * 8; i += 256) {
            int k = i >> 3, p8 = i & 7;
            uint4 v = *(const uint4*)&Sbase[(size_t)k * 2240 + c0 + p8 * 8];
            *(uint4*)&sS[k][p8 * 8] = v;
        }
        __syncthreads();

        float d[8][4];
#pragma unroll
        for (int j = 0; j < 8; j++)
#pragma unroll
            for (int c = 0; c < 4; c++) d[j][c] = 0.f;

        const int kr_l = (lane & 7) + ((lane >> 3) & 1) * 8;
        const int nc_l = (lane >> 4) * 8;
#pragma unroll
        for (int ks = 0; ks < 4; ks++) {
            int kr = ks * 16 + kr_l;
#pragma unroll
            for (int n16 = 0; n16 < 4; n16++) {
                u32 b0, b1, b2, b3;
                ldsm_x4t(b0, b1, b2, b3,
                         sSb + (u32)((kr * SPAD + n16 * 16 + nc_l) * 2));
                mma16816(d[2 * n16], afr[ks], b0, b1);
                mma16816(d[2 * n16 + 1], afr[ks], b2, b3);
            }
        }

        if (tile != 34) {
#pragma unroll
            for (int n8 = 0; n8 < 8; n8++) {
                ins3(d[n8][0], ta0, ta1, ta2);
                ins3(d[n8][1], ta0, ta1, ta2);
                ins3(d[n8][2], tb0, tb1, tb2);
                ins3(d[n8][3], tb0, tb1, tb2);
            }
        } else {
            int cb = c0 + 2 * (lane & 3);
#pragma unroll
            for (int n8 = 0; n8 < 8; n8++) {
                int c = cb + n8 * 8;
                if (c < 2205) { ins3(d[n8][0], ta0, ta1, ta2);
                                ins3(d[n8][2], tb0, tb1, tb2); }
                if (c + 1 < 2205) { ins3(d[n8][1], ta0, ta1, ta2);
                                    ins3(d[n8][3], tb0, tb1, tb2); }
            }
        }
    }

#pragma unroll
    for (int off = 1; off <= 2; off <<= 1) {
        float x0 = __shfl_xor_sync(0xffffffffu, ta0, off);
        float x1 = __shfl_xor_sync(0xffffffffu, ta1, off);
        float x2 = __shfl_xor_sync(0xffffffffu, ta2, off);
        ins3(x0, ta0, ta1, ta2);
        ins3(x1, ta0, ta1, ta2);
        ins3(x2, ta0, ta1, ta2);
        float y0 = __shfl_xor_sync(0xffffffffu, tb0, off);
        float y1 = __shfl_xor_sync(0xffffffffu, tb1, off);
        float y2 = __shfl_xor_sync(0xffffffffu, tb2, off);
        ins3(y0, tb0, tb1, tb2);
        ins3(y1, tb0, tb1, tb2);
        ins3(y2, tb0, tb1, tb2);
    }

    float s = 0.f;
    if ((lane & 3) == 0) {
        int r1 = rbase + m0 + (lane >> 2);
        if (r1 < 441) s += ta0 + ta1 + ta2;
        if (r1 + 8 < 441) s += tb0 + tb1 + tb2;
    }
#pragma unroll
    for (int off = 16; off > 0; off >>= 1)
        s += __shfl_down_sync(0xffffffffu, s, off);
    if (lane == 0) red[wid] = s;
    __syncthreads();
    if (tid == 0) {
        float r = 0.f;
#pragma unroll
        for (int i = 0; i < 8; i++) r += red[i];
        part[(b * 5 + n) * 4 + rchunk] = r;
    }
}

__global__ void finalize_kernel(const float* __restrict__ part,
                                float* __restrict__ out) {
    int i = threadIdx.x;
    if (i < 160) {
        float s = 0.f;
#pragma unroll
        for (int k = 0; k < 4; k++) s += part[4 * i + k];
        out[i] = s;
    }
}

// ---------------------------------------------------------------------------
extern "C" void kernel_launch(void* const* d_in, const int* in_sizes, int n_in,
                              void* d_out, int out_size) {
    const float* input1 = (const float*)d_in[0];
    const float* input2 = (const float*)d_in[1];
    const float* w1 = (const float*)d_in[2];
    const float* g1 = (const float*)d_in[3];
    const float* b1 = (const float*)d_in[4];
    const float* w2 = (const float*)d_in[5];
    const float* g2 = (const float*)d_in[6];
    const float* b2 = (const float*)d_in[7];
    const float* w3 = (const float*)d_in[8];
    const float* g3 = (const float*)d_in[9];
    const float* b3 = (const float*)d_in[10];
    const float* w4 = (const float*)d_in[11];
    const float* g4 = (const float*)d_in[12];
    const float* b4 = (const float*)d_in[13];
    float* out = (float*)d_out;

    void* poolPtr = nullptr;
    cudaGetSymbolAddress(&poolPtr, d_pool);
    float* P = (float*)poolPtr;
    float* p1pre = P + OFF_P1;
    float* c2 = P + OFF_C2;
    float* c3 = P + OFF_C3;
    float* c4 = P + OFF_C4;
    __nv_bfloat16* Qh = (__nv_bfloat16*)(P + OFF_QH);
    __nv_bfloat16* ShK = (__nv_bfloat16*)(P + OFF_SK);
    float* sc = P + OFF_SC;
    float* sh = P + OFF_SHF;
    float* part = P + OFF_PART;
    float* wb2b = P + OFF_WB;                  // conv2 bf16 frags (18432)
    float* wb3 = P + OFF_WB + 18432;           // conv3 tf32 (36864)
    float* wb4 = P + OFF_WB + 18432 + 36864;   // conv4 tf32 (36864)
    float* wb1 = P + OFF_WB1;
    float* st1 = P + OFF_ST1;

    const int WPREP_TOT = 18432 + 2 * 36864 + 2048;
    wprep_kernel<<<(WPREP_TOT + 255) / 256, 256>>>(w1, w2, w3, w4, wb2b, wb1);
    conv1_pool_kernel<<<dim3(42, NIMG), 256>>>(input1, input2, wb1, p1pre, st1);
    stats_fused_kernel<<<64, 256>>>(st1, 42, 7056, g1, b1, sc, sh);
    // conv2: bf16 m16n8k16 (BN1+LReLU fused on input)
    conv2_bf16_kernel<<<dim3(14, NIMG), 256>>>(p1pre, wb2b, c2, sc, sh, st1);
    stats_fused_kernel<<<64, 256>>>(st1, 14, 1764, g2, b2, sc, sh);
    // conv3: pipelined tf32, BN2+LReLU+pool fused on input
    conv_mma_pipe_kernel<21, 6, 25, 2><<<dim3(4, NIMG), 256>>>(
        c2, wb3, c3, sc, sh, st1);
    stats_fused_kernel<<<64, 256>>>(st1, 4, 441, g3, b3, sc, sh);
    // conv4: pipelined tf32, BN3+LReLU fused on input
    conv_mma_pipe_kernel<21, 6, 25, 1><<<dim3(4, NIMG), 256>>>(
        c3, wb4, c4, sc, sh, st1);
    stats_fused_kernel<<<64, 256>>>(st1, 4, 441, g4, b4, sc, sh);
    qsnorm_kernel<<<(32 * 441 + 5 * 2240 + 127) / 128, 128>>>(c4, sc, sh,
                                                              Qh, ShK);
    sims_mma_kernel<<<dim3(4, 5, 32), 256>>>(Qh, ShK, part);
    finalize_kernel<<<1, 160>>>(part, out);
}

// round 15
// speedup vs baseline: 1.1911x; 1.0266x over previous
#include <cuda_runtime.h>
#include <cuda_bf16.h>
#include <math.h>

// ---------------------------------------------------------------------------
// FourLayer_64F. Round 15: conv3/conv4 join conv2 on bf16 mma.sync m16n8k16
// (ci-paired bf16 smem words; 4 chunks of 16 ci; MODE keeps BN/pool fusion).
// conv1 stays tf32. Rest = R14 structure (12 launches, fused stats, bf16 sims).
// ---------------------------------------------------------------------------

#define NIMG 57
#define NEG_SLOPE 0.2f

typedef unsigned int u32;

__device__ __forceinline__ u32 f2tf32(float v) {
    u32 r;
    asm("cvt.rna.tf32.f32 %0, %1;" : "=r"(r) : "f"(v));
    return r;
}
__device__ __forceinline__ u32 pack_bf16(float lo, float hi) {
    __nv_bfloat162 p = __floats2bfloat162_rn(lo, hi);
    return *(u32*)&p;
}

// ---------------- scratch pool (floats) ------------------------------------
#define OFF_P1   ((size_t)0)                        // 57*64*1764 pooled pre-BN1
#define OFF_C2   (OFF_P1 + (size_t)57*64*1764)      // 57*64*1764
#define OFF_C3   (OFF_C2 + (size_t)57*64*1764)      // 57*64*441
#define OFF_C4   (OFF_C3 + (size_t)57*64*441)
#define OFF_QH   (OFF_C4 + (size_t)57*64*441)       // bf16 32*441*64 -> 451584 f
#define OFF_SK   (OFF_QH + (size_t)451584)          // bf16 5*64*2240 -> 358400 f
#define OFF_SC   (OFF_SK + (size_t)358400)          // 6*64 scale
#define OFF_SHF  (OFF_SC + 384)                     // 6*64 shift
#define OFF_PART (OFF_SHF + 384)                    // 32*5*4
#define OFF_WB   (OFF_PART + 640)                   // 3*18432 bf16 conv frags
#define OFF_WB1  (OFF_WB + (size_t)3*18432)         // 2048 conv1 tf32
#define OFF_ST1  (OFF_WB1 + 2048)                   // 57*42*64*2 block partials
#define POOL_TOTAL (OFF_ST1 + (size_t)57*42*64*2)

__device__ float d_pool[POOL_TOTAL];

__device__ __forceinline__ float lrelu(float v) {
    return v >= 0.f ? v : NEG_SLOPE * v;
}
__device__ __forceinline__ int img_group(int img) {
    return (img < 32) ? 0 : 1 + (img - 32) / 5;
}

__device__ __forceinline__ u32 smem_u32(const void* p) {
    u32 a;
    asm("{ .reg .u64 t; cvta.to.shared.u64 t, %1; cvt.u32.u64 %0, t; }"
        : "=r"(a) : "l"(p));
    return a;
}
__device__ __forceinline__ void ldsm_x4(u32& r0, u32& r1, u32& r2, u32& r3,
                                        u32 addr) {
    asm volatile("ldmatrix.sync.aligned.m8n8.x4.shared.b16 {%0,%1,%2,%3}, [%4];"
                 : "=r"(r0), "=r"(r1), "=r"(r2), "=r"(r3) : "r"(addr));
}
__device__ __forceinline__ void ldsm_x4t(u32& r0, u32& r1, u32& r2, u32& r3,
                                         u32 addr) {
    asm volatile(
        "ldmatrix.sync.aligned.m8n8.x4.trans.shared.b16 {%0,%1,%2,%3}, [%4];"
        : "=r"(r0), "=r"(r1), "=r"(r2), "=r"(r3) : "r"(addr));
}
__device__ __forceinline__ void mma16816(float* d, const u32* a, u32 b0, u32 b1) {
    asm volatile(
        "mma.sync.aligned.m16n8k16.row.col.f32.bf16.bf16.f32 "
        "{%0,%1,%2,%3}, {%4,%5,%6,%7}, {%8,%9}, {%0,%1,%2,%3};"
        : "+f"(d[0]), "+f"(d[1]), "+f"(d[2]), "+f"(d[3])
        : "r"(a[0]), "r"(a[1]), "r"(a[2]), "r"(a[3]), "r"(b0), "r"(b1));
}
__device__ __forceinline__ void mma_tf32(float* d, u32 a0, u32 a1, u32 a2,
                                         u32 a3, u32 b0, u32 b1) {
    asm volatile(
        "mma.sync.aligned.m16n8k8.row.col.f32.tf32.tf32.f32 "
        "{%0,%1,%2,%3}, {%4,%5,%6,%7}, {%8,%9}, {%0,%1,%2,%3};"
        : "+f"(d[0]), "+f"(d[1]), "+f"(d[2]), "+f"(d[3])
        : "r"(a0), "r"(a1), "r"(a2), "r"(a3), "r"(b0), "r"(b1));
}

// ---------------------------------------------------------------------------
// Weight prep, one launch:
//   [0, 3*18432):  conv2/3/4 bf16 A-fragments (m16n8k16 layout)
//   then 2048:     conv1 tf32 (K=27 padded to 32)
// ---------------------------------------------------------------------------
__global__ void wprep_kernel(const float* __restrict__ w1,
                             const float* __restrict__ w2,
                             const float* __restrict__ w3,
                             const float* __restrict__ w4,
                             float* __restrict__ wbuf,
                             float* __restrict__ wbuf1) {
    int idx = blockIdx.x * 256 + threadIdx.x;
    if (idx < 3 * 18432) {
        int which = idx / 18432;
        int r = idx % 18432;
        const float* w = (which == 0) ? w2 : (which == 1) ? w3 : w4;
        int j = r & 3;
        int lane = (r >> 2) & 31;
        int wm = (r >> 7) & 3;
        int rest = r >> 9;              // cc4*9 + t, 0..35
        int t = rest % 9, cc4 = rest / 9;
        int oc = wm * 16 + (lane >> 2) + 8 * (j & 1);
        int k2 = 2 * (lane & 3) + 8 * (j >> 1);
        int ci = cc4 * 16 + k2;
        float lo = w[(oc * 64 + ci) * 9 + t];
        float hi = w[(oc * 64 + ci + 1) * 9 + t];
        wbuf[idx] = __uint_as_float(pack_bf16(lo, hi));
    } else if (idx < 3 * 18432 + 2048) {
        int r = idx - 3 * 18432;
        int j = r & 3;
        int lane = (r >> 2) & 31;
        int wm = (r >> 7) & 3;
        int ks = r >> 9;
        int oc = wm * 16 + (lane >> 2) + (j & 1) * 8;
        int k = ks * 8 + (lane & 3) + ((j >> 1) & 1) * 4;
        float v = 0.f;
        if (k < 27) v = w1[(oc * 3 + k / 9) * 9 + (k % 9)];
        wbuf1[r] = __uint_as_float(f2tf32(v));
    }
}

// ---------------------------------------------------------------------------
// conv1 + maxpool, tf32 shift-GEMM (unchanged). grid (42, 57).
// ---------------------------------------------------------------------------
#define C1P 88
#define C1CIP 360

__global__ void __launch_bounds__(256) conv1_pool_kernel(
    const float* __restrict__ in1, const float* __restrict__ in2,
    const float* __restrict__ wbuf1, float* __restrict__ p1pre,
    float* __restrict__ st1) {
    __shared__ char sraw[45056];
    __shared__ float s_stats[2][64][2];
    u32* s_in = (u32*)sraw;
    float(*sacc)[176] = (float(*)[176])sraw;

    const int bx = blockIdx.x;
    const int img = blockIdx.y;
    const int tid = threadIdx.x;
    const int wid = tid >> 5, lane = tid & 31;
    const int wm = wid & 3, wn = wid >> 2;

    const float* ip = (img < 32) ? (in1 + (size_t)img * 3 * 7056)
                                 : (in2 + (size_t)(img - 32) * 3 * 7056);

    for (int i = tid; i < 3 * 4 * C1P; i += 256) {
        int ci = i / (4 * C1P);
        int rem = i % (4 * C1P);
        int r = rem / C1P, c = rem % C1P;
        int gy = 2 * bx - 1 + r, gx = c - 1;
        float v = 0.f;
        if (gy >= 0 && gy < 84 && gx >= 0 && gx < 84)
            v = ip[ci * 7056 + gy * 84 + gx];
        s_in[ci * C1CIP + r * C1P + c] = f2tf32(v);
    }
    if (tid < 24)
        s_in[(tid / 8) * C1CIP + 4 * C1P + (tid % 8)] = 0u;
    __syncthreads();

    u32 koffA[4], koffB[4];
#pragma unroll
    for (int ks = 0; ks < 4; ks++) {
        int kA = ks * 8 + (lane & 3), kB = kA + 4;
        koffA[ks] = (kA < 27)
            ? (u32)((kA / 9) * C1CIP + ((kA % 9) / 3) * C1P + (kA % 9) % 3)
            : 0u;
        koffB[ks] = (kB < 27)
            ? (u32)((kB / 9) * C1CIP + ((kB % 9) / 3) * C1P + (kB % 9) % 3)
            : 0u;
    }
    const u32 pixrow = (u32)(wn * C1P) + (u32)(lane >> 2);

    float acc[11][4];
#pragma unroll
    for (int n8 = 0; n8 < 11; n8++)
#pragma unroll
        for (int j = 0; j < 4; j++) acc[n8][j] = 0.f;

#pragma unroll
    for (int ks = 0; ks < 4; ks++) {
        float4 af = *(const float4*)&wbuf1[((ks * 4 + wm) * 32 + lane) * 4];
        u32 a0 = __float_as_uint(af.x);
        u32 a1 = __float_as_uint(af.y);
        u32 a2 = __float_as_uint(af.z);
        u32 a3 = __float_as_uint(af.w);
#pragma unroll
        for (int n8 = 0; n8 < 11; n8++) {
            u32 p = pixrow + n8 * 8;
            u32 b0 = s_in[koffA[ks] + p];
            u32 b1 = s_in[koffB[ks] + p];
            mma_tf32(acc[n8], a0, a1, a2, a3, b0, b1);
        }
    }
    __syncthreads();

    const int oc0 = wm * 16 + (lane >> 2);
    float s0 = 0.f, q0 = 0.f, s1 = 0.f, q1 = 0.f;
#pragma unroll
    for (int n8 = 0; n8 < 11; n8++) {
        int col = n8 * 8 + 2 * (lane & 3);
        if (col < 84) {
            float v0 = acc[n8][0], v1 = acc[n8][2];
            sacc[oc0][wn * C1P + col] = v0;
            sacc[oc0 + 8][wn * C1P + col] = v1;
            s0 += v0; q0 = fmaf(v0, v0, q0);
            s1 += v1; q1 = fmaf(v1, v1, q1);
        }
        if (col + 1 < 84) {
            float v0 = acc[n8][1], v1 = acc[n8][3];
            sacc[oc0][wn * C1P + col + 1] = v0;
            sacc[oc0 + 8][wn * C1P + col + 1] = v1;
            s0 += v0; q0 = fmaf(v0, v0, q0);
            s1 += v1; q1 = fmaf(v1, v1, q1);
        }
    }
#pragma unroll
    for (int off = 1; off <= 2; off <<= 1) {
        s0 += __shfl_xor_sync(0xffffffffu, s0, off);
        q0 += __shfl_xor_sync(0xffffffffu, q0, off);
        s1 += __shfl_xor_sync(0xffffffffu, s1, off);
        q1 += __shfl_xor_sync(0xffffffffu, q1, off);
    }
    if ((lane & 3) == 0) {
        s_stats[wn][oc0][0] = s0;
        s_stats[wn][oc0][1] = q0;
        s_stats[wn][oc0 + 8][0] = s1;
        s_stats[wn][oc0 + 8][1] = q1;
    }
    __syncthreads();

    for (int i = tid; i < 64 * 42; i += 256) {
        int oc = i / 42, pc = i % 42;
        float v = fmaxf(fmaxf(sacc[oc][2 * pc], sacc[oc][2 * pc + 1]),
                        fmaxf(sacc[oc][C1P + 2 * pc], sacc[oc][C1P + 2 * pc + 1]));
        p1pre[((size_t)img * 64 + oc) * 1764 + bx * 42 + pc] = v;
    }
    if (tid < 128) {
        int oc = tid >> 1, wh = tid & 1;
        st1[(((size_t)img * 42 + bx) * 64 + oc) * 2 + wh] =
            s_stats[0][oc][wh] + s_stats[1][oc][wh];
    }
}

// ---------------------------------------------------------------------------
// Fused stats (unchanged). grid (64), 256 threads.
// ---------------------------------------------------------------------------
__global__ void stats_fused_kernel(const float* __restrict__ st1, int NB,
                                   int HW,
                                   const float* __restrict__ gamma,
                                   const float* __restrict__ beta,
                                   float* __restrict__ scale,
                                   float* __restrict__ shift) {
    const int c = blockIdx.x;
    const int tid = threadIdx.x;
    float a[6][2];
#pragma unroll
    for (int g = 0; g < 6; g++) { a[g][0] = 0.f; a[g][1] = 0.f; }
    const int total = NIMG * NB;
    for (int i = tid; i < total; i += 256) {
        int img = i / NB, blk = i % NB;
        int g = img_group(img);
        const float* p = &st1[(((size_t)img * NB + blk) * 64 + c) * 2];
        a[g][0] += p[0];
        a[g][1] += p[1];
    }
    __shared__ float sm[256][12];
#pragma unroll
    for (int g = 0; g < 6; g++) {
        sm[tid][2 * g] = a[g][0];
        sm[tid][2 * g + 1] = a[g][1];
    }
    __syncthreads();
    for (int off = 128; off > 0; off >>= 1) {
        if (tid < off)
#pragma unroll
            for (int j = 0; j < 12; j++) sm[tid][j] += sm[tid + off][j];
        __syncthreads();
    }
    if (tid < 6) {
        int g = tid;
        int nimg = (g == 0) ? 32 : 5;
        float cnt = (float)(nimg * HW);
        float m = sm[0][2 * g] / cnt;
        float var = sm[0][2 * g + 1] / cnt - m * m;
        float inv = rsqrtf(var + 1e-5f);
        float sc = gamma[c] * inv;
        scale[g * 64 + c] = sc;
        shift[g * 64 + c] = beta[c] - m * sc;
    }
}

// ---------------------------------------------------------------------------
// conv64 in bf16 m16n8k16. Warps: 4M x 2N. Smem: bf16 ci-PAIRS as u32 words
//   sB[cp][r*PITCH+c] = (x[2cp], x[2cp+1]),  cp = 0..7 per 16-ci chunk.
// B frag = 2 LDS.32 ((lane&3)*CIP, +4*CIP). 4 chunks; per chunk 9 taps x
// 8 n8 x 1 mma. CIP === 8 (mod 32) -> conflict-free.
// MODE: 1 = BN+LReLU on input; 2 = BN+LReLU+2x2 maxpool on 2H-sized input.
// ---------------------------------------------------------------------------
template <int H, int NROWS, int PITCH, int CIP, int MODE>
__global__ void __launch_bounds__(256) conv_bf16_kernel(
    const float* __restrict__ in, const float* __restrict__ wbuf,
    float* __restrict__ out,
    const float* __restrict__ scale, const float* __restrict__ shift,
    float* __restrict__ st1) {
    constexpr int R = NROWS + 2;
    constexpr int W = H;
    constexpr int HW = H * H;
    constexpr int TOT = 8 * R * (W + 2);
    constexpr int IN_HW = (MODE == 2) ? 4 * HW : HW;
    constexpr int IN_W = (MODE == 2) ? 2 * W : W;

    __shared__ u32 sB[8 * CIP];
    __shared__ float s_stats[2][64][2];

    const int rb = blockIdx.x * NROWS;
    const int img = blockIdx.y;
    const int tid = threadIdx.x;
    const int wid = tid >> 5, lane = tid & 31;
    const int wm = wid & 3, wn = wid >> 2;
    const int g = img_group(img);
    const int vrows = min(rb + NROWS, H) - rb;
    const int valid = vrows * W;

    u32 baddr[8];
    {
        u32 kq = (u32)(lane & 3) * CIP;
#pragma unroll
        for (int n8 = 0; n8 < 8; n8++) {
            int n = wn * 64 + n8 * 8 + (lane >> 2);
            u32 poff = 0;
            if (n < valid) poff = (u32)((n / W) * PITCH + (n % W));
            baddr[n8] = kq + poff;
        }
    }

    float acc[8][4];
#pragma unroll
    for (int n8 = 0; n8 < 8; n8++)
#pragma unroll
        for (int j = 0; j < 4; j++) acc[n8][j] = 0.f;

    const float* ip = in + (size_t)img * 64 * IN_HW;

    for (int cc4 = 0; cc4 < 4; cc4++) {
        __syncthreads();
        for (int i = tid; i < TOT; i += 256) {
            int cp = i / (R * (W + 2));
            int rem = i % (R * (W + 2));
            int r = rem / (W + 2), c = rem % (W + 2);
            int gy = rb - 1 + r, gx = c - 1;
            u32 word = 0u;
            if (gy >= 0 && gy < H && gx >= 0 && gx < W) {
                int ci0 = cc4 * 16 + 2 * cp;
                float v0, v1;
                if (MODE == 2) {
                    const float* q0 = ip + (size_t)ci0 * IN_HW +
                                      (2 * gy) * IN_W + 2 * gx;
                    const float* q1 = q0 + IN_HW;
                    float sc0 = scale[g * 64 + ci0], sf0 = shift[g * 64 + ci0];
                    float sc1 = scale[g * 64 + ci0 + 1],
                          sf1 = shift[g * 64 + ci0 + 1];
                    float a0 = lrelu(fmaf(q0[0], sc0, sf0));
                    float a1 = lrelu(fmaf(q0[1], sc0, sf0));
                    float a2 = lrelu(fmaf(q0[IN_W], sc0, sf0));
                    float a3 = lrelu(fmaf(q0[IN_W + 1], sc0, sf0));
                    v0 = fmaxf(fmaxf(a0, a1), fmaxf(a2, a3));
                    float b0 = lrelu(fmaf(q1[0], sc1, sf1));
                    float b1 = lrelu(fmaf(q1[1], sc1, sf1));
                    float b2 = lrelu(fmaf(q1[IN_W], sc1, sf1));
                    float b3 = lrelu(fmaf(q1[IN_W + 1], sc1, sf1));
                    v1 = fmaxf(fmaxf(b0, b1), fmaxf(b2, b3));
                } else {
                    v0 = ip[(size_t)ci0 * IN_HW + gy * W + gx];
                    v1 = ip[(size_t)(ci0 + 1) * IN_HW + gy * W + gx];
                    v0 = lrelu(fmaf(v0, scale[g * 64 + ci0],
                                    shift[g * 64 + ci0]));
                    v1 = lrelu(fmaf(v1, scale[g * 64 + ci0 + 1],
                                    shift[g * 64 + ci0 + 1]));
                }
                word = pack_bf16(v0, v1);
            }
            sB[cp * CIP + r * PITCH + c] = word;
        }
        __syncthreads();

#pragma unroll
        for (int t = 0; t < 9; t++) {
            const int dy = t / 3, dx = t % 3;
            const int soff = dy * PITCH + dx;
            float4 af = *(const float4*)&wbuf[(((cc4 * 9 + t) * 4 + wm) * 32 +
                                              lane) * 4];
            u32 a[4] = {__float_as_uint(af.x), __float_as_uint(af.y),
                        __float_as_uint(af.z), __float_as_uint(af.w)};
#pragma unroll
            for (int n8 = 0; n8 < 8; n8++) {
                u32 b0 = sB[baddr[n8] + soff];
                u32 b1 = sB[baddr[n8] + soff + 4 * CIP];
                mma16816(acc[n8], a, b0, b1);
            }
        }
    }

    const int r0 = wm * 16 + (lane >> 2);
    float* op0 = out + ((size_t)img * 64 + r0) * HW;
    float* op1 = out + ((size_t)img * 64 + r0 + 8) * HW;
    float s0 = 0.f, q0 = 0.f, s1 = 0.f, q1 = 0.f;
#pragma unroll
    for (int n8 = 0; n8 < 8; n8++) {
        int nb = wn * 64 + n8 * 8 + 2 * (lane & 3);
        if (nb < valid) {
            int p = (rb + nb / W) * W + nb % W;
            float v0 = acc[n8][0], v1 = acc[n8][2];
            op0[p] = v0;
            op1[p] = v1;
            s0 += v0; q0 = fmaf(v0, v0, q0);
            s1 += v1; q1 = fmaf(v1, v1, q1);
        }
        if (nb + 1 < valid) {
            int p = (rb + (nb + 1) / W) * W + (nb + 1) % W;
            float v0 = acc[n8][1], v1 = acc[n8][3];
            op0[p] = v0;
            op1[p] = v1;
            s0 += v0; q0 = fmaf(v0, v0, q0);
            s1 += v1; q1 = fmaf(v1, v1, q1);
        }
    }
#pragma unroll
    for (int off = 1; off <= 2; off <<= 1) {
        s0 += __shfl_xor_sync(0xffffffffu, s0, off);
        q0 += __shfl_xor_sync(0xffffffffu, q0, off);
        s1 += __shfl_xor_sync(0xffffffffu, s1, off);
        q1 += __shfl_xor_sync(0xffffffffu, q1, off);
    }
    if ((lane & 3) == 0) {
        s_stats[wn][r0][0] = s0;
        s_stats[wn][r0][1] = q0;
        s_stats[wn][r0 + 8][0] = s1;
        s_stats[wn][r0 + 8][1] = q1;
    }
    __syncthreads();
    if (tid < 128) {
        int oc = tid >> 1, wh = tid & 1;
        st1[(((size_t)img * gridDim.x + blockIdx.x) * 64 + oc) * 2 + wh] =
            s_stats[0][oc][wh] + s_stats[1][oc][wh];
    }
}

// ---------------------------------------------------------------------------
// qsnorm (unchanged).
// ---------------------------------------------------------------------------
__global__ void qsnorm_kernel(const float* __restrict__ f,
                              const float* __restrict__ scale,
                              const float* __restrict__ shift,
                              __nv_bfloat16* __restrict__ Qh,
                              __nv_bfloat16* __restrict__ ShK) {
    int idx = blockIdx.x * blockDim.x + threadIdx.x;
    if (idx < 32 * 441) {
        int b = idx / 441, pix = idx % 441;
        const float* p = f + (size_t)b * 64 * 441 + pix;
        float vals[64];
        float s = 0.f;
#pragma unroll 8
        for (int c = 0; c < 64; c++) {
            float v = lrelu(fmaf(p[c * 441], scale[c], shift[c]));
            vals[c] = v;
            s = fmaf(v, v, s);
        }
        float inv = rsqrtf(s);
        __nv_bfloat162* op = (__nv_bfloat162*)&Qh[(size_t)idx * 64];
#pragma unroll 8
        for (int c = 0; c < 32; c++)
            op[c] = __floats2bfloat162_rn(vals[2 * c] * inv,
                                          vals[2 * c + 1] * inv);
    } else if (idx < 32 * 441 + 5 * 2240) {
        int r = idx - 32 * 441;
        int n = r / 2240, m = r % 2240;
        if (m >= 2205) {
#pragma unroll 8
            for (int c = 0; c < 64; c++)
                ShK[((size_t)n * 64 + c) * 2240 + m] = __float2bfloat16(0.f);
            return;
        }
        int sh = m / 441, pix = m % 441;
        int img = 32 + n * 5 + sh;
        int g = 1 + n;
        const float* p = f + (size_t)img * 64 * 441 + pix;
        float vals[64];
        float s = 0.f;
#pragma unroll 8
        for (int c = 0; c < 64; c++) {
            float v = lrelu(fmaf(p[c * 441], scale[g * 64 + c],
                                 shift[g * 64 + c]));
            vals[c] = v;
            s = fmaf(v, v, s);
        }
        float inv = rsqrtf(s);
#pragma unroll 8
        for (int c = 0; c < 64; c++)
            ShK[((size_t)n * 64 + c) * 2240 + m] =
                __float2bfloat16(vals[c] * inv);
    }
}

// ---------------------------------------------------------------------------
// sims via mma.sync m16n8k16 bf16, 128 rows/block (unchanged).
// ---------------------------------------------------------------------------
#define SPAD 72

__device__ __forceinline__ void ins3(float v, float& t0, float& t1, float& t2) {
    float lo = fminf(v, t0);
    t0 = fmaxf(v, t0);
    float mid = fminf(lo, t1);
    t1 = fmaxf(lo, t1);
    t2 = fmaxf(t2, mid);
}

__global__ void __launch_bounds__(256) sims_mma_kernel(
    const __nv_bfloat16* __restrict__ Qh,
    const __nv_bfloat16* __restrict__ ShK,
    float* __restrict__ part) {
    __shared__ __nv_bfloat16 sQ[128][SPAD];
    __shared__ __nv_bfloat16 sS[64][SPAD];
    __shared__ float red[8];

    const int rchunk = blockIdx.x;
    const int n = blockIdx.y;
    const int b = blockIdx.z;
    const int rbase = rchunk * 128;
    const int tid = threadIdx.x;
    const int wid = tid >> 5, lane = tid & 31;

    for (int i = tid; i < 128 * 8; i += 256) {
        int r = i >> 3, c8 = i & 7;
        uint4 v = make_uint4(0u, 0u, 0u, 0u);
        if (rbase + r < 441)
            v = *(const uint4*)&Qh[((size_t)(b * 441 + rbase + r)) * 64 + c8 * 8];
        *(uint4*)&sQ[r][c8 * 8] = v;
    }
    __syncthreads();

    const u32 sQb = smem_u32(&sQ[0][0]);
    const u32 sSb = smem_u32(&sS[0][0]);
    const int m0 = wid * 16;

    u32 afr[4][4];
    {
        int rr = m0 + (lane & 15);
        int cc = (lane >> 4) * 8;
#pragma unroll
        for (int ks = 0; ks < 4; ks++)
            ldsm_x4(afr[ks][0], afr[ks][1], afr[ks][2], afr[ks][3],
                    sQb + (u32)((rr * SPAD + ks * 16 + cc) * 2));
    }

    float ta0 = -1e30f, ta1 = -1e30f, ta2 = -1e30f;
    float tb0 = -1e30f, tb1 = -1e30f, tb2 = -1e30f;

    const __nv_bfloat16* Sbase = ShK + (size_t)n * 64 * 2240;

    for (int tile = 0; tile < 35; tile++) {
        const int c0 = tile * 64;
        __syncthreads();
        for (int i = tid; i < 64 * 8; i += 256) {
            int k = i >> 3, p8 = i & 7;
            uint4 v = *(const uint4*)&Sbase[(size_t)k * 2240 + c0 + p8 * 8];
            *(uint4*)&sS[k][p8 * 8] = v;
        }
        __syncthreads();

        float d[8][4];
#pragma unroll
        for (int j = 0; j < 8; j++)
#pragma unroll
            for (int c = 0; c < 4; c++) d[j][c] = 0.f;

        const int kr_l = (lane & 7) + ((lane >> 3) & 1) * 8;
        const int nc_l = (lane >> 4) * 8;
#pragma unroll
        for (int ks = 0; ks < 4; ks++) {
            int kr = ks * 16 + kr_l;
#pragma unroll
            for (int n16 = 0; n16 < 4; n16++) {
                u32 b0, b1, b2, b3;
                ldsm_x4t(b0, b1, b2, b3,
                         sSb + (u32)((kr * SPAD + n16 * 16 + nc_l) * 2));
                mma16816(d[2 * n16], afr[ks], b0, b1);
                mma16816(d[2 * n16 + 1], afr[ks], b2, b3);
            }
        }

        if (tile != 34) {
#pragma unroll
            for (int n8 = 0; n8 < 8; n8++) {
                ins3(d[n8][0], ta0, ta1, ta2);
                ins3(d[n8][1], ta0, ta1, ta2);
                ins3(d[n8][2], tb0, tb1, tb2);
                ins3(d[n8][3], tb0, tb1, tb2);
            }
        } else {
            int cb = c0 + 2 * (lane & 3);
#pragma unroll
            for (int n8 = 0; n8 < 8; n8++) {
                int c = cb + n8 * 8;
                if (c < 2205) { ins3(d[n8][0], ta0, ta1, ta2);
                                ins3(d[n8][2], tb0, tb1, tb2); }
                if (c + 1 < 2205) { ins3(d[n8][1], ta0, ta1, ta2);
                                    ins3(d[n8][3], tb0, tb1, tb2); }
            }
        }
    }

#pragma unroll
    for (int off = 1; off <= 2; off <<= 1) {
        float x0 = __shfl_xor_sync(0xffffffffu, ta0, off);
        float x1 = __shfl_xor_sync(0xffffffffu, ta1, off);
        float x2 = __shfl_xor_sync(0xffffffffu, ta2, off);
        ins3(x0, ta0, ta1, ta2);
        ins3(x1, ta0, ta1, ta2);
        ins3(x2, ta0, ta1, ta2);
        float y0 = __shfl_xor_sync(0xffffffffu, tb0, off);
        float y1 = __shfl_xor_sync(0xffffffffu, tb1, off);
        float y2 = __shfl_xor_sync(0xffffffffu, tb2, off);
        ins3(y0, tb0, tb1, tb2);
        ins3(y1, tb0, tb1, tb2);
        ins3(y2, tb0, tb1, tb2);
    }

    float s = 0.f;
    if ((lane & 3) == 0) {
        int r1 = rbase + m0 + (lane >> 2);
        if (r1 < 441) s += ta0 + ta1 + ta2;
        if (r1 + 8 < 441) s += tb0 + tb1 + tb2;
    }
#pragma unroll
    for (int off = 16; off > 0; off >>= 1)
        s += __shfl_down_sync(0xffffffffu, s, off);
    if (lane == 0) red[wid] = s;
    __syncthreads();
    if (tid == 0) {
        float r = 0.f;
#pragma unroll
        for (int i = 0; i < 8; i++) r += red[i];
        part[(b * 5 + n) * 4 + rchunk] = r;
    }
}

__global__ void finalize_kernel(const float* __restrict__ part,
                                float* __restrict__ out) {
    int i = threadIdx.x;
    if (i < 160) {
        float s = 0.f;
#pragma unroll
        for (int k = 0; k < 4; k++) s += part[4 * i + k];
        out[i] = s;
    }
}

// ---------------------------------------------------------------------------
extern "C" void kernel_launch(void* const* d_in, const int* in_sizes, int n_in,
                              void* d_out, int out_size) {
    const float* input1 = (const float*)d_in[0];
    const float* input2 = (const float*)d_in[1];
    const float* w1 = (const float*)d_in[2];
    const float* g1 = (const float*)d_in[3];
    const float* b1 = (const float*)d_in[4];
    const float* w2 = (const float*)d_in[5];
    const float* g2 = (const float*)d_in[6];
    const float* b2 = (const float*)d_in[7];
    const float* w3 = (const float*)d_in[8];
    const float* g3 = (const float*)d_in[9];
    const float* b3 = (const float*)d_in[10];
    const float* w4 = (const float*)d_in[11];
    const float* g4 = (const float*)d_in[12];
    const float* b4 = (const float*)d_in[13];
    float* out = (float*)d_out;

    void* poolPtr = nullptr;
    cudaGetSymbolAddress(&poolPtr, d_pool);
    float* P = (float*)poolPtr;
    float* p1pre = P + OFF_P1;
    float* c2 = P + OFF_C2;
    float* c3 = P + OFF_C3;
    float* c4 = P + OFF_C4;
    __nv_bfloat16* Qh = (__nv_bfloat16*)(P + OFF_QH);
    __nv_bfloat16* ShK = (__nv_bfloat16*)(P + OFF_SK);
    float* sc = P + OFF_SC;
    float* sh = P + OFF_SHF;
    float* part = P + OFF_PART;
    float* wb2b = P + OFF_WB;                 // conv2 bf16 frags
    float* wb3b = P + OFF_WB + 18432;         // conv3 bf16 frags
    float* wb4b = P + OFF_WB + 2 * 18432;     // conv4 bf16 frags
    float* wb1 = P + OFF_WB1;
    float* st1 = P + OFF_ST1;

    const int WPREP_TOT = 3 * 18432 + 2048;
    wprep_kernel<<<(WPREP_TOT + 255) / 256, 256>>>(w1, w2, w3, w4, wb2b, wb1);
    conv1_pool_kernel<<<dim3(42, NIMG), 256>>>(input1, input2, wb1, p1pre, st1);
    stats_fused_kernel<<<64, 256>>>(st1, 42, 7056, g1, b1, sc, sh);
    // conv2: bf16, H=42, PITCH=44, CIP=232 (BN1+LReLU fused on input)
    conv_bf16_kernel<42, 3, 44, 232, 1><<<dim3(14, NIMG), 256>>>(
        p1pre, wb2b, c2, sc, sh, st1);
    stats_fused_kernel<<<64, 256>>>(st1, 14, 1764, g2, b2, sc, sh);
    // conv3: bf16, H=21, PITCH=24, CIP=200 (BN2+LReLU+pool fused on input)
    conv_bf16_kernel<21, 6, 24, 200, 2><<<dim3(4, NIMG), 256>>>(
        c2, wb3b, c3, sc, sh, st1);
    stats_fused_kernel<<<64, 256>>>(st1, 4, 441, g3, b3, sc, sh);
    // conv4: bf16, H=21 (BN3+LReLU fused on input)
    conv_bf16_kernel<21, 6, 24, 200, 1><<<dim3(4, NIMG), 256>>>(
        c3, wb4b, c4, sc, sh, st1);
    stats_fused_kernel<<<64, 256>>>(st1, 4, 441, g4, b4, sc, sh);
    qsnorm_kernel<<<(32 * 441 + 5 * 2240 + 127) / 128, 128>>>(c4, sc, sh,
                                                              Qh, ShK);
    sims_mma_kernel<<<dim3(4, 5, 32), 256>>>(Qh, ShK, part);
    finalize_kernel<<<1, 160>>>(part, out);
}

// round 16
// speedup vs baseline: 1.2660x; 1.0628x over previous
#include <cuda_runtime.h>
#include <cuda_bf16.h>
#include <math.h>

// ---------------------------------------------------------------------------
// FourLayer_64F. Round 16: sims S-tiles double-buffered (register prefetch,
// 1 sync/tile); conv2 epilogue uses paired STG.64. Rest = Round 15 (bf16
// m16n8k16 convs 2-4, tf32 conv1, fused BN stats/pool, 12 launches).
// ---------------------------------------------------------------------------

#define NIMG 57
#define NEG_SLOPE 0.2f

typedef unsigned int u32;

__device__ __forceinline__ u32 f2tf32(float v) {
    u32 r;
    asm("cvt.rna.tf32.f32 %0, %1;" : "=r"(r) : "f"(v));
    return r;
}
__device__ __forceinline__ u32 pack_bf16(float lo, float hi) {
    __nv_bfloat162 p = __floats2bfloat162_rn(lo, hi);
    return *(u32*)&p;
}

// ---------------- scratch pool (floats) ------------------------------------
#define OFF_P1   ((size_t)0)                        // 57*64*1764 pooled pre-BN1
#define OFF_C2   (OFF_P1 + (size_t)57*64*1764)      // 57*64*1764
#define OFF_C3   (OFF_C2 + (size_t)57*64*1764)      // 57*64*441
#define OFF_C4   (OFF_C3 + (size_t)57*64*441)
#define OFF_QH   (OFF_C4 + (size_t)57*64*441)       // bf16 32*441*64 -> 451584 f
#define OFF_SK   (OFF_QH + (size_t)451584)          // bf16 5*64*2240 -> 358400 f
#define OFF_SC   (OFF_SK + (size_t)358400)          // 6*64 scale
#define OFF_SHF  (OFF_SC + 384)                     // 6*64 shift
#define OFF_PART (OFF_SHF + 384)                    // 32*5*4
#define OFF_WB   (OFF_PART + 640)                   // 3*18432 bf16 conv frags
#define OFF_WB1  (OFF_WB + (size_t)3*18432)         // 2048 conv1 tf32
#define OFF_ST1  (OFF_WB1 + 2048)                   // 57*42*64*2 block partials
#define POOL_TOTAL (OFF_ST1 + (size_t)57*42*64*2)

__device__ float d_pool[POOL_TOTAL];

__device__ __forceinline__ float lrelu(float v) {
    return v >= 0.f ? v : NEG_SLOPE * v;
}
__device__ __forceinline__ int img_group(int img) {
    return (img < 32) ? 0 : 1 + (img - 32) / 5;
}

__device__ __forceinline__ u32 smem_u32(const void* p) {
    u32 a;
    asm("{ .reg .u64 t; cvta.to.shared.u64 t, %1; cvt.u32.u64 %0, t; }"
        : "=r"(a) : "l"(p));
    return a;
}
__device__ __forceinline__ void ldsm_x4(u32& r0, u32& r1, u32& r2, u32& r3,
                                        u32 addr) {
    asm volatile("ldmatrix.sync.aligned.m8n8.x4.shared.b16 {%0,%1,%2,%3}, [%4];"
                 : "=r"(r0), "=r"(r1), "=r"(r2), "=r"(r3) : "r"(addr));
}
__device__ __forceinline__ void ldsm_x4t(u32& r0, u32& r1, u32& r2, u32& r3,
                                         u32 addr) {
    asm volatile(
        "ldmatrix.sync.aligned.m8n8.x4.trans.shared.b16 {%0,%1,%2,%3}, [%4];"
        : "=r"(r0), "=r"(r1), "=r"(r2), "=r"(r3) : "r"(addr));
}
__device__ __forceinline__ void mma16816(float* d, const u32* a, u32 b0, u32 b1) {
    asm volatile(
        "mma.sync.aligned.m16n8k16.row.col.f32.bf16.bf16.f32 "
        "{%0,%1,%2,%3}, {%4,%5,%6,%7}, {%8,%9}, {%0,%1,%2,%3};"
        : "+f"(d[0]), "+f"(d[1]), "+f"(d[2]), "+f"(d[3])
        : "r"(a[0]), "r"(a[1]), "r"(a[2]), "r"(a[3]), "r"(b0), "r"(b1));
}
__device__ __forceinline__ void mma_tf32(float* d, u32 a0, u32 a1, u32 a2,
                                         u32 a3, u32 b0, u32 b1) {
    asm volatile(
        "mma.sync.aligned.m16n8k8.row.col.f32.tf32.tf32.f32 "
        "{%0,%1,%2,%3}, {%4,%5,%6,%7}, {%8,%9}, {%0,%1,%2,%3};"
        : "+f"(d[0]), "+f"(d[1]), "+f"(d[2]), "+f"(d[3])
        : "r"(a0), "r"(a1), "r"(a2), "r"(a3), "r"(b0), "r"(b1));
}

// ---------------------------------------------------------------------------
// Weight prep, one launch (unchanged from R15).
// ---------------------------------------------------------------------------
__global__ void wprep_kernel(const float* __restrict__ w1,
                             const float* __restrict__ w2,
                             const float* __restrict__ w3,
                             const float* __restrict__ w4,
                             float* __restrict__ wbuf,
                             float* __restrict__ wbuf1) {
    int idx = blockIdx.x * 256 + threadIdx.x;
    if (idx < 3 * 18432) {
        int which = idx / 18432;
        int r = idx % 18432;
        const float* w = (which == 0) ? w2 : (which == 1) ? w3 : w4;
        int j = r & 3;
        int lane = (r >> 2) & 31;
        int wm = (r >> 7) & 3;
        int rest = r >> 9;
        int t = rest % 9, cc4 = rest / 9;
        int oc = wm * 16 + (lane >> 2) + 8 * (j & 1);
        int k2 = 2 * (lane & 3) + 8 * (j >> 1);
        int ci = cc4 * 16 + k2;
        float lo = w[(oc * 64 + ci) * 9 + t];
        float hi = w[(oc * 64 + ci + 1) * 9 + t];
        wbuf[idx] = __uint_as_float(pack_bf16(lo, hi));
    } else if (idx < 3 * 18432 + 2048) {
        int r = idx - 3 * 18432;
        int j = r & 3;
        int lane = (r >> 2) & 31;
        int wm = (r >> 7) & 3;
        int ks = r >> 9;
        int oc = wm * 16 + (lane >> 2) + (j & 1) * 8;
        int k = ks * 8 + (lane & 3) + ((j >> 1) & 1) * 4;
        float v = 0.f;
        if (k < 27) v = w1[(oc * 3 + k / 9) * 9 + (k % 9)];
        wbuf1[r] = __uint_as_float(f2tf32(v));
    }
}

// ---------------------------------------------------------------------------
// conv1 + maxpool, tf32 shift-GEMM (unchanged). grid (42, 57).
// ---------------------------------------------------------------------------
#define C1P 88
#define C1CIP 360

__global__ void __launch_bounds__(256) conv1_pool_kernel(
    const float* __restrict__ in1, const float* __restrict__ in2,
    const float* __restrict__ wbuf1, float* __restrict__ p1pre,
    float* __restrict__ st1) {
    __shared__ char sraw[45056];
    __shared__ float s_stats[2][64][2];
    u32* s_in = (u32*)sraw;
    float(*sacc)[176] = (float(*)[176])sraw;

    const int bx = blockIdx.x;
    const int img = blockIdx.y;
    const int tid = threadIdx.x;
    const int wid = tid >> 5, lane = tid & 31;
    const int wm = wid & 3, wn = wid >> 2;

    const float* ip = (img < 32) ? (in1 + (size_t)img * 3 * 7056)
                                 : (in2 + (size_t)(img - 32) * 3 * 7056);

    for (int i = tid; i < 3 * 4 * C1P; i += 256) {
        int ci = i / (4 * C1P);
        int rem = i % (4 * C1P);
        int r = rem / C1P, c = rem % C1P;
        int gy = 2 * bx - 1 + r, gx = c - 1;
        float v = 0.f;
        if (gy >= 0 && gy < 84 && gx >= 0 && gx < 84)
            v = ip[ci * 7056 + gy * 84 + gx];
        s_in[ci * C1CIP + r * C1P + c] = f2tf32(v);
    }
    if (tid < 24)
        s_in[(tid / 8) * C1CIP + 4 * C1P + (tid % 8)] = 0u;
    __syncthreads();

    u32 koffA[4], koffB[4];
#pragma unroll
    for (int ks = 0; ks < 4; ks++) {
        int kA = ks * 8 + (lane & 3), kB = kA + 4;
        koffA[ks] = (kA < 27)
            ? (u32)((kA / 9) * C1CIP + ((kA % 9) / 3) * C1P + (kA % 9) % 3)
            : 0u;
        koffB[ks] = (kB < 27)
            ? (u32)((kB / 9) * C1CIP + ((kB % 9) / 3) * C1P + (kB % 9) % 3)
            : 0u;
    }
    const u32 pixrow = (u32)(wn * C1P) + (u32)(lane >> 2);

    float acc[11][4];
#pragma unroll
    for (int n8 = 0; n8 < 11; n8++)
#pragma unroll
        for (int j = 0; j < 4; j++) acc[n8][j] = 0.f;

#pragma unroll
    for (int ks = 0; ks < 4; ks++) {
        float4 af = *(const float4*)&wbuf1[((ks * 4 + wm) * 32 + lane) * 4];
        u32 a0 = __float_as_uint(af.x);
        u32 a1 = __float_as_uint(af.y);
        u32 a2 = __float_as_uint(af.z);
        u32 a3 = __float_as_uint(af.w);
#pragma unroll
        for (int n8 = 0; n8 < 11; n8++) {
            u32 p = pixrow + n8 * 8;
            u32 b0 = s_in[koffA[ks] + p];
            u32 b1 = s_in[koffB[ks] + p];
            mma_tf32(acc[n8], a0, a1, a2, a3, b0, b1);
        }
    }
    __syncthreads();

    const int oc0 = wm * 16 + (lane >> 2);
    float s0 = 0.f, q0 = 0.f, s1 = 0.f, q1 = 0.f;
#pragma unroll
    for (int n8 = 0; n8 < 11; n8++) {
        int col = n8 * 8 + 2 * (lane & 3);
        if (col < 84) {
            float v0 = acc[n8][0], v1 = acc[n8][2];
            sacc[oc0][wn * C1P + col] = v0;
            sacc[oc0 + 8][wn * C1P + col] = v1;
            s0 += v0; q0 = fmaf(v0, v0, q0);
            s1 += v1; q1 = fmaf(v1, v1, q1);
        }
        if (col + 1 < 84) {
            float v0 = acc[n8][1], v1 = acc[n8][3];
            sacc[oc0][wn * C1P + col + 1] = v0;
            sacc[oc0 + 8][wn * C1P + col + 1] = v1;
            s0 += v0; q0 = fmaf(v0, v0, q0);
            s1 += v1; q1 = fmaf(v1, v1, q1);
        }
    }
#pragma unroll
    for (int off = 1; off <= 2; off <<= 1) {
        s0 += __shfl_xor_sync(0xffffffffu, s0, off);
        q0 += __shfl_xor_sync(0xffffffffu, q0, off);
        s1 += __shfl_xor_sync(0xffffffffu, s1, off);
        q1 += __shfl_xor_sync(0xffffffffu, q1, off);
    }
    if ((lane & 3) == 0) {
        s_stats[wn][oc0][0] = s0;
        s_stats[wn][oc0][1] = q0;
        s_stats[wn][oc0 + 8][0] = s1;
        s_stats[wn][oc0 + 8][1] = q1;
    }
    __syncthreads();

    for (int i = tid; i < 64 * 42; i += 256) {
        int oc = i / 42, pc = i % 42;
        float v = fmaxf(fmaxf(sacc[oc][2 * pc], sacc[oc][2 * pc + 1]),
                        fmaxf(sacc[oc][C1P + 2 * pc], sacc[oc][C1P + 2 * pc + 1]));
        p1pre[((size_t)img * 64 + oc) * 1764 + bx * 42 + pc] = v;
    }
    if (tid < 128) {
        int oc = tid >> 1, wh = tid & 1;
        st1[(((size_t)img * 42 + bx) * 64 + oc) * 2 + wh] =
            s_stats[0][oc][wh] + s_stats[1][oc][wh];
    }
}

// ---------------------------------------------------------------------------
// Fused stats (unchanged). grid (64), 256 threads.
// ---------------------------------------------------------------------------
__global__ void stats_fused_kernel(const float* __restrict__ st1, int NB,
                                   int HW,
                                   const float* __restrict__ gamma,
                                   const float* __restrict__ beta,
                                   float* __restrict__ scale,
                                   float* __restrict__ shift) {
    const int c = blockIdx.x;
    const int tid = threadIdx.x;
    float a[6][2];
#pragma unroll
    for (int g = 0; g < 6; g++) { a[g][0] = 0.f; a[g][1] = 0.f; }
    const int total = NIMG * NB;
    for (int i = tid; i < total; i += 256) {
        int img = i / NB, blk = i % NB;
        int g = img_group(img);
        const float* p = &st1[(((size_t)img * NB + blk) * 64 + c) * 2];
        a[g][0] += p[0];
        a[g][1] += p[1];
    }
    __shared__ float sm[256][12];
#pragma unroll
    for (int g = 0; g < 6; g++) {
        sm[tid][2 * g] = a[g][0];
        sm[tid][2 * g + 1] = a[g][1];
    }
    __syncthreads();
    for (int off = 128; off > 0; off >>= 1) {
        if (tid < off)
#pragma unroll
            for (int j = 0; j < 12; j++) sm[tid][j] += sm[tid + off][j];
        __syncthreads();
    }
    if (tid < 6) {
        int g = tid;
        int nimg = (g == 0) ? 32 : 5;
        float cnt = (float)(nimg * HW);
        float m = sm[0][2 * g] / cnt;
        float var = sm[0][2 * g + 1] / cnt - m * m;
        float inv = rsqrtf(var + 1e-5f);
        float sc = gamma[c] * inv;
        scale[g * 64 + c] = sc;
        shift[g * 64 + c] = beta[c] - m * sc;
    }
}

// ---------------------------------------------------------------------------
// conv64 in bf16 m16n8k16 (as R15) + paired STG.64 epilogue when W is even.
// ---------------------------------------------------------------------------
template <int H, int NROWS, int PITCH, int CIP, int MODE>
__global__ void __launch_bounds__(256) conv_bf16_kernel(
    const float* __restrict__ in, const float* __restrict__ wbuf,
    float* __restrict__ out,
    const float* __restrict__ scale, const float* __restrict__ shift,
    float* __restrict__ st1) {
    constexpr int R = NROWS + 2;
    constexpr int W = H;
    constexpr int HW = H * H;
    constexpr int TOT = 8 * R * (W + 2);
    constexpr int IN_HW = (MODE == 2) ? 4 * HW : HW;
    constexpr int IN_W = (MODE == 2) ? 2 * W : W;

    __shared__ u32 sB[8 * CIP];
    __shared__ float s_stats[2][64][2];

    const int rb = blockIdx.x * NROWS;
    const int img = blockIdx.y;
    const int tid = threadIdx.x;
    const int wid = tid >> 5, lane = tid & 31;
    const int wm = wid & 3, wn = wid >> 2;
    const int g = img_group(img);
    const int vrows = min(rb + NROWS, H) - rb;
    const int valid = vrows * W;

    u32 baddr[8];
    {
        u32 kq = (u32)(lane & 3) * CIP;
#pragma unroll
        for (int n8 = 0; n8 < 8; n8++) {
            int n = wn * 64 + n8 * 8 + (lane >> 2);
            u32 poff = 0;
            if (n < valid) poff = (u32)((n / W) * PITCH + (n % W));
            baddr[n8] = kq + poff;
        }
    }

    float acc[8][4];
#pragma unroll
    for (int n8 = 0; n8 < 8; n8++)
#pragma unroll
        for (int j = 0; j < 4; j++) acc[n8][j] = 0.f;

    const float* ip = in + (size_t)img * 64 * IN_HW;

    for (int cc4 = 0; cc4 < 4; cc4++) {
        __syncthreads();
        for (int i = tid; i < TOT; i += 256) {
            int cp = i / (R * (W + 2));
            int rem = i % (R * (W + 2));
            int r = rem / (W + 2), c = rem % (W + 2);
            int gy = rb - 1 + r, gx = c - 1;
            u32 word = 0u;
            if (gy >= 0 && gy < H && gx >= 0 && gx < W) {
                int ci0 = cc4 * 16 + 2 * cp;
                float v0, v1;
                if (MODE == 2) {
                    const float* q0 = ip + (size_t)ci0 * IN_HW +
                                      (2 * gy) * IN_W + 2 * gx;
                    const float* q1 = q0 + IN_HW;
                    float sc0 = scale[g * 64 + ci0], sf0 = shift[g * 64 + ci0];
                    float sc1 = scale[g * 64 + ci0 + 1],
                          sf1 = shift[g * 64 + ci0 + 1];
                    float a0 = lrelu(fmaf(q0[0], sc0, sf0));
                    float a1 = lrelu(fmaf(q0[1], sc0, sf0));
                    float a2 = lrelu(fmaf(q0[IN_W], sc0, sf0));
                    float a3 = lrelu(fmaf(q0[IN_W + 1], sc0, sf0));
                    v0 = fmaxf(fmaxf(a0, a1), fmaxf(a2, a3));
                    float b0 = lrelu(fmaf(q1[0], sc1, sf1));
                    float b1 = lrelu(fmaf(q1[1], sc1, sf1));
                    float b2 = lrelu(fmaf(q1[IN_W], sc1, sf1));
                    float b3 = lrelu(fmaf(q1[IN_W + 1], sc1, sf1));
                    v1 = fmaxf(fmaxf(b0, b1), fmaxf(b2, b3));
                } else {
                    v0 = ip[(size_t)ci0 * IN_HW + gy * W + gx];
                    v1 = ip[(size_t)(ci0 + 1) * IN_HW + gy * W + gx];
                    v0 = lrelu(fmaf(v0, scale[g * 64 + ci0],
                                    shift[g * 64 + ci0]));
                    v1 = lrelu(fmaf(v1, scale[g * 64 + ci0 + 1],
                                    shift[g * 64 + ci0 + 1]));
                }
                word = pack_bf16(v0, v1);
            }
            sB[cp * CIP + r * PITCH + c] = word;
        }
        __syncthreads();

#pragma unroll
        for (int t = 0; t < 9; t++) {
            const int dy = t / 3, dx = t % 3;
            const int soff = dy * PITCH + dx;
            float4 af = *(const float4*)&wbuf[(((cc4 * 9 + t) * 4 + wm) * 32 +
                                              lane) * 4];
            u32 a[4] = {__float_as_uint(af.x), __float_as_uint(af.y),
                        __float_as_uint(af.z), __float_as_uint(af.w)};
#pragma unroll
            for (int n8 = 0; n8 < 8; n8++) {
                u32 b0 = sB[baddr[n8] + soff];
                u32 b1 = sB[baddr[n8] + soff + 4 * CIP];
                mma16816(acc[n8], a, b0, b1);
            }
        }
    }

    const int r0 = wm * 16 + (lane >> 2);
    float* op0 = out + ((size_t)img * 64 + r0) * HW;
    float* op1 = out + ((size_t)img * 64 + r0 + 8) * HW;
    float s0 = 0.f, q0 = 0.f, s1 = 0.f, q1 = 0.f;
#pragma unroll
    for (int n8 = 0; n8 < 8; n8++) {
        int nb = wn * 64 + n8 * 8 + 2 * (lane & 3);
        if (W % 2 == 0) {
            // even W: nb even => nb, nb+1 always same row; 8B aligned
            if (nb + 1 < valid) {
                int p = (rb + nb / W) * W + nb % W;
                float v0 = acc[n8][0], v1 = acc[n8][1];
                float w0 = acc[n8][2], w1 = acc[n8][3];
                *(float2*)&op0[p] = make_float2(v0, v1);
                *(float2*)&op1[p] = make_float2(w0, w1);
                s0 += v0 + v1;
                q0 = fmaf(v0, v0, fmaf(v1, v1, q0));
                s1 += w0 + w1;
                q1 = fmaf(w0, w0, fmaf(w1, w1, q1));
            } else if (nb < valid) {
                int p = (rb + nb / W) * W + nb % W;
                float v0 = acc[n8][0], w0 = acc[n8][2];
                op0[p] = v0;
                op1[p] = w0;
                s0 += v0; q0 = fmaf(v0, v0, q0);
                s1 += w0; q1 = fmaf(w0, w0, q1);
            }
        } else {
            if (nb < valid) {
                int p = (rb + nb / W) * W + nb % W;
                float v0 = acc[n8][0], v1 = acc[n8][2];
                op0[p] = v0;
                op1[p] = v1;
                s0 += v0; q0 = fmaf(v0, v0, q0);
                s1 += v1; q1 = fmaf(v1, v1, q1);
            }
            if (nb + 1 < valid) {
                int p = (rb + (nb + 1) / W) * W + (nb + 1) % W;
                float v0 = acc[n8][1], v1 = acc[n8][3];
                op0[p] = v0;
                op1[p] = v1;
                s0 += v0; q0 = fmaf(v0, v0, q0);
                s1 += v1; q1 = fmaf(v1, v1, q1);
            }
        }
    }
#pragma unroll
    for (int off = 1; off <= 2; off <<= 1) {
        s0 += __shfl_xor_sync(0xffffffffu, s0, off);
        q0 += __shfl_xor_sync(0xffffffffu, q0, off);
        s1 += __shfl_xor_sync(0xffffffffu, s1, off);
        q1 += __shfl_xor_sync(0xffffffffu, q1, off);
    }
    if ((lane & 3) == 0) {
        s_stats[wn][r0][0] = s0;
        s_stats[wn][r0][1] = q0;
        s_stats[wn][r0 + 8][0] = s1;
        s_stats[wn][r0 + 8][1] = q1;
    }
    __syncthreads();
    if (tid < 128) {
        int oc = tid >> 1, wh = tid & 1;
        st1[(((size_t)img * gridDim.x + blockIdx.x) * 64 + oc) * 2 + wh] =
            s_stats[0][oc][wh] + s_stats[1][oc][wh];
    }
}

// ---------------------------------------------------------------------------
// qsnorm (unchanged).
// ---------------------------------------------------------------------------
__global__ void qsnorm_kernel(const float* __restrict__ f,
                              const float* __restrict__ scale,
                              const float* __restrict__ shift,
                              __nv_bfloat16* __restrict__ Qh,
                              __nv_bfloat16* __restrict__ ShK) {
    int idx = blockIdx.x * blockDim.x + threadIdx.x;
    if (idx < 32 * 441) {
        int b = idx / 441, pix = idx % 441;
        const float* p = f + (size_t)b * 64 * 441 + pix;
        float vals[64];
        float s = 0.f;
#pragma unroll 8
        for (int c = 0; c < 64; c++) {
            float v = lrelu(fmaf(p[c * 441], scale[c], shift[c]));
            vals[c] = v;
            s = fmaf(v, v, s);
        }
        float inv = rsqrtf(s);
        __nv_bfloat162* op = (__nv_bfloat162*)&Qh[(size_t)idx * 64];
#pragma unroll 8
        for (int c = 0; c < 32; c++)
            op[c] = __floats2bfloat162_rn(vals[2 * c] * inv,
                                          vals[2 * c + 1] * inv);
    } else if (idx < 32 * 441 + 5 * 2240) {
        int r = idx - 32 * 441;
        int n = r / 2240, m = r % 2240;
        if (m >= 2205) {
#pragma unroll 8
            for (int c = 0; c < 64; c++)
                ShK[((size_t)n * 64 + c) * 2240 + m] = __float2bfloat16(0.f);
            return;
        }
        int sh = m / 441, pix = m % 441;
        int img = 32 + n * 5 + sh;
        int g = 1 + n;
        const float* p = f + (size_t)img * 64 * 441 + pix;
        float vals[64];
        float s = 0.f;
#pragma unroll 8
        for (int c = 0; c < 64; c++) {
            float v = lrelu(fmaf(p[c * 441], scale[g * 64 + c],
                                 shift[g * 64 + c]));
            vals[c] = v;
            s = fmaf(v, v, s);
        }
        float inv = rsqrtf(s);
#pragma unroll 8
        for (int c = 0; c < 64; c++)
            ShK[((size_t)n * 64 + c) * 2240 + m] =
                __float2bfloat16(vals[c] * inv);
    }
}

// ---------------------------------------------------------------------------
// sims via mma.sync m16n8k16 bf16, 128 rows/block; S tiles double-buffered
// (register prefetch during mma+fold, one sync per tile).
// grid (4 rowchunks, 5 classes, 32 b).
// ---------------------------------------------------------------------------
#define SPAD 72

__device__ __forceinline__ void ins3(float v, float& t0, float& t1, float& t2) {
    float lo = fminf(v, t0);
    t0 = fmaxf(v, t0);
    float mid = fminf(lo, t1);
    t1 = fmaxf(lo, t1);
    t2 = fmaxf(t2, mid);
}

__global__ void __launch_bounds__(256) sims_mma_kernel(
    const __nv_bfloat16* __restrict__ Qh,
    const __nv_bfloat16* __restrict__ ShK,
    float* __restrict__ part) {
    __shared__ __nv_bfloat16 sQ[128][SPAD];
    __shared__ __nv_bfloat16 sS[2][64][SPAD];
    __shared__ float red[8];

    const int rchunk = blockIdx.x;
    const int n = blockIdx.y;
    const int b = blockIdx.z;
    const int rbase = rchunk * 128;
    const int tid = threadIdx.x;
    const int wid = tid >> 5, lane = tid & 31;

    for (int i = tid; i < 128 * 8; i += 256) {
        int r = i >> 3, c8 = i & 7;
        uint4 v = make_uint4(0u, 0u, 0u, 0u);
        if (rbase + r < 441)
            v = *(const uint4*)&Qh[((size_t)(b * 441 + rbase + r)) * 64 + c8 * 8];
        *(uint4*)&sQ[r][c8 * 8] = v;
    }
    __syncthreads();

    const u32 sQb = smem_u32(&sQ[0][0]);
    const u32 sSb0 = smem_u32(&sS[0][0][0]);
    const u32 sSstride = (u32)(64 * SPAD * 2);
    const int m0 = wid * 16;

    u32 afr[4][4];
    {
        int rr = m0 + (lane & 15);
        int cc = (lane >> 4) * 8;
#pragma unroll
        for (int ks = 0; ks < 4; ks++)
            ldsm_x4(afr[ks][0], afr[ks][1], afr[ks][2], afr[ks][3],
                    sQb + (u32)((rr * SPAD + ks * 16 + cc) * 2));
    }

    float ta0 = -1e30f, ta1 = -1e30f, ta2 = -1e30f;
    float tb0 = -1e30f, tb1 = -1e30f, tb2 = -1e30f;

    const __nv_bfloat16* Sbase = ShK + (size_t)n * 64 * 2240;

    // prefetch indices: element i covers (k = i>>3, col8 = i&7)
    const int i0 = tid, i1 = tid + 256;
    const int k0 = i0 >> 3, p80 = (i0 & 7) * 8;
    const int k1 = i1 >> 3, p81 = (i1 & 7) * 8;

    uint4 pf0, pf1;
    {
        pf0 = *(const uint4*)&Sbase[(size_t)k0 * 2240 + p80];
        pf1 = *(const uint4*)&Sbase[(size_t)k1 * 2240 + p81];
    }
    *(uint4*)&sS[0][k0][p80] = pf0;
    *(uint4*)&sS[0][k1][p81] = pf1;
    __syncthreads();

    for (int tile = 0; tile < 35; tile++) {
        if (tile < 34) {
            const int c0n = (tile + 1) * 64;
            pf0 = *(const uint4*)&Sbase[(size_t)k0 * 2240 + c0n + p80];
            pf1 = *(const uint4*)&Sbase[(size_t)k1 * 2240 + c0n + p81];
        }

        const u32 sSb = sSb0 + (u32)(tile & 1) * sSstride;
        const int c0 = tile * 64;

        float d[8][4];
#pragma unroll
        for (int j = 0; j < 8; j++)
#pragma unroll
            for (int c = 0; c < 4; c++) d[j][c] = 0.f;

        const int kr_l = (lane & 7) + ((lane >> 3) & 1) * 8;
        const int nc_l = (lane >> 4) * 8;
#pragma unroll
        for (int ks = 0; ks < 4; ks++) {
            int kr = ks * 16 + kr_l;
#pragma unroll
            for (int n16 = 0; n16 < 4; n16++) {
                u32 b0, b1, b2, b3;
                ldsm_x4t(b0, b1, b2, b3,
                         sSb + (u32)((kr * SPAD + n16 * 16 + nc_l) * 2));
                mma16816(d[2 * n16], afr[ks], b0, b1);
                mma16816(d[2 * n16 + 1], afr[ks], b2, b3);
            }
        }

        if (tile != 34) {
#pragma unroll
            for (int n8 = 0; n8 < 8; n8++) {
                ins3(d[n8][0], ta0, ta1, ta2);
                ins3(d[n8][1], ta0, ta1, ta2);
                ins3(d[n8][2], tb0, tb1, tb2);
                ins3(d[n8][3], tb0, tb1, tb2);
            }
        } else {
            int cb = c0 + 2 * (lane & 3);
#pragma unroll
            for (int n8 = 0; n8 < 8; n8++) {
                int c = cb + n8 * 8;
                if (c < 2205) { ins3(d[n8][0], ta0, ta1, ta2);
                                ins3(d[n8][2], tb0, tb1, tb2); }
                if (c + 1 < 2205) { ins3(d[n8][1], ta0, ta1, ta2);
                                    ins3(d[n8][3], tb0, tb1, tb2); }
            }
        }

        if (tile < 34) {
            int nb = (tile + 1) & 1;
            *(uint4*)&sS[nb][k0][p80] = pf0;
            *(uint4*)&sS[nb][k1][p81] = pf1;
        }
        __syncthreads();
    }

#pragma unroll
    for (int off = 1; off <= 2; off <<= 1) {
        float x0 = __shfl_xor_sync(0xffffffffu, ta0, off);
        float x1 = __shfl_xor_sync(0xffffffffu, ta1, off);
        float x2 = __shfl_xor_sync(0xffffffffu, ta2, off);
        ins3(x0, ta0, ta1, ta2);
        ins3(x1, ta0, ta1, ta2);
        ins3(x2, ta0, ta1, ta2);
        float y0 = __shfl_xor_sync(0xffffffffu, tb0, off);
        float y1 = __shfl_xor_sync(0xffffffffu, tb1, off);
        float y2 = __shfl_xor_sync(0xffffffffu, tb2, off);
        ins3(y0, tb0, tb1, tb2);
        ins3(y1, tb0, tb1, tb2);
        ins3(y2, tb0, tb1, tb2);
    }

    float s = 0.f;
    if ((lane & 3) == 0) {
        int r1 = rbase + m0 + (lane >> 2);
        if (r1 < 441) s += ta0 + ta1 + ta2;
        if (r1 + 8 < 441) s += tb0 + tb1 + tb2;
    }
#pragma unroll
    for (int off = 16; off > 0; off >>= 1)
        s += __shfl_down_sync(0xffffffffu, s, off);
    if (lane == 0) red[wid] = s;
    __syncthreads();
    if (tid == 0) {
        float r = 0.f;
#pragma unroll
        for (int i = 0; i < 8; i++) r += red[i];
        part[(b * 5 + n) * 4 + rchunk] = r;
    }
}

__global__ void finalize_kernel(const float* __restrict__ part,
                                float* __restrict__ out) {
    int i = threadIdx.x;
    if (i < 160) {
        float s = 0.f;
#pragma unroll
        for (int k = 0; k < 4; k++) s += part[4 * i + k];
        out[i] = s;
    }
}

// ---------------------------------------------------------------------------
extern "C" void kernel_launch(void* const* d_in, const int* in_sizes, int n_in,
                              void* d_out, int out_size) {
    const float* input1 = (const float*)d_in[0];
    const float* input2 = (const float*)d_in[1];
    const float* w1 = (const float*)d_in[2];
    const float* g1 = (const float*)d_in[3];
    const float* b1 = (const float*)d_in[4];
    const float* w2 = (const float*)d_in[5];
    const float* g2 = (const float*)d_in[6];
    const float* b2 = (const float*)d_in[7];
    const float* w3 = (const float*)d_in[8];
    const float* g3 = (const float*)d_in[9];
    const float* b3 = (const float*)d_in[10];
    const float* w4 = (const float*)d_in[11];
    const float* g4 = (const float*)d_in[12];
    const float* b4 = (const float*)d_in[13];
    float* out = (float*)d_out;

    void* poolPtr = nullptr;
    cudaGetSymbolAddress(&poolPtr, d_pool);
    float* P = (float*)poolPtr;
    float* p1pre = P + OFF_P1;
    float* c2 = P + OFF_C2;
    float* c3 = P + OFF_C3;
    float* c4 = P + OFF_C4;
    __nv_bfloat16* Qh = (__nv_bfloat16*)(P + OFF_QH);
    __nv_bfloat16* ShK = (__nv_bfloat16*)(P + OFF_SK);
    float* sc = P + OFF_SC;
    float* sh = P + OFF_SHF;
    float* part = P + OFF_PART;
    float* wb2b = P + OFF_WB;
    float* wb3b = P + OFF_WB + 18432;
    float* wb4b = P + OFF_WB + 2 * 18432;
    float* wb1 = P + OFF_WB1;
    float* st1 = P + OFF_ST1;

    const int WPREP_TOT = 3 * 18432 + 2048;
    wprep_kernel<<<(WPREP_TOT + 255) / 256, 256>>>(w1, w2, w3, w4, wb2b, wb1);
    conv1_pool_kernel<<<dim3(42, NIMG), 256>>>(input1, input2, wb1, p1pre, st1);
    stats_fused_kernel<<<64, 256>>>(st1, 42, 7056, g1, b1, sc, sh);
    conv_bf16_kernel<42, 3, 44, 232, 1><<<dim3(14, NIMG), 256>>>(
        p1pre, wb2b, c2, sc, sh, st1);
    stats_fused_kernel<<<64, 256>>>(st1, 14, 1764, g2, b2, sc, sh);
    conv_bf16_kernel<21, 6, 24, 200, 2><<<dim3(4, NIMG), 256>>>(
        c2, wb3b, c3, sc, sh, st1);
    stats_fused_kernel<<<64, 256>>>(st1, 4, 441, g3, b3, sc, sh);
    conv_bf16_kernel<21, 6, 24, 200, 1><<<dim3(4, NIMG), 256>>>(
        c3, wb4b, c4, sc, sh, st1);
    stats_fused_kernel<<<64, 256>>>(st1, 4, 441, g4, b4, sc, sh);
    qsnorm_kernel<<<(32 * 441 + 5 * 2240 + 127) / 128, 128>>>(c4, sc, sh,
                                                              Qh, ShK);
    sims_mma_kernel<<<dim3(4, 5, 32), 256>>>(Qh, ShK, part);
    finalize_kernel<<<1, 160>>>(part, out);
}

// round 17
// speedup vs baseline: 1.3030x; 1.0293x over previous
#include <cuda_runtime.h>
#include <cuda_bf16.h>
#include <math.h>

// ---------------------------------------------------------------------------
// FourLayer_64F. Round 17: conv_bf16 stages the FULL K dimension (32 bf16
// ci-pair planes) in one smem pass -> one __syncthreads total, one big-MLP
// load phase, 288 uninterrupted mma. Rest = Round 16 (tf32 conv1, fused BN
// stats/pool, double-buffered bf16 sims, 12 launches).
// ---------------------------------------------------------------------------

#define NIMG 57
#define NEG_SLOPE 0.2f

typedef unsigned int u32;

__device__ __forceinline__ u32 f2tf32(float v) {
    u32 r;
    asm("cvt.rna.tf32.f32 %0, %1;" : "=r"(r) : "f"(v));
    return r;
}
__device__ __forceinline__ u32 pack_bf16(float lo, float hi) {
    __nv_bfloat162 p = __floats2bfloat162_rn(lo, hi);
    return *(u32*)&p;
}

// ---------------- scratch pool (floats) ------------------------------------
#define OFF_P1   ((size_t)0)                        // 57*64*1764 pooled pre-BN1
#define OFF_C2   (OFF_P1 + (size_t)57*64*1764)      // 57*64*1764
#define OFF_C3   (OFF_C2 + (size_t)57*64*1764)      // 57*64*441
#define OFF_C4   (OFF_C3 + (size_t)57*64*441)
#define OFF_QH   (OFF_C4 + (size_t)57*64*441)       // bf16 32*441*64 -> 451584 f
#define OFF_SK   (OFF_QH + (size_t)451584)          // bf16 5*64*2240 -> 358400 f
#define OFF_SC   (OFF_SK + (size_t)358400)          // 6*64 scale
#define OFF_SHF  (OFF_SC + 384)                     // 6*64 shift
#define OFF_PART (OFF_SHF + 384)                    // 32*5*4
#define OFF_WB   (OFF_PART + 640)                   // 3*18432 bf16 conv frags
#define OFF_WB1  (OFF_WB + (size_t)3*18432)         // 2048 conv1 tf32
#define OFF_ST1  (OFF_WB1 + 2048)                   // 57*42*64*2 block partials
#define POOL_TOTAL (OFF_ST1 + (size_t)57*42*64*2)

__device__ float d_pool[POOL_TOTAL];

__device__ __forceinline__ float lrelu(float v) {
    return v >= 0.f ? v : NEG_SLOPE * v;
}
__device__ __forceinline__ int img_group(int img) {
    return (img < 32) ? 0 : 1 + (img - 32) / 5;
}

__device__ __forceinline__ u32 smem_u32(const void* p) {
    u32 a;
    asm("{ .reg .u64 t; cvta.to.shared.u64 t, %1; cvt.u32.u64 %0, t; }"
        : "=r"(a) : "l"(p));
    return a;
}
__device__ __forceinline__ void ldsm_x4(u32& r0, u32& r1, u32& r2, u32& r3,
                                        u32 addr) {
    asm volatile("ldmatrix.sync.aligned.m8n8.x4.shared.b16 {%0,%1,%2,%3}, [%4];"
                 : "=r"(r0), "=r"(r1), "=r"(r2), "=r"(r3) : "r"(addr));
}
__device__ __forceinline__ void ldsm_x4t(u32& r0, u32& r1, u32& r2, u32& r3,
                                         u32 addr) {
    asm volatile(
        "ldmatrix.sync.aligned.m8n8.x4.trans.shared.b16 {%0,%1,%2,%3}, [%4];"
        : "=r"(r0), "=r"(r1), "=r"(r2), "=r"(r3) : "r"(addr));
}
__device__ __forceinline__ void mma16816(float* d, const u32* a, u32 b0, u32 b1) {
    asm volatile(
        "mma.sync.aligned.m16n8k16.row.col.f32.bf16.bf16.f32 "
        "{%0,%1,%2,%3}, {%4,%5,%6,%7}, {%8,%9}, {%0,%1,%2,%3};"
        : "+f"(d[0]), "+f"(d[1]), "+f"(d[2]), "+f"(d[3])
        : "r"(a[0]), "r"(a[1]), "r"(a[2]), "r"(a[3]), "r"(b0), "r"(b1));
}
__device__ __forceinline__ void mma_tf32(float* d, u32 a0, u32 a1, u32 a2,
                                         u32 a3, u32 b0, u32 b1) {
    asm volatile(
        "mma.sync.aligned.m16n8k8.row.col.f32.tf32.tf32.f32 "
        "{%0,%1,%2,%3}, {%4,%5,%6,%7}, {%8,%9}, {%0,%1,%2,%3};"
        : "+f"(d[0]), "+f"(d[1]), "+f"(d[2]), "+f"(d[3])
        : "r"(a0), "r"(a1), "r"(a2), "r"(a3), "r"(b0), "r"(b1));
}

// ---------------------------------------------------------------------------
// Weight prep, one launch (unchanged from R15/16).
// ---------------------------------------------------------------------------
__global__ void wprep_kernel(const float* __restrict__ w1,
                             const float* __restrict__ w2,
                             const float* __restrict__ w3,
                             const float* __restrict__ w4,
                             float* __restrict__ wbuf,
                             float* __restrict__ wbuf1) {
    int idx = blockIdx.x * 256 + threadIdx.x;
    if (idx < 3 * 18432) {
        int which = idx / 18432;
        int r = idx % 18432;
        const float* w = (which == 0) ? w2 : (which == 1) ? w3 : w4;
        int j = r & 3;
        int lane = (r >> 2) & 31;
        int wm = (r >> 7) & 3;
        int rest = r >> 9;
        int t = rest % 9, cc4 = rest / 9;
        int oc = wm * 16 + (lane >> 2) + 8 * (j & 1);
        int k2 = 2 * (lane & 3) + 8 * (j >> 1);
        int ci = cc4 * 16 + k2;
        float lo = w[(oc * 64 + ci) * 9 + t];
        float hi = w[(oc * 64 + ci + 1) * 9 + t];
        wbuf[idx] = __uint_as_float(pack_bf16(lo, hi));
    } else if (idx < 3 * 18432 + 2048) {
        int r = idx - 3 * 18432;
        int j = r & 3;
        int lane = (r >> 2) & 31;
        int wm = (r >> 7) & 3;
        int ks = r >> 9;
        int oc = wm * 16 + (lane >> 2) + (j & 1) * 8;
        int k = ks * 8 + (lane & 3) + ((j >> 1) & 1) * 4;
        float v = 0.f;
        if (k < 27) v = w1[(oc * 3 + k / 9) * 9 + (k % 9)];
        wbuf1[r] = __uint_as_float(f2tf32(v));
    }
}

// ---------------------------------------------------------------------------
// conv1 + maxpool, tf32 shift-GEMM (unchanged). grid (42, 57).
// ---------------------------------------------------------------------------
#define C1P 88
#define C1CIP 360

__global__ void __launch_bounds__(256) conv1_pool_kernel(
    const float* __restrict__ in1, const float* __restrict__ in2,
    const float* __restrict__ wbuf1, float* __restrict__ p1pre,
    float* __restrict__ st1) {
    __shared__ char sraw[45056];
    __shared__ float s_stats[2][64][2];
    u32* s_in = (u32*)sraw;
    float(*sacc)[176] = (float(*)[176])sraw;

    const int bx = blockIdx.x;
    const int img = blockIdx.y;
    const int tid = threadIdx.x;
    const int wid = tid >> 5, lane = tid & 31;
    const int wm = wid & 3, wn = wid >> 2;

    const float* ip = (img < 32) ? (in1 + (size_t)img * 3 * 7056)
                                 : (in2 + (size_t)(img - 32) * 3 * 7056);

    for (int i = tid; i < 3 * 4 * C1P; i += 256) {
        int ci = i / (4 * C1P);
        int rem = i % (4 * C1P);
        int r = rem / C1P, c = rem % C1P;
        int gy = 2 * bx - 1 + r, gx = c - 1;
        float v = 0.f;
        if (gy >= 0 && gy < 84 && gx >= 0 && gx < 84)
            v = ip[ci * 7056 + gy * 84 + gx];
        s_in[ci * C1CIP + r * C1P + c] = f2tf32(v);
    }
    if (tid < 24)
        s_in[(tid / 8) * C1CIP + 4 * C1P + (tid % 8)] = 0u;
    __syncthreads();

    u32 koffA[4], koffB[4];
#pragma unroll
    for (int ks = 0; ks < 4; ks++) {
        int kA = ks * 8 + (lane & 3), kB = kA + 4;
        koffA[ks] = (kA < 27)
            ? (u32)((kA / 9) * C1CIP + ((kA % 9) / 3) * C1P + (kA % 9) % 3)
            : 0u;
        koffB[ks] = (kB < 27)
            ? (u32)((kB / 9) * C1CIP + ((kB % 9) / 3) * C1P + (kB % 9) % 3)
            : 0u;
    }
    const u32 pixrow = (u32)(wn * C1P) + (u32)(lane >> 2);

    float acc[11][4];
#pragma unroll
    for (int n8 = 0; n8 < 11; n8++)
#pragma unroll
        for (int j = 0; j < 4; j++) acc[n8][j] = 0.f;

#pragma unroll
    for (int ks = 0; ks < 4; ks++) {
        float4 af = *(const float4*)&wbuf1[((ks * 4 + wm) * 32 + lane) * 4];
        u32 a0 = __float_as_uint(af.x);
        u32 a1 = __float_as_uint(af.y);
        u32 a2 = __float_as_uint(af.z);
        u32 a3 = __float_as_uint(af.w);
#pragma unroll
        for (int n8 = 0; n8 < 11; n8++) {
            u32 p = pixrow + n8 * 8;
            u32 b0 = s_in[koffA[ks] + p];
            u32 b1 = s_in[koffB[ks] + p];
            mma_tf32(acc[n8], a0, a1, a2, a3, b0, b1);
        }
    }
    __syncthreads();

    const int oc0 = wm * 16 + (lane >> 2);
    float s0 = 0.f, q0 = 0.f, s1 = 0.f, q1 = 0.f;
#pragma unroll
    for (int n8 = 0; n8 < 11; n8++) {
        int col = n8 * 8 + 2 * (lane & 3);
        if (col < 84) {
            float v0 = acc[n8][0], v1 = acc[n8][2];
            sacc[oc0][wn * C1P + col] = v0;
            sacc[oc0 + 8][wn * C1P + col] = v1;
            s0 += v0; q0 = fmaf(v0, v0, q0);
            s1 += v1; q1 = fmaf(v1, v1, q1);
        }
        if (col + 1 < 84) {
            float v0 = acc[n8][1], v1 = acc[n8][3];
            sacc[oc0][wn * C1P + col + 1] = v0;
            sacc[oc0 + 8][wn * C1P + col + 1] = v1;
            s0 += v0; q0 = fmaf(v0, v0, q0);
            s1 += v1; q1 = fmaf(v1, v1, q1);
        }
    }
#pragma unroll
    for (int off = 1; off <= 2; off <<= 1) {
        s0 += __shfl_xor_sync(0xffffffffu, s0, off);
        q0 += __shfl_xor_sync(0xffffffffu, q0, off);
        s1 += __shfl_xor_sync(0xffffffffu, s1, off);
        q1 += __shfl_xor_sync(0xffffffffu, q1, off);
    }
    if ((lane & 3) == 0) {
        s_stats[wn][oc0][0] = s0;
        s_stats[wn][oc0][1] = q0;
        s_stats[wn][oc0 + 8][0] = s1;
        s_stats[wn][oc0 + 8][1] = q1;
    }
    __syncthreads();

    for (int i = tid; i < 64 * 42; i += 256) {
        int oc = i / 42, pc = i % 42;
        float v = fmaxf(fmaxf(sacc[oc][2 * pc], sacc[oc][2 * pc + 1]),
                        fmaxf(sacc[oc][C1P + 2 * pc], sacc[oc][C1P + 2 * pc + 1]));
        p1pre[((size_t)img * 64 + oc) * 1764 + bx * 42 + pc] = v;
    }
    if (tid < 128) {
        int oc = tid >> 1, wh = tid & 1;
        st1[(((size_t)img * 42 + bx) * 64 + oc) * 2 + wh] =
            s_stats[0][oc][wh] + s_stats[1][oc][wh];
    }
}

// ---------------------------------------------------------------------------
// Fused stats (unchanged). grid (64), 256 threads.
// ---------------------------------------------------------------------------
__global__ void stats_fused_kernel(const float* __restrict__ st1, int NB,
                                   int HW,
                                   const float* __restrict__ gamma,
                                   const float* __restrict__ beta,
                                   float* __restrict__ scale,
                                   float* __restrict__ shift) {
    const int c = blockIdx.x;
    const int tid = threadIdx.x;
    float a[6][2];
#pragma unroll
    for (int g = 0; g < 6; g++) { a[g][0] = 0.f; a[g][1] = 0.f; }
    const int total = NIMG * NB;
    for (int i = tid; i < total; i += 256) {
        int img = i / NB, blk = i % NB;
        int g = img_group(img);
        const float* p = &st1[(((size_t)img * NB + blk) * 64 + c) * 2];
        a[g][0] += p[0];
        a[g][1] += p[1];
    }
    __shared__ float sm[256][12];
#pragma unroll
    for (int g = 0; g < 6; g++) {
        sm[tid][2 * g] = a[g][0];
        sm[tid][2 * g + 1] = a[g][1];
    }
    __syncthreads();
    for (int off = 128; off > 0; off >>= 1) {
        if (tid < off)
#pragma unroll
            for (int j = 0; j < 12; j++) sm[tid][j] += sm[tid + off][j];
        __syncthreads();
    }
    if (tid < 6) {
        int g = tid;
        int nimg = (g == 0) ? 32 : 5;
        float cnt = (float)(nimg * HW);
        float m = sm[0][2 * g] / cnt;
        float var = sm[0][2 * g + 1] / cnt - m * m;
        float inv = rsqrtf(var + 1e-5f);
        float sc = gamma[c] * inv;
        scale[g * 64 + c] = sc;
        shift[g * 64 + c] = beta[c] - m * sc;
    }
}

// ---------------------------------------------------------------------------
// conv64 in bf16 m16n8k16, FULL-K staging: all 32 ci-pair planes loaded in one
// pass (one __syncthreads), then 4x72 mma uninterrupted. Paired STG.64
// epilogue for even W. CIP === 8 (mod 32) -> conflict-free B reads.
// MODE: 1 = BN+LReLU on input; 2 = BN+LReLU+2x2 maxpool on 2H-sized input.
// ---------------------------------------------------------------------------
template <int H, int NROWS, int PITCH, int CIP, int MODE>
__global__ void __launch_bounds__(256) conv_bf16_kernel(
    const float* __restrict__ in, const float* __restrict__ wbuf,
    float* __restrict__ out,
    const float* __restrict__ scale, const float* __restrict__ shift,
    float* __restrict__ st1) {
    constexpr int R = NROWS + 2;
    constexpr int W = H;
    constexpr int HW = H * H;
    constexpr int PLANE = R * (W + 2);      // valid words per plane
    constexpr int TOT4 = 32 * PLANE;        // all 32 pair-planes
    constexpr int IN_HW = (MODE == 2) ? 4 * HW : HW;
    constexpr int IN_W = (MODE == 2) ? 2 * W : W;

    __shared__ u32 sB[32 * CIP];
    __shared__ float s_stats[2][64][2];

    const int rb = blockIdx.x * NROWS;
    const int img = blockIdx.y;
    const int tid = threadIdx.x;
    const int wid = tid >> 5, lane = tid & 31;
    const int wm = wid & 3, wn = wid >> 2;
    const int g = img_group(img);
    const int vrows = min(rb + NROWS, H) - rb;
    const int valid = vrows * W;

    u32 baddr[8];
    {
        u32 kq = (u32)(lane & 3) * CIP;
#pragma unroll
        for (int n8 = 0; n8 < 8; n8++) {
            int n = wn * 64 + n8 * 8 + (lane >> 2);
            u32 poff = 0;
            if (n < valid) poff = (u32)((n / W) * PITCH + (n % W));
            baddr[n8] = kq + poff;
        }
    }

    float acc[8][4];
#pragma unroll
    for (int n8 = 0; n8 < 8; n8++)
#pragma unroll
        for (int j = 0; j < 4; j++) acc[n8][j] = 0.f;

    const float* ip = in + (size_t)img * 64 * IN_HW;

    // ---- single load phase: all 32 ci-pair planes ----
    for (int i = tid; i < TOT4; i += 256) {
        int p = i / PLANE;                  // plane 0..31
        int rem = i % PLANE;
        int r = rem / (W + 2), c = rem % (W + 2);
        int gy = rb - 1 + r, gx = c - 1;
        u32 word = 0u;
        if (gy >= 0 && gy < H && gx >= 0 && gx < W) {
            int ci0 = 2 * p;                // = cc4*16 + 2*cp with p = cc4*8+cp
            float v0, v1;
            if (MODE == 2) {
                const float* q0 = ip + (size_t)ci0 * IN_HW +
                                  (2 * gy) * IN_W + 2 * gx;
                const float* q1 = q0 + IN_HW;
                float sc0 = scale[g * 64 + ci0], sf0 = shift[g * 64 + ci0];
                float sc1 = scale[g * 64 + ci0 + 1],
                      sf1 = shift[g * 64 + ci0 + 1];
                float a0 = lrelu(fmaf(q0[0], sc0, sf0));
                float a1 = lrelu(fmaf(q0[1], sc0, sf0));
                float a2 = lrelu(fmaf(q0[IN_W], sc0, sf0));
                float a3 = lrelu(fmaf(q0[IN_W + 1], sc0, sf0));
                v0 = fmaxf(fmaxf(a0, a1), fmaxf(a2, a3));
                float b0 = lrelu(fmaf(q1[0], sc1, sf1));
                float b1 = lrelu(fmaf(q1[1], sc1, sf1));
                float b2 = lrelu(fmaf(q1[IN_W], sc1, sf1));
                float b3 = lrelu(fmaf(q1[IN_W + 1], sc1, sf1));
                v1 = fmaxf(fmaxf(b0, b1), fmaxf(b2, b3));
            } else {
                v0 = ip[(size_t)ci0 * IN_HW + gy * W + gx];
                v1 = ip[(size_t)(ci0 + 1) * IN_HW + gy * W + gx];
                v0 = lrelu(fmaf(v0, scale[g * 64 + ci0],
                                shift[g * 64 + ci0]));
                v1 = lrelu(fmaf(v1, scale[g * 64 + ci0 + 1],
                                shift[g * 64 + ci0 + 1]));
            }
            word = pack_bf16(v0, v1);
        }
        // plane p: note pairing (2p, 2p+1); plane layout cc4-major works
        // because ci0 = 2*p covers (cc4*16 + 2*cp) exactly in order.
        sB[p * CIP + r * PITCH + c] = word;
    }
    __syncthreads();

    // ---- mma phase: 4 chunks x 9 taps x 8 n8, no further syncs ----
#pragma unroll
    for (int cc4 = 0; cc4 < 4; cc4++) {
        const u32 cbase = (u32)(cc4 * 8 * CIP);
#pragma unroll
        for (int t = 0; t < 9; t++) {
            const int dy = t / 3, dx = t % 3;
            const int soff = dy * PITCH + dx;
            float4 af = *(const float4*)&wbuf[(((cc4 * 9 + t) * 4 + wm) * 32 +
                                              lane) * 4];
            u32 a[4] = {__float_as_uint(af.x), __float_as_uint(af.y),
                        __float_as_uint(af.z), __float_as_uint(af.w)};
#pragma unroll
            for (int n8 = 0; n8 < 8; n8++) {
                u32 b0 = sB[cbase + baddr[n8] + soff];
                u32 b1 = sB[cbase + baddr[n8] + soff + 4 * CIP];
                mma16816(acc[n8], a, b0, b1);
            }
        }
    }

    const int r0 = wm * 16 + (lane >> 2);
    float* op0 = out + ((size_t)img * 64 + r0) * HW;
    float* op1 = out + ((size_t)img * 64 + r0 + 8) * HW;
    float s0 = 0.f, q0 = 0.f, s1 = 0.f, q1 = 0.f;
#pragma unroll
    for (int n8 = 0; n8 < 8; n8++) {
        int nb = wn * 64 + n8 * 8 + 2 * (lane & 3);
        if (W % 2 == 0) {
            if (nb + 1 < valid) {
                int p = (rb + nb / W) * W + nb % W;
                float v0 = acc[n8][0], v1 = acc[n8][1];
                float w0 = acc[n8][2], w1 = acc[n8][3];
                *(float2*)&op0[p] = make_float2(v0, v1);
                *(float2*)&op1[p] = make_float2(w0, w1);
                s0 += v0 + v1;
                q0 = fmaf(v0, v0, fmaf(v1, v1, q0));
                s1 += w0 + w1;
                q1 = fmaf(w0, w0, fmaf(w1, w1, q1));
            } else if (nb < valid) {
                int p = (rb + nb / W) * W + nb % W;
                float v0 = acc[n8][0], w0 = acc[n8][2];
                op0[p] = v0;
                op1[p] = w0;
                s0 += v0; q0 = fmaf(v0, v0, q0);
                s1 += w0; q1 = fmaf(w0, w0, q1);
            }
        } else {
            if (nb < valid) {
                int p = (rb + nb / W) * W + nb % W;
                float v0 = acc[n8][0], v1 = acc[n8][2];
                op0[p] = v0;
                op1[p] = v1;
                s0 += v0; q0 = fmaf(v0, v0, q0);
                s1 += v1; q1 = fmaf(v1, v1, q1);
            }
            if (nb + 1 < valid) {
                int p = (rb + (nb + 1) / W) * W + (nb + 1) % W;
                float v0 = acc[n8][1], v1 = acc[n8][3];
                op0[p] = v0;
                op1[p] = v1;
                s0 += v0; q0 = fmaf(v0, v0, q0);
                s1 += v1; q1 = fmaf(v1, v1, q1);
            }
        }
    }
#pragma unroll
    for (int off = 1; off <= 2; off <<= 1) {
        s0 += __shfl_xor_sync(0xffffffffu, s0, off);
        q0 += __shfl_xor_sync(0xffffffffu, q0, off);
        s1 += __shfl_xor_sync(0xffffffffu, s1, off);
        q1 += __shfl_xor_sync(0xffffffffu, q1, off);
    }
    if ((lane & 3) == 0) {
        s_stats[wn][r0][0] = s0;
        s_stats[wn][r0][1] = q0;
        s_stats[wn][r0 + 8][0] = s1;
        s_stats[wn][r0 + 8][1] = q1;
    }
    __syncthreads();
    if (tid < 128) {
        int oc = tid >> 1, wh = tid & 1;
        st1[(((size_t)img * gridDim.x + blockIdx.x) * 64 + oc) * 2 + wh] =
            s_stats[0][oc][wh] + s_stats[1][oc][wh];
    }
}

// ---------------------------------------------------------------------------
// qsnorm (unchanged).
// ---------------------------------------------------------------------------
__global__ void qsnorm_kernel(const float* __restrict__ f,
                              const float* __restrict__ scale,
                              const float* __restrict__ shift,
                              __nv_bfloat16* __restrict__ Qh,
                              __nv_bfloat16* __restrict__ ShK) {
    int idx = blockIdx.x * blockDim.x + threadIdx.x;
    if (idx < 32 * 441) {
        int b = idx / 441, pix = idx % 441;
        const float* p = f + (size_t)b * 64 * 441 + pix;
        float vals[64];
        float s = 0.f;
#pragma unroll 8
        for (int c = 0; c < 64; c++) {
            float v = lrelu(fmaf(p[c * 441], scale[c], shift[c]));
            vals[c] = v;
            s = fmaf(v, v, s);
        }
        float inv = rsqrtf(s);
        __nv_bfloat162* op = (__nv_bfloat162*)&Qh[(size_t)idx * 64];
#pragma unroll 8
        for (int c = 0; c < 32; c++)
            op[c] = __floats2bfloat162_rn(vals[2 * c] * inv,
                                          vals[2 * c + 1] * inv);
    } else if (idx < 32 * 441 + 5 * 2240) {
        int r = idx - 32 * 441;
        int n = r / 2240, m = r % 2240;
        if (m >= 2205) {
#pragma unroll 8
            for (int c = 0; c < 64; c++)
                ShK[((size_t)n * 64 + c) * 2240 + m] = __float2bfloat16(0.f);
            return;
        }
        int sh = m / 441, pix = m % 441;
        int img = 32 + n * 5 + sh;
        int g = 1 + n;
        const float* p = f + (size_t)img * 64 * 441 + pix;
        float vals[64];
        float s = 0.f;
#pragma unroll 8
        for (int c = 0; c < 64; c++) {
            float v = lrelu(fmaf(p[c * 441], scale[g * 64 + c],
                                 shift[g * 64 + c]));
            vals[c] = v;
            s = fmaf(v, v, s);
        }
        float inv = rsqrtf(s);
#pragma unroll 8
        for (int c = 0; c < 64; c++)
            ShK[((size_t)n * 64 + c) * 2240 + m] =
                __float2bfloat16(vals[c] * inv);
    }
}

// ---------------------------------------------------------------------------
// sims via mma.sync m16n8k16 bf16, 128 rows/block, double-buffered S tiles
// (unchanged from R16).
// ---------------------------------------------------------------------------
#define SPAD 72

__device__ __forceinline__ void ins3(float v, float& t0, float& t1, float& t2) {
    float lo = fminf(v, t0);
    t0 = fmaxf(v, t0);
    float mid = fminf(lo, t1);
    t1 = fmaxf(lo, t1);
    t2 = fmaxf(t2, mid);
}

__global__ void __launch_bounds__(256) sims_mma_kernel(
    const __nv_bfloat16* __restrict__ Qh,
    const __nv_bfloat16* __restrict__ ShK,
    float* __restrict__ part) {
    __shared__ __nv_bfloat16 sQ[128][SPAD];
    __shared__ __nv_bfloat16 sS[2][64][SPAD];
    __shared__ float red[8];

    const int rchunk = blockIdx.x;
    const int n = blockIdx.y;
    const int b = blockIdx.z;
    const int rbase = rchunk * 128;
    const int tid = threadIdx.x;
    const int wid = tid >> 5, lane = tid & 31;

    for (int i = tid; i < 128 * 8; i += 256) {
        int r = i >> 3, c8 = i & 7;
        uint4 v = make_uint4(0u, 0u, 0u, 0u);
        if (rbase + r < 441)
            v = *(const uint4*)&Qh[((size_t)(b * 441 + rbase + r)) * 64 + c8 * 8];
        *(uint4*)&sQ[r][c8 * 8] = v;
    }
    __syncthreads();

    const u32 sQb = smem_u32(&sQ[0][0]);
    const u32 sSb0 = smem_u32(&sS[0][0][0]);
    const u32 sSstride = (u32)(64 * SPAD * 2);
    const int m0 = wid * 16;

    u32 afr[4][4];
    {
        int rr = m0 + (lane & 15);
        int cc = (lane >> 4) * 8;
#pragma unroll
        for (int ks = 0; ks < 4; ks++)
            ldsm_x4(afr[ks][0], afr[ks][1], afr[ks][2], afr[ks][3],
                    sQb + (u32)((rr * SPAD + ks * 16 + cc) * 2));
    }

    float ta0 = -1e30f, ta1 = -1e30f, ta2 = -1e30f;
    float tb0 = -1e30f, tb1 = -1e30f, tb2 = -1e30f;

    const __nv_bfloat16* Sbase = ShK + (size_t)n * 64 * 2240;

    const int i0 = tid, i1 = tid + 256;
    const int k0 = i0 >> 3, p80 = (i0 & 7) * 8;
    const int k1 = i1 >> 3, p81 = (i1 & 7) * 8;

    uint4 pf0, pf1;
    {
        pf0 = *(const uint4*)&Sbase[(size_t)k0 * 2240 + p80];
        pf1 = *(const uint4*)&Sbase[(size_t)k1 * 2240 + p81];
    }
    *(uint4*)&sS[0][k0][p80] = pf0;
    *(uint4*)&sS[0][k1][p81] = pf1;
    __syncthreads();

    for (int tile = 0; tile < 35; tile++) {
        if (tile < 34) {
            const int c0n = (tile + 1) * 64;
            pf0 = *(const uint4*)&Sbase[(size_t)k0 * 2240 + c0n + p80];
            pf1 = *(const uint4*)&Sbase[(size_t)k1 * 2240 + c0n + p81];
        }

        const u32 sSb = sSb0 + (u32)(tile & 1) * sSstride;
        const int c0 = tile * 64;

        float d[8][4];
#pragma unroll
        for (int j = 0; j < 8; j++)
#pragma unroll
            for (int c = 0; c < 4; c++) d[j][c] = 0.f;

        const int kr_l = (lane & 7) + ((lane >> 3) & 1) * 8;
        const int nc_l = (lane >> 4) * 8;
#pragma unroll
        for (int ks = 0; ks < 4; ks++) {
            int kr = ks * 16 + kr_l;
#pragma unroll
            for (int n16 = 0; n16 < 4; n16++) {
                u32 b0, b1, b2, b3;
                ldsm_x4t(b0, b1, b2, b3,
                         sSb + (u32)((kr * SPAD + n16 * 16 + nc_l) * 2));
                mma16816(d[2 * n16], afr[ks], b0, b1);
                mma16816(d[2 * n16 + 1], afr[ks], b2, b3);
            }
        }

        if (tile != 34) {
#pragma unroll
            for (int n8 = 0; n8 < 8; n8++) {
                ins3(d[n8][0], ta0, ta1, ta2);
                ins3(d[n8][1], ta0, ta1, ta2);
                ins3(d[n8][2], tb0, tb1, tb2);
                ins3(d[n8][3], tb0, tb1, tb2);
            }
        } else {
            int cb = c0 + 2 * (lane & 3);
#pragma unroll
            for (int n8 = 0; n8 < 8; n8++) {
                int c = cb + n8 * 8;
                if (c < 2205) { ins3(d[n8][0], ta0, ta1, ta2);
                                ins3(d[n8][2], tb0, tb1, tb2); }
                if (c + 1 < 2205) { ins3(d[n8][1], ta0, ta1, ta2);
                                    ins3(d[n8][3], tb0, tb1, tb2); }
            }
        }

        if (tile < 34) {
            int nb = (tile + 1) & 1;
            *(uint4*)&sS[nb][k0][p80] = pf0;
            *(uint4*)&sS[nb][k1][p81] = pf1;
        }
        __syncthreads();
    }

#pragma unroll
    for (int off = 1; off <= 2; off <<= 1) {
        float x0 = __shfl_xor_sync(0xffffffffu, ta0, off);
        float x1 = __shfl_xor_sync(0xffffffffu, ta1, off);
        float x2 = __shfl_xor_sync(0xffffffffu, ta2, off);
        ins3(x0, ta0, ta1, ta2);
        ins3(x1, ta0, ta1, ta2);
        ins3(x2, ta0, ta1, ta2);
        float y0 = __shfl_xor_sync(0xffffffffu, tb0, off);
        float y1 = __shfl_xor_sync(0xffffffffu, tb1, off);
        float y2 = __shfl_xor_sync(0xffffffffu, tb2, off);
        ins3(y0, tb0, tb1, tb2);
        ins3(y1, tb0, tb1, tb2);
        ins3(y2, tb0, tb1, tb2);
    }

    float s = 0.f;
    if ((lane & 3) == 0) {
        int r1 = rbase + m0 + (lane >> 2);
        if (r1 < 441) s += ta0 + ta1 + ta2;
        if (r1 + 8 < 441) s += tb0 + tb1 + tb2;
    }
#pragma unroll
    for (int off = 16; off > 0; off >>= 1)
        s += __shfl_down_sync(0xffffffffu, s, off);
    if (lane == 0) red[wid] = s;
    __syncthreads();
    if (tid == 0) {
        float r = 0.f;
#pragma unroll
        for (int i = 0; i < 8; i++) r += red[i];
        part[(b * 5 + n) * 4 + rchunk] = r;
    }
}

__global__ void finalize_kernel(const float* __restrict__ part,
                                float* __restrict__ out) {
    int i = threadIdx.x;
    if (i < 160) {
        float s = 0.f;
#pragma unroll
        for (int k = 0; k < 4; k++) s += part[4 * i + k];
        out[i] = s;
    }
}

// ---------------------------------------------------------------------------
extern "C" void kernel_launch(void* const* d_in, const int* in_sizes, int n_in,
                              void* d_out, int out_size) {
    const float* input1 = (const float*)d_in[0];
    const float* input2 = (const float*)d_in[1];
    const float* w1 = (const float*)d_in[2];
    const float* g1 = (const float*)d_in[3];
    const float* b1 = (const float*)d_in[4];
    const float* w2 = (const float*)d_in[5];
    const float* g2 = (const float*)d_in[6];
    const float* b2 = (const float*)d_in[7];
    const float* w3 = (const float*)d_in[8];
    const float* g3 = (const float*)d_in[9];
    const float* b3 = (const float*)d_in[10];
    const float* w4 = (const float*)d_in[11];
    const float* g4 = (const float*)d_in[12];
    const float* b4 = (const float*)d_in[13];
    float* out = (float*)d_out;

    void* poolPtr = nullptr;
    cudaGetSymbolAddress(&poolPtr, d_pool);
    float* P = (float*)poolPtr;
    float* p1pre = P + OFF_P1;
    float* c2 = P + OFF_C2;
    float* c3 = P + OFF_C3;
    float* c4 = P + OFF_C4;
    __nv_bfloat16* Qh = (__nv_bfloat16*)(P + OFF_QH);
    __nv_bfloat16* ShK = (__nv_bfloat16*)(P + OFF_SK);
    float* sc = P + OFF_SC;
    float* sh = P + OFF_SHF;
    float* part = P + OFF_PART;
    float* wb2b = P + OFF_WB;
    float* wb3b = P + OFF_WB + 18432;
    float* wb4b = P + OFF_WB + 2 * 18432;
    float* wb1 = P + OFF_WB1;
    float* st1 = P + OFF_ST1;

    const int WPREP_TOT = 3 * 18432 + 2048;
    wprep_kernel<<<(WPREP_TOT + 255) / 256, 256>>>(w1, w2, w3, w4, wb2b, wb1);
    conv1_pool_kernel<<<dim3(42, NIMG), 256>>>(input1, input2, wb1, p1pre, st1);
    stats_fused_kernel<<<64, 256>>>(st1, 42, 7056, g1, b1, sc, sh);
    conv_bf16_kernel<42, 3, 44, 232, 1><<<dim3(14, NIMG), 256>>>(
        p1pre, wb2b, c2, sc, sh, st1);
    stats_fused_kernel<<<64, 256>>>(st1, 14, 1764, g2, b2, sc, sh);
    conv_bf16_kernel<21, 6, 24, 200, 2><<<dim3(4, NIMG), 256>>>(
        c2, wb3b, c3, sc, sh, st1);
    stats_fused_kernel<<<64, 256>>>(st1, 4, 441, g3, b3, sc, sh);
    conv_bf16_kernel<21, 6, 24, 200, 1><<<dim3(4, NIMG), 256>>>(
        c3, wb4b, c4, sc, sh, st1);
    stats_fused_kernel<<<64, 256>>>(st1, 4, 441, g4, b4, sc, sh);
    qsnorm_kernel<<<(32 * 441 + 5 * 2240 + 127) / 128, 128>>>(c4, sc, sh,
                                                              Qh, ShK);
    sims_mma_kernel<<<dim3(4, 5, 32), 256>>>(Qh, ShK, part);
    finalize_kernel<<<1, 160>>>(part, out);
}